// round 11
// baseline (speedup 1.0000x reference)
#include <cuda_runtime.h>
#include <cuda_bf16.h>
#include <cuda_fp16.h>
#include <math.h>
#include <stdint.h>

#define TT 2048
#define SS 512
#define BB 4
#define HH 1024
#define NST 128
#define LL 6
#define VV 32000
#define NHD 8
#define FFD 4096
#define DHD 128
typedef long long ll;

// ---------------- scratch ----------------
__device__ float g_x [TT * HH];
__device__ float g_t1[TT * FFD];
__device__ float g_t2[TT * FFD];
__device__ float g_sc[BB * NHD * SS * SS];
__device__ float g_vt[BB * NHD * DHD * SS];

// bf16 packers
__device__ __forceinline__ uint32_t pack_hi(float x, float y) {
    __nv_bfloat162 h = __floats2bfloat162_rn(x, y);
    return *reinterpret_cast<uint32_t*>(&h);
}
__device__ __forceinline__ uint32_t pack_lo(float x, float y) {
    float hx = __bfloat162float(__float2bfloat16_rn(x));
    float hy = __bfloat162float(__float2bfloat16_rn(y));
    __nv_bfloat162 l = __floats2bfloat162_rn(x - hx, y - hy);
    return *reinterpret_cast<uint32_t*>(&l);
}
// fp16 packers
__device__ __forceinline__ uint32_t pack_hi16(float x, float y) {
    __half2 h = __floats2half2_rn(x, y);
    return *reinterpret_cast<uint32_t*>(&h);
}
__device__ __forceinline__ uint32_t pack_lores16(float x, float y) {
    float hx = __half2float(__float2half_rn(x));
    float hy = __half2float(__float2half_rn(y));
    __half2 l = __floats2half2_rn(x - hx, y - hy);   // unscaled residual
    return *reinterpret_cast<uint32_t*>(&l);
}

#define MMA_BF16(ACC, AFR, BF0, BF1)                                            \
    asm volatile(                                                               \
        "mma.sync.aligned.m16n8k16.row.col.f32.bf16.bf16.f32 "                  \
        "{%0,%1,%2,%3}, {%4,%5,%6,%7}, {%8,%9}, {%0,%1,%2,%3};"                 \
        : "+f"((ACC)[0]), "+f"((ACC)[1]), "+f"((ACC)[2]), "+f"((ACC)[3])        \
        : "r"((AFR)[0]), "r"((AFR)[1]), "r"((AFR)[2]), "r"((AFR)[3]),           \
          "r"(BF0), "r"(BF1))

#define MMA_F16(ACC, AFR, BF0, BF1)                                             \
    asm volatile(                                                               \
        "mma.sync.aligned.m16n8k16.row.col.f32.f16.f16.f32 "                    \
        "{%0,%1,%2,%3}, {%4,%5,%6,%7}, {%8,%9}, {%0,%1,%2,%3};"                 \
        : "+f"((ACC)[0]), "+f"((ACC)[1]), "+f"((ACC)[2]), "+f"((ACC)[3])        \
        : "r"((AFR)[0]), "r"((AFR)[1]), "r"((AFR)[2]), "r"((AFR)[3]),           \
          "r"(BF0), "r"(BF1))

// ================= pipelined NT GEMM (128x128, GBK=16), two numeric modes ====
// MODE 0: bf16x3 (hi/lo both sides, 3 passes)
// MODE 1: fp16x2 (A hi only; B hi + unscaled residual; 2 passes)
template<int MODE>
__global__ __launch_bounds__(128, 2)
void gemm_main(const float* __restrict__ A, const float* __restrict__ B,
               const float* __restrict__ bias, float* __restrict__ C,
               int K, int lda, int ldb, int ldc, int zmod,
               ll sAa, ll sAb, ll sBa, ll sBb, ll sCa, ll sCb, float alpha, int act)
{
    __shared__ uint32_t sm[2][4][1024];

    int tid = threadIdx.x;
    int lane = tid & 31, warp = tid >> 5;
    int g = lane >> 2, c0 = lane & 3;
    int wm = (warp & 1) * 64, wn = (warp >> 1) * 64;

    int z = blockIdx.z;
    int zq = z / zmod, zr = z % zmod;
    A += (ll)zq * sAa + (ll)zr * sAb;
    B += (ll)zq * sBa + (ll)zr * sBb;
    C += (ll)zq * sCa + (ll)zr * sCb;

    int row0 = blockIdx.y * 128, col0 = blockIdx.x * 128;
    const float* Ag = A + (ll)row0 * lda;
    const float* Bg = B + (ll)col0 * ldb;

    int ur[4], uh[4], uw[4], ut[4];
#pragma unroll
    for (int p = 0; p < 4; p++) {
        int id = tid + 128 * p;
        ut[p] = (id < 256) ? 0 : 2;
        int id2 = id & 255;
        ur[p] = id2 >> 1; uh[p] = id2 & 1;
        uw[p] = ur[p] * 8 + 4 * (uh[p] ^ ((ur[p] >> 2) & 1));
    }
    int aBase[4], bBase[8];
#pragma unroll
    for (int mt = 0; mt < 4; mt++) {
        int r = wm + mt * 16 + g;
        aBase[mt] = r * 8 + (c0 ^ (((r >> 2) & 1) << 2));
    }
#pragma unroll
    for (int nt = 0; nt < 8; nt++) {
        int r = wn + nt * 8 + g;
        bBase[nt] = r * 8 + (c0 ^ (((r >> 2) & 1) << 2));
    }
    float acc[4][8][4];
#pragma unroll
    for (int a = 0; a < 4; a++)
#pragma unroll
        for (int b = 0; b < 8; b++)
#pragma unroll
            for (int c = 0; c < 4; c++) acc[a][b][c] = 0.f;

    float4 pf[8];
    const int NCH = K >> 4;
    auto LDGU = [&](int k0) {
#pragma unroll
        for (int p = 0; p < 4; p++) {
            const float* src = (ut[p] == 0)
                ? Ag + (ll)ur[p] * lda + k0 + 8 * uh[p]
                : Bg + (ll)ur[p] * ldb + k0 + 8 * uh[p];
            pf[2 * p]     = *reinterpret_cast<const float4*>(src);
            pf[2 * p + 1] = *reinterpret_cast<const float4*>(src + 4);
        }
    };
    auto STSU = [&](int buf) {
#pragma unroll
        for (int p = 0; p < 4; p++) {
            float4 f0 = pf[2 * p], f1 = pf[2 * p + 1];
            if (MODE == 0) {
                *reinterpret_cast<uint4*>(&sm[buf][ut[p]][uw[p]]) =
                    make_uint4(pack_hi(f0.x, f0.y), pack_hi(f0.z, f0.w),
                               pack_hi(f1.x, f1.y), pack_hi(f1.z, f1.w));
                *reinterpret_cast<uint4*>(&sm[buf][ut[p] + 1][uw[p]]) =
                    make_uint4(pack_lo(f0.x, f0.y), pack_lo(f0.z, f0.w),
                               pack_lo(f1.x, f1.y), pack_lo(f1.z, f1.w));
            } else {
                *reinterpret_cast<uint4*>(&sm[buf][ut[p]][uw[p]]) =
                    make_uint4(pack_hi16(f0.x, f0.y), pack_hi16(f0.z, f0.w),
                               pack_hi16(f1.x, f1.y), pack_hi16(f1.z, f1.w));
                if (ut[p] == 2)
                    *reinterpret_cast<uint4*>(&sm[buf][3][uw[p]]) =
                        make_uint4(pack_lores16(f0.x, f0.y), pack_lores16(f0.z, f0.w),
                                   pack_lores16(f1.x, f1.y), pack_lores16(f1.z, f1.w));
            }
        }
    };
    LDGU(0); STSU(0); __syncthreads();

    for (int kb = 0; kb < NCH; kb++) {
        int buf = kb & 1;
        if (kb + 1 < NCH) LDGU((kb + 1) << 4);

        const uint32_t* AH = sm[buf][0];
        const uint32_t* AL = sm[buf][1];
        const uint32_t* BH = sm[buf][2];
        const uint32_t* BL = sm[buf][3];

        uint32_t ah[4][4], al[4][4], bH[8][2], bL[8][2];
#pragma unroll
        for (int mt = 0; mt < 4; mt++) {
            int a0 = aBase[mt];
            ah[mt][0] = AH[a0];      ah[mt][1] = AH[a0 + 64];
            ah[mt][2] = AH[a0 ^ 4];  ah[mt][3] = AH[(a0 + 64) ^ 4];
            if (MODE == 0) {
                al[mt][0] = AL[a0];      al[mt][1] = AL[a0 + 64];
                al[mt][2] = AL[a0 ^ 4];  al[mt][3] = AL[(a0 + 64) ^ 4];
            }
        }
#pragma unroll
        for (int nt = 0; nt < 8; nt++) {
            int b0 = bBase[nt];
            bH[nt][0] = BH[b0]; bH[nt][1] = BH[b0 ^ 4];
            bL[nt][0] = BL[b0]; bL[nt][1] = BL[b0 ^ 4];
        }
        if (MODE == 0) {
#pragma unroll
            for (int mt = 0; mt < 4; mt++)
#pragma unroll
                for (int nt = 0; nt < 8; nt++)
                    MMA_BF16(acc[mt][nt], ah[mt], bH[nt][0], bH[nt][1]);
#pragma unroll
            for (int mt = 0; mt < 4; mt++)
#pragma unroll
                for (int nt = 0; nt < 8; nt++)
                    MMA_BF16(acc[mt][nt], al[mt], bH[nt][0], bH[nt][1]);
#pragma unroll
            for (int mt = 0; mt < 4; mt++)
#pragma unroll
                for (int nt = 0; nt < 8; nt++)
                    MMA_BF16(acc[mt][nt], ah[mt], bL[nt][0], bL[nt][1]);
        } else {
#pragma unroll
            for (int mt = 0; mt < 4; mt++)
#pragma unroll
                for (int nt = 0; nt < 8; nt++)
                    MMA_F16(acc[mt][nt], ah[mt], bH[nt][0], bH[nt][1]);
#pragma unroll
            for (int mt = 0; mt < 4; mt++)
#pragma unroll
                for (int nt = 0; nt < 8; nt++)
                    MMA_F16(acc[mt][nt], ah[mt], bL[nt][0], bL[nt][1]);
        }

        if (kb + 1 < NCH) STSU(buf ^ 1);
        __syncthreads();
    }

#pragma unroll
    for (int mt = 0; mt < 4; mt++) {
#pragma unroll
        for (int nt = 0; nt < 8; nt++) {
            int cb = col0 + wn + nt * 8 + 2 * c0;
            float bz0 = bias ? bias[cb] : 0.f;
            float bz1 = bias ? bias[cb + 1] : 0.f;
#pragma unroll
            for (int h = 0; h < 2; h++) {
                int r = row0 + wm + mt * 16 + g + h * 8;
                float v0 = acc[mt][nt][h * 2 + 0] * alpha + bz0;
                float v1 = acc[mt][nt][h * 2 + 1] * alpha + bz1;
                if (act) {
                    v0 = 0.5f * v0 * (1.f + erff(v0 * 0.70710678118654752f));
                    v1 = 0.5f * v1 * (1.f + erff(v1 * 0.70710678118654752f));
                }
                *reinterpret_cast<float2*>(&C[(ll)r * ldc + cb]) = make_float2(v0, v1);
            }
        }
    }
}

// ================= small-tile bf16x3 NT GEMM (64x64, R8 reorder) ========
__global__ __launch_bounds__(128, 4)
void gemm_small(const float* __restrict__ A, const float* __restrict__ B,
                const float* __restrict__ bias, float* __restrict__ C,
                int K, int lda, int ldb, int ldc)
{
    __shared__ uint32_t AsH[1024], AsL[1024], BsH[1024], BsL[1024];
    int tid = threadIdx.x;
    int lane = tid & 31, warp = tid >> 5;
    int g = lane >> 2, c0 = lane & 3;
    int wm = (warp & 1) * 32, wn = (warp >> 1) * 32;
    int row0 = blockIdx.y * 64, col0 = blockIdx.x * 64;
    const float* Ag = A + (ll)row0 * lda;
    const float* Bg = B + (ll)col0 * ldb;

    float acc[2][4][4];
#pragma unroll
    for (int a = 0; a < 2; a++)
#pragma unroll
        for (int b = 0; b < 4; b++)
#pragma unroll
            for (int c = 0; c < 4; c++) acc[a][b][c] = 0.f;

    int aAddr[2][4], bAddr[4][2];
#pragma unroll
    for (int mt = 0; mt < 2; mt++)
#pragma unroll
        for (int i = 0; i < 4; i++) {
            int r = wm + mt * 16 + g + (i & 1) * 8;
            int j = c0 + (i >> 1) * 4;
            aAddr[mt][i] = r * 16 + (j ^ (((r >> 1) & 3) << 2));
        }
#pragma unroll
    for (int nt = 0; nt < 4; nt++)
#pragma unroll
        for (int i = 0; i < 2; i++) {
            int r = wn + nt * 8 + g;
            int j = c0 + i * 4;
            bAddr[nt][i] = r * 16 + (j ^ (((r >> 1) & 3) << 2));
        }

    for (int k0 = 0; k0 < K; k0 += 32) {
        __syncthreads();
#pragma unroll
        for (int p = 0; p < 8; p++) {
            int f = tid + 128 * p;
            int isA = f < 512;
            int fb = f & 511;
            int m = fb >> 3, q = fb & 7;
            const float* src = isA ? Ag + (ll)m * lda + k0 + q * 4
                                   : Bg + (ll)m * ldb + k0 + q * 4;
            float4 f4 = *reinterpret_cast<const float4*>(src);
            uint32_t w0 = m * 16 + ((2 * q) ^ (((m >> 1) & 3) << 2));
            if (isA) {
                *reinterpret_cast<uint2*>(AsH + w0) = make_uint2(pack_hi(f4.x, f4.y), pack_hi(f4.z, f4.w));
                *reinterpret_cast<uint2*>(AsL + w0) = make_uint2(pack_lo(f4.x, f4.y), pack_lo(f4.z, f4.w));
            } else {
                *reinterpret_cast<uint2*>(BsH + w0) = make_uint2(pack_hi(f4.x, f4.y), pack_hi(f4.z, f4.w));
                *reinterpret_cast<uint2*>(BsL + w0) = make_uint2(pack_lo(f4.x, f4.y), pack_lo(f4.z, f4.w));
            }
        }
        __syncthreads();
#pragma unroll
        for (int ks = 0; ks < 2; ks++) {
            int kx = ks * 8;
            uint32_t ah[2][4], al[2][4], bH[4][2], bL[4][2];
#pragma unroll
            for (int mt = 0; mt < 2; mt++)
#pragma unroll
                for (int i = 0; i < 4; i++) {
                    ah[mt][i] = AsH[aAddr[mt][i] ^ kx];
                    al[mt][i] = AsL[aAddr[mt][i] ^ kx];
                }
#pragma unroll
            for (int nt = 0; nt < 4; nt++)
#pragma unroll
                for (int i = 0; i < 2; i++) {
                    bH[nt][i] = BsH[bAddr[nt][i] ^ kx];
                    bL[nt][i] = BsL[bAddr[nt][i] ^ kx];
                }
#pragma unroll
            for (int mt = 0; mt < 2; mt++)
#pragma unroll
                for (int nt = 0; nt < 4; nt++)
                    MMA_BF16(acc[mt][nt], ah[mt], bH[nt][0], bH[nt][1]);
#pragma unroll
            for (int mt = 0; mt < 2; mt++)
#pragma unroll
                for (int nt = 0; nt < 4; nt++)
                    MMA_BF16(acc[mt][nt], al[mt], bH[nt][0], bH[nt][1]);
#pragma unroll
            for (int mt = 0; mt < 2; mt++)
#pragma unroll
                for (int nt = 0; nt < 4; nt++)
                    MMA_BF16(acc[mt][nt], ah[mt], bL[nt][0], bL[nt][1]);
        }
    }
#pragma unroll
    for (int mt = 0; mt < 2; mt++) {
#pragma unroll
        for (int nt = 0; nt < 4; nt++) {
            int cb = col0 + wn + nt * 8 + 2 * c0;
            float bz0 = bias ? bias[cb] : 0.f;
            float bz1 = bias ? bias[cb + 1] : 0.f;
#pragma unroll
            for (int h = 0; h < 2; h++) {
                int r = row0 + wm + mt * 16 + g + h * 8;
                float v0 = acc[mt][nt][h * 2 + 0] + bz0;
                float v1 = acc[mt][nt][h * 2 + 1] + bz1;
                *reinterpret_cast<float2*>(&C[(ll)r * ldc + cb]) = make_float2(v0, v1);
            }
        }
    }
}

// ---------------- elementwise ----------------
__global__ void embed_kernel(const int* __restrict__ ids, const float* __restrict__ emb,
                             const float* __restrict__ pos, float* __restrict__ x) {
    int t = blockIdx.x;
    int id = ids[t];
    int s = t % SS;
    const float* er = emb + (ll)id * HH;
    const float* pr = pos + (ll)s * HH;
    float* xr = x + (ll)t * HH;
    for (int j = threadIdx.x; j < HH; j += blockDim.x) xr[j] = er[j] + pr[j];
}

__global__ void ln_kernel(float* __restrict__ out, const float* __restrict__ a,
                          const float* __restrict__ res, const float* __restrict__ coef,
                          float coef_off, const float* __restrict__ g,
                          const float* __restrict__ bvec, float scale) {
    int t = blockIdx.x;
    __shared__ float red[256];
    float v[4];
    float s = 0.f;
#pragma unroll
    for (int j = 0; j < 4; j++) {
        int h = threadIdx.x + 256 * j;
        float xv = a[(ll)t * HH + h];
        if (res) {
            float c = (coef ? coef[h] : 0.f) + coef_off;
            xv += c * res[(ll)t * HH + h];
        }
        v[j] = xv;
        s += xv;
    }
    red[threadIdx.x] = s; __syncthreads();
    for (int o = 128; o > 0; o >>= 1) { if (threadIdx.x < o) red[threadIdx.x] += red[threadIdx.x + o]; __syncthreads(); }
    float mean = red[0] * (1.f / HH); __syncthreads();
    float s2 = 0.f;
#pragma unroll
    for (int j = 0; j < 4; j++) { float d = v[j] - mean; s2 += d * d; }
    red[threadIdx.x] = s2; __syncthreads();
    for (int o = 128; o > 0; o >>= 1) { if (threadIdx.x < o) red[threadIdx.x] += red[threadIdx.x + o]; __syncthreads(); }
    float rstd = rsqrtf(red[0] * (1.f / HH) + 1e-5f);
#pragma unroll
    for (int j = 0; j < 4; j++) {
        int h = threadIdx.x + 256 * j;
        out[(ll)t * HH + h] = ((v[j] - mean) * rstd * g[h] + bvec[h]) * scale;
    }
}

__global__ void gate_u_kernel(const float* __restrict__ gl, float* __restrict__ u, int n) {
    int i = blockIdx.x * blockDim.x + threadIdx.x;
    if (i < n) u[i] = u[i] / (1.f + expf(-gl[i]));
}

__global__ void scan_kernel(float* __restrict__ u, const float* __restrict__ A_log) {
    int b = blockIdx.x, n = threadIdx.x;
    float a = expf(A_log[n]);
    float s = 0.f;
    ll base = (ll)b * SS * NST + n;
    for (int t0 = 0; t0 < SS; t0 += 8) {
        float uv[8];
#pragma unroll
        for (int j = 0; j < 8; j++) uv[j] = u[base + (ll)(t0 + j) * NST];
#pragma unroll
        for (int j = 0; j < 8; j++) { s = a * s + uv[j]; uv[j] = s; }
#pragma unroll
        for (int j = 0; j < 8; j++) u[base + (ll)(t0 + j) * NST] = uv[j];
    }
}

__global__ void softmax512(float* __restrict__ p) {
    ll row = blockIdx.x;
    float* r = p + row * SS;
    int t = threadIdx.x;
    float v0 = r[t], v1 = r[t + 256];
    __shared__ float red[256];
    red[t] = fmaxf(v0, v1); __syncthreads();
    for (int o = 128; o > 0; o >>= 1) { if (t < o) red[t] = fmaxf(red[t], red[t + o]); __syncthreads(); }
    float m = red[0]; __syncthreads();
    float e0 = expf(v0 - m), e1 = expf(v1 - m);
    red[t] = e0 + e1; __syncthreads();
    for (int o = 128; o > 0; o >>= 1) { if (t < o) red[t] += red[t + o]; __syncthreads(); }
    float inv = 1.f / red[0];
    r[t] = e0 * inv; r[t + 256] = e1 * inv;
}

__global__ void transpose_v(const float* __restrict__ qkv, float* __restrict__ vt) {
    __shared__ float tile[32][33];
    int b = blockIdx.z >> 3, h = blockIdx.z & 7;
    int s0 = blockIdx.x * 32, d0 = blockIdx.y * 32;
    int tx = threadIdx.x, ty = threadIdx.y;
    for (int i = ty; i < 32; i += 8)
        tile[i][tx] = qkv[((ll)(b * SS + s0 + i)) * (3 * HH) + 2 * HH + h * DHD + d0 + tx];
    __syncthreads();
    for (int i = ty; i < 32; i += 8)
        vt[((ll)blockIdx.z * DHD + d0 + i) * SS + s0 + tx] = tile[tx][i];
}

// ---------------- host ----------------
static inline void G(const float* A, const float* B, const float* bias, float* C,
                     int M, int N, int K, int lda, int ldb, int ldc,
                     int mode,                           // 0=bf16x3, 1=fp16x2
                     int batch = 1, int zmod = 1,
                     ll sAa = 0, ll sAb = 0, ll sBa = 0, ll sBb = 0,
                     ll sCa = 0, ll sCb = 0, float alpha = 1.f, int act = 0) {
    ll cm = (N % 128 == 0 && M % 128 == 0)
          ? (ll)(N / 128) * (M / 128) * batch : 0;
    if (cm >= 64) {
        dim3 grid(N / 128, M / 128, batch);
        if (mode == 1)
            gemm_main<1><<<grid, 128>>>(A, B, bias, C, K, lda, ldb, ldc, zmod,
                                        sAa, sAb, sBa, sBb, sCa, sCb, alpha, act);
        else
            gemm_main<0><<<grid, 128>>>(A, B, bias, C, K, lda, ldb, ldc, zmod,
                                        sAa, sAb, sBa, sBb, sCa, sCb, alpha, act);
    } else {
        dim3 grid(N / 64, M / 64, batch);
        gemm_small<<<grid, 128>>>(A, B, bias, C, K, lda, ldb, ldc);
    }
}

extern "C" void kernel_launch(void* const* d_in, const int* in_sizes, int n_in,
                              void* d_out, int out_size) {
    const int*   ids  = (const int*)  d_in[0];
    const float* emb  = (const float*)d_in[1];
    const float* pos  = (const float*)d_in[2];
    const float* A_log= (const float*)d_in[3];
    const float* WB   = (const float*)d_in[4];
    const float* WC   = (const float*)d_in[5];
    const float* Dp   = (const float*)d_in[6];
    const float* Wg   = (const float*)d_in[7];
    const float* bg   = (const float*)d_in[8];
    const float* Wout = (const float*)d_in[9];
    const float* bout = (const float*)d_in[10];
    const float* gs   = (const float*)d_in[11];
    const float* bs   = (const float*)d_in[12];
    const float* Wqkv = (const float*)d_in[13];
    const float* bqkv = (const float*)d_in[14];
    const float* Wo   = (const float*)d_in[15];
    const float* bo   = (const float*)d_in[16];
    const float* W1   = (const float*)d_in[17];
    const float* b1   = (const float*)d_in[18];
    const float* W2   = (const float*)d_in[19];
    const float* b2   = (const float*)d_in[20];
    const float* g1   = (const float*)d_in[21];
    const float* bn1  = (const float*)d_in[22];
    const float* g2   = (const float*)d_in[23];
    const float* bn2  = (const float*)d_in[24];
    const float* g3   = (const float*)d_in[25];
    const float* bn3  = (const float*)d_in[26];
    const float* gf   = (const float*)d_in[27];
    const float* bf   = (const float*)d_in[28];

    float *x, *t1, *t2, *sc, *vt;
    cudaGetSymbolAddress((void**)&x,  g_x);
    cudaGetSymbolAddress((void**)&t1, g_t1);
    cudaGetSymbolAddress((void**)&t2, g_t2);
    cudaGetSymbolAddress((void**)&sc, g_sc);
    cudaGetSymbolAddress((void**)&vt, g_vt);

    embed_kernel<<<TT, 256>>>(ids, emb, pos, x);

    for (int i = 0; i < LL; i++) {
        // ===== SSM =====
        G(x, Wg + (ll)i * NST * HH, bg + (ll)i * NST, t1,
          TT, NST, HH, HH, HH, NST, 0);
        G(x, WB + (ll)i * NST * HH, nullptr, t2,
          TT, NST, HH, HH, HH, NST, 0);
        gate_u_kernel<<<(TT * NST + 255) / 256, 256>>>(t1, t2, TT * NST);
        scan_kernel<<<BB, NST>>>(t2, A_log + (ll)i * NST);
        G(t2, WC + (ll)i * HH * NST, nullptr, t1,
          TT, HH, NST, NST, NST, HH, 1);
        ln_kernel<<<TT, 256>>>(t2, t1, x, Dp + (ll)i * HH, 1.f,
                               gs + (ll)i * HH, bs + (ll)i * HH, 1.f);
        G(t2, Wout + (ll)i * HH * HH, bout + (ll)i * HH, t1,
          TT, HH, HH, HH, HH, HH, 1);
        ln_kernel<<<TT, 256>>>(x, t1, x, nullptr, 1.f,
                               g1 + (ll)i * HH, bn1 + (ll)i * HH, 1.f);

        // ===== attention (odd layers) + memory fold (x2) =====
        if (i & 1) {
            G(x, Wqkv + (ll)i * 3 * HH * HH, bqkv + (ll)i * 3 * HH, t1,
              TT, 3 * HH, HH, HH, HH, 3 * HH, 1);
            float asc = 1.f / sqrtf((float)DHD);
            G(t1, t1 + HH, nullptr, sc, SS, SS, DHD, 3 * HH, 3 * HH, SS, 0,
              BB * NHD, NHD,
              (ll)SS * 3 * HH, DHD,
              (ll)SS * 3 * HH, DHD,
              (ll)NHD * SS * SS, (ll)SS * SS, asc, 0);
            softmax512<<<BB * NHD * SS, 256>>>(sc);
            {
                dim3 tg(SS / 32, DHD / 32, BB * NHD);
                transpose_v<<<tg, dim3(32, 8)>>>(t1, vt);
            }
            G(sc, vt, nullptr, t2, SS, DHD, SS, SS, SS, HH, 0,
              BB * NHD, NHD,
              (ll)NHD * SS * SS, (ll)SS * SS,
              (ll)NHD * DHD * SS, (ll)DHD * SS,
              (ll)SS * HH, DHD, 1.f, 0);
            G(t2, Wo + (ll)i * HH * HH, bo + (ll)i * HH, t1,
              TT, HH, HH, HH, HH, HH, 1);
            ln_kernel<<<TT, 256>>>(x, t1, x, nullptr, 1.f,
                                   g2 + (ll)i * HH, bn2 + (ll)i * HH, 2.f);
        } else {
            ln_kernel<<<TT, 256>>>(x, x, nullptr, nullptr, 0.f,
                                   g2 + (ll)i * HH, bn2 + (ll)i * HH, 2.f);
        }

        // ===== FFN =====
        G(x, W1 + (ll)i * FFD * HH, b1 + (ll)i * FFD, t1,
          TT, FFD, HH, HH, HH, FFD, 1, 1, 1, 0, 0, 0, 0, 0, 0, 1.f, 1);
        G(t1, W2 + (ll)i * HH * FFD, b2 + (ll)i * HH, t2,
          TT, HH, FFD, FFD, FFD, HH, 1);
        ln_kernel<<<TT, 256>>>(x, t2, x, nullptr, 1.f,
                               g3 + (ll)i * HH, bn3 + (ll)i * HH, 1.f);
    }

    // ===== final LN + tied lm_head (fp16x2) =====
    ln_kernel<<<TT, 256>>>(t1, x, nullptr, nullptr, 0.f, gf, bf, 1.f);
    G(t1, emb, nullptr, (float*)d_out, TT, VV, HH, HH, HH, VV, 1);
}

// round 12
// speedup vs baseline: 1.4257x; 1.4257x over previous
#include <cuda_runtime.h>
#include <cuda_bf16.h>
#include <cuda_fp16.h>
#include <math.h>
#include <stdint.h>

#define TT 2048
#define SS 512
#define BB 4
#define HH 1024
#define NST 128
#define LL 6
#define VV 32000
#define NHD 8
#define FFD 4096
#define DHD 128
typedef long long ll;

// ---------------- scratch ----------------
__device__ float g_x [TT * HH];
__device__ float g_t1[TT * FFD];
__device__ float g_t2[TT * FFD];
__device__ float g_sc[BB * NHD * SS * SS];
__device__ float g_vt[BB * NHD * DHD * SS];

// bf16 packers
__device__ __forceinline__ uint32_t pack_hi(float x, float y) {
    __nv_bfloat162 h = __floats2bfloat162_rn(x, y);
    return *reinterpret_cast<uint32_t*>(&h);
}
__device__ __forceinline__ uint32_t pack_lo(float x, float y) {
    float hx = __bfloat162float(__float2bfloat16_rn(x));
    float hy = __bfloat162float(__float2bfloat16_rn(y));
    __nv_bfloat162 l = __floats2bfloat162_rn(x - hx, y - hy);
    return *reinterpret_cast<uint32_t*>(&l);
}
// fp16 packers
__device__ __forceinline__ uint32_t pack_hi16(float x, float y) {
    __half2 h = __floats2half2_rn(x, y);
    return *reinterpret_cast<uint32_t*>(&h);
}
__device__ __forceinline__ uint32_t pack_lores16(float x, float y) {
    float hx = __half2float(__float2half_rn(x));
    float hy = __half2float(__float2half_rn(y));
    __half2 l = __floats2half2_rn(x - hx, y - hy);   // unscaled residual
    return *reinterpret_cast<uint32_t*>(&l);
}

#define MMA_BF16(ACC, AFR, BF0, BF1)                                            \
    asm volatile(                                                               \
        "mma.sync.aligned.m16n8k16.row.col.f32.bf16.bf16.f32 "                  \
        "{%0,%1,%2,%3}, {%4,%5,%6,%7}, {%8,%9}, {%0,%1,%2,%3};"                 \
        : "+f"((ACC)[0]), "+f"((ACC)[1]), "+f"((ACC)[2]), "+f"((ACC)[3])        \
        : "r"((AFR)[0]), "r"((AFR)[1]), "r"((AFR)[2]), "r"((AFR)[3]),           \
          "r"(BF0), "r"(BF1))

#define MMA_F16(ACC, AFR, BF0, BF1)                                             \
    asm volatile(                                                               \
        "mma.sync.aligned.m16n8k16.row.col.f32.f16.f16.f32 "                    \
        "{%0,%1,%2,%3}, {%4,%5,%6,%7}, {%8,%9}, {%0,%1,%2,%3};"                 \
        : "+f"((ACC)[0]), "+f"((ACC)[1]), "+f"((ACC)[2]), "+f"((ACC)[3])        \
        : "r"((AFR)[0]), "r"((AFR)[1]), "r"((AFR)[2]), "r"((AFR)[3]),           \
          "r"(BF0), "r"(BF1))

// ================= R10 bf16x3 NT GEMM (128x128, GBK=16, 3 separated passes) ===
__global__ __launch_bounds__(128, 2)
void gemm_main(const float* __restrict__ A, const float* __restrict__ B,
               const float* __restrict__ bias, float* __restrict__ C,
               int K, int lda, int ldb, int ldc, int zmod,
               ll sAa, ll sAb, ll sBa, ll sBb, ll sCa, ll sCb, float alpha, int act)
{
    __shared__ uint32_t sm[2][4][1024];

    int tid = threadIdx.x;
    int lane = tid & 31, warp = tid >> 5;
    int g = lane >> 2, c0 = lane & 3;
    int wm = (warp & 1) * 64, wn = (warp >> 1) * 64;

    int z = blockIdx.z;
    int zq = z / zmod, zr = z % zmod;
    A += (ll)zq * sAa + (ll)zr * sAb;
    B += (ll)zq * sBa + (ll)zr * sBb;
    C += (ll)zq * sCa + (ll)zr * sCb;

    int row0 = blockIdx.y * 128, col0 = blockIdx.x * 128;
    const float* Ag = A + (ll)row0 * lda;
    const float* Bg = B + (ll)col0 * ldb;

    int ur[4], uh[4], uw[4], ut[4];
#pragma unroll
    for (int p = 0; p < 4; p++) {
        int id = tid + 128 * p;
        ut[p] = (id < 256) ? 0 : 2;
        int id2 = id & 255;
        ur[p] = id2 >> 1; uh[p] = id2 & 1;
        uw[p] = ur[p] * 8 + 4 * (uh[p] ^ ((ur[p] >> 2) & 1));
    }
    int aBase[4], bBase[8];
#pragma unroll
    for (int mt = 0; mt < 4; mt++) {
        int r = wm + mt * 16 + g;
        aBase[mt] = r * 8 + (c0 ^ (((r >> 2) & 1) << 2));
    }
#pragma unroll
    for (int nt = 0; nt < 8; nt++) {
        int r = wn + nt * 8 + g;
        bBase[nt] = r * 8 + (c0 ^ (((r >> 2) & 1) << 2));
    }
    float acc[4][8][4];
#pragma unroll
    for (int a = 0; a < 4; a++)
#pragma unroll
        for (int b = 0; b < 8; b++)
#pragma unroll
            for (int c = 0; c < 4; c++) acc[a][b][c] = 0.f;

    float4 pf[8];
    const int NCH = K >> 4;
    auto LDGU = [&](int k0) {
#pragma unroll
        for (int p = 0; p < 4; p++) {
            const float* src = (ut[p] == 0)
                ? Ag + (ll)ur[p] * lda + k0 + 8 * uh[p]
                : Bg + (ll)ur[p] * ldb + k0 + 8 * uh[p];
            pf[2 * p]     = *reinterpret_cast<const float4*>(src);
            pf[2 * p + 1] = *reinterpret_cast<const float4*>(src + 4);
        }
    };
    auto STSU = [&](int buf) {
#pragma unroll
        for (int p = 0; p < 4; p++) {
            float4 f0 = pf[2 * p], f1 = pf[2 * p + 1];
            *reinterpret_cast<uint4*>(&sm[buf][ut[p]][uw[p]]) =
                make_uint4(pack_hi(f0.x, f0.y), pack_hi(f0.z, f0.w),
                           pack_hi(f1.x, f1.y), pack_hi(f1.z, f1.w));
            *reinterpret_cast<uint4*>(&sm[buf][ut[p] + 1][uw[p]]) =
                make_uint4(pack_lo(f0.x, f0.y), pack_lo(f0.z, f0.w),
                           pack_lo(f1.x, f1.y), pack_lo(f1.z, f1.w));
        }
    };
    LDGU(0); STSU(0); __syncthreads();

    for (int kb = 0; kb < NCH; kb++) {
        int buf = kb & 1;
        if (kb + 1 < NCH) LDGU((kb + 1) << 4);

        const uint32_t* AH = sm[buf][0];
        const uint32_t* AL = sm[buf][1];
        const uint32_t* BH = sm[buf][2];
        const uint32_t* BL = sm[buf][3];

        uint32_t ah[4][4], al[4][4], bH[8][2], bL[8][2];
#pragma unroll
        for (int mt = 0; mt < 4; mt++) {
            int a0 = aBase[mt];
            ah[mt][0] = AH[a0];      ah[mt][1] = AH[a0 + 64];
            ah[mt][2] = AH[a0 ^ 4];  ah[mt][3] = AH[(a0 + 64) ^ 4];
            al[mt][0] = AL[a0];      al[mt][1] = AL[a0 + 64];
            al[mt][2] = AL[a0 ^ 4];  al[mt][3] = AL[(a0 + 64) ^ 4];
        }
#pragma unroll
        for (int nt = 0; nt < 8; nt++) {
            int b0 = bBase[nt];
            bH[nt][0] = BH[b0]; bH[nt][1] = BH[b0 ^ 4];
            bL[nt][0] = BL[b0]; bL[nt][1] = BL[b0 ^ 4];
        }
#pragma unroll
        for (int mt = 0; mt < 4; mt++)
#pragma unroll
            for (int nt = 0; nt < 8; nt++)
                MMA_BF16(acc[mt][nt], ah[mt], bH[nt][0], bH[nt][1]);
#pragma unroll
        for (int mt = 0; mt < 4; mt++)
#pragma unroll
            for (int nt = 0; nt < 8; nt++)
                MMA_BF16(acc[mt][nt], al[mt], bH[nt][0], bH[nt][1]);
#pragma unroll
        for (int mt = 0; mt < 4; mt++)
#pragma unroll
            for (int nt = 0; nt < 8; nt++)
                MMA_BF16(acc[mt][nt], ah[mt], bL[nt][0], bL[nt][1]);

        if (kb + 1 < NCH) STSU(buf ^ 1);
        __syncthreads();
    }

#pragma unroll
    for (int mt = 0; mt < 4; mt++) {
#pragma unroll
        for (int nt = 0; nt < 8; nt++) {
            int cb = col0 + wn + nt * 8 + 2 * c0;
            float bz0 = bias ? bias[cb] : 0.f;
            float bz1 = bias ? bias[cb + 1] : 0.f;
#pragma unroll
            for (int h = 0; h < 2; h++) {
                int r = row0 + wm + mt * 16 + g + h * 8;
                float v0 = acc[mt][nt][h * 2 + 0] * alpha + bz0;
                float v1 = acc[mt][nt][h * 2 + 1] * alpha + bz1;
                if (act) {
                    v0 = 0.5f * v0 * (1.f + erff(v0 * 0.70710678118654752f));
                    v1 = 0.5f * v1 * (1.f + erff(v1 * 0.70710678118654752f));
                }
                *reinterpret_cast<float2*>(&C[(ll)r * ldc + cb]) = make_float2(v0, v1);
            }
        }
    }
}

// ================= fp16x2 NT GEMM — exact clone of R10's fast gemm_lmh =======
// A = fp16 hi only; B = fp16 hi + unscaled residual. Two passes into one
// fp32 accumulator. Extended ONLY with bias/alpha/act epilogue.
__global__ __launch_bounds__(128, 2)
void gemm_f16(const float* __restrict__ A, const float* __restrict__ B,
              const float* __restrict__ bias, float* __restrict__ C,
              int K, int lda, int ldb, int ldc, float alpha, int act)
{
    __shared__ uint32_t sm[2][3][1024];   // [buf][AsH,BsH,BsL]

    int tid = threadIdx.x;
    int lane = tid & 31, warp = tid >> 5;
    int g = lane >> 2, c0 = lane & 3;
    int wm = (warp & 1) * 64, wn = (warp >> 1) * 64;

    int row0 = blockIdx.y * 128, col0 = blockIdx.x * 128;
    const float* Ag = A + (ll)row0 * lda;
    const float* Bg = B + (ll)col0 * ldb;

    int ur[4], uh[4], uw[4], ut[4];
#pragma unroll
    for (int p = 0; p < 4; p++) {
        int id = tid + 128 * p;
        ut[p] = (id < 256) ? 0 : 1;          // 0 = A unit, 1 = B unit
        int id2 = id & 255;
        ur[p] = id2 >> 1; uh[p] = id2 & 1;
        uw[p] = ur[p] * 8 + 4 * (uh[p] ^ ((ur[p] >> 2) & 1));
    }
    int aBase[4], bBase[8];
#pragma unroll
    for (int mt = 0; mt < 4; mt++) {
        int r = wm + mt * 16 + g;
        aBase[mt] = r * 8 + (c0 ^ (((r >> 2) & 1) << 2));
    }
#pragma unroll
    for (int nt = 0; nt < 8; nt++) {
        int r = wn + nt * 8 + g;
        bBase[nt] = r * 8 + (c0 ^ (((r >> 2) & 1) << 2));
    }
    float acc[4][8][4];
#pragma unroll
    for (int a = 0; a < 4; a++)
#pragma unroll
        for (int b = 0; b < 8; b++)
#pragma unroll
            for (int c = 0; c < 4; c++) acc[a][b][c] = 0.f;

    float4 pf[8];
    const int NCH = K >> 4;
    auto LDGU = [&](int k0) {
#pragma unroll
        for (int p = 0; p < 4; p++) {
            const float* src = (ut[p] == 0)
                ? Ag + (ll)ur[p] * lda + k0 + 8 * uh[p]
                : Bg + (ll)ur[p] * ldb + k0 + 8 * uh[p];
            pf[2 * p]     = *reinterpret_cast<const float4*>(src);
            pf[2 * p + 1] = *reinterpret_cast<const float4*>(src + 4);
        }
    };
    auto STSU = [&](int buf) {
#pragma unroll
        for (int p = 0; p < 4; p++) {
            float4 f0 = pf[2 * p], f1 = pf[2 * p + 1];
            if (ut[p] == 0) {
                *reinterpret_cast<uint4*>(&sm[buf][0][uw[p]]) =
                    make_uint4(pack_hi16(f0.x, f0.y), pack_hi16(f0.z, f0.w),
                               pack_hi16(f1.x, f1.y), pack_hi16(f1.z, f1.w));
            } else {
                *reinterpret_cast<uint4*>(&sm[buf][1][uw[p]]) =
                    make_uint4(pack_hi16(f0.x, f0.y), pack_hi16(f0.z, f0.w),
                               pack_hi16(f1.x, f1.y), pack_hi16(f1.z, f1.w));
                *reinterpret_cast<uint4*>(&sm[buf][2][uw[p]]) =
                    make_uint4(pack_lores16(f0.x, f0.y), pack_lores16(f0.z, f0.w),
                               pack_lores16(f1.x, f1.y), pack_lores16(f1.z, f1.w));
            }
        }
    };
    LDGU(0); STSU(0); __syncthreads();

    for (int kb = 0; kb < NCH; kb++) {
        int buf = kb & 1;
        if (kb + 1 < NCH) LDGU((kb + 1) << 4);

        const uint32_t* AH = sm[buf][0];
        const uint32_t* BH = sm[buf][1];
        const uint32_t* BL = sm[buf][2];

        uint32_t ah[4][4], bH[8][2], bL[8][2];
#pragma unroll
        for (int mt = 0; mt < 4; mt++) {
            int a0 = aBase[mt];
            ah[mt][0] = AH[a0];      ah[mt][1] = AH[a0 + 64];
            ah[mt][2] = AH[a0 ^ 4];  ah[mt][3] = AH[(a0 + 64) ^ 4];
        }
#pragma unroll
        for (int nt = 0; nt < 8; nt++) {
            int b0 = bBase[nt];
            bH[nt][0] = BH[b0]; bH[nt][1] = BH[b0 ^ 4];
            bL[nt][0] = BL[b0]; bL[nt][1] = BL[b0 ^ 4];
        }
        // pass 1: hi*hi
#pragma unroll
        for (int mt = 0; mt < 4; mt++)
#pragma unroll
            for (int nt = 0; nt < 8; nt++)
                MMA_F16(acc[mt][nt], ah[mt], bH[nt][0], bH[nt][1]);
        // pass 2: hi*residual (same accumulator, RAW distance 32)
#pragma unroll
        for (int mt = 0; mt < 4; mt++)
#pragma unroll
            for (int nt = 0; nt < 8; nt++)
                MMA_F16(acc[mt][nt], ah[mt], bL[nt][0], bL[nt][1]);

        if (kb + 1 < NCH) STSU(buf ^ 1);
        __syncthreads();
    }

#pragma unroll
    for (int mt = 0; mt < 4; mt++) {
#pragma unroll
        for (int nt = 0; nt < 8; nt++) {
            int cb = col0 + wn + nt * 8 + 2 * c0;
            float bz0 = bias ? bias[cb] : 0.f;
            float bz1 = bias ? bias[cb + 1] : 0.f;
#pragma unroll
            for (int h = 0; h < 2; h++) {
                int r = row0 + wm + mt * 16 + g + h * 8;
                float v0 = acc[mt][nt][h * 2 + 0] * alpha + bz0;
                float v1 = acc[mt][nt][h * 2 + 1] * alpha + bz1;
                if (act) {
                    v0 = 0.5f * v0 * (1.f + erff(v0 * 0.70710678118654752f));
                    v1 = 0.5f * v1 * (1.f + erff(v1 * 0.70710678118654752f));
                }
                *reinterpret_cast<float2*>(&C[(ll)r * ldc + cb]) = make_float2(v0, v1);
            }
        }
    }
}

// ================= small-tile bf16x3 NT GEMM (64x64, R8 reorder) ========
__global__ __launch_bounds__(128, 4)
void gemm_small(const float* __restrict__ A, const float* __restrict__ B,
                const float* __restrict__ bias, float* __restrict__ C,
                int K, int lda, int ldb, int ldc)
{
    __shared__ uint32_t AsH[1024], AsL[1024], BsH[1024], BsL[1024];
    int tid = threadIdx.x;
    int lane = tid & 31, warp = tid >> 5;
    int g = lane >> 2, c0 = lane & 3;
    int wm = (warp & 1) * 32, wn = (warp >> 1) * 32;
    int row0 = blockIdx.y * 64, col0 = blockIdx.x * 64;
    const float* Ag = A + (ll)row0 * lda;
    const float* Bg = B + (ll)col0 * ldb;

    float acc[2][4][4];
#pragma unroll
    for (int a = 0; a < 2; a++)
#pragma unroll
        for (int b = 0; b < 4; b++)
#pragma unroll
            for (int c = 0; c < 4; c++) acc[a][b][c] = 0.f;

    int aAddr[2][4], bAddr[4][2];
#pragma unroll
    for (int mt = 0; mt < 2; mt++)
#pragma unroll
        for (int i = 0; i < 4; i++) {
            int r = wm + mt * 16 + g + (i & 1) * 8;
            int j = c0 + (i >> 1) * 4;
            aAddr[mt][i] = r * 16 + (j ^ (((r >> 1) & 3) << 2));
        }
#pragma unroll
    for (int nt = 0; nt < 4; nt++)
#pragma unroll
        for (int i = 0; i < 2; i++) {
            int r = wn + nt * 8 + g;
            int j = c0 + i * 4;
            bAddr[nt][i] = r * 16 + (j ^ (((r >> 1) & 3) << 2));
        }

    for (int k0 = 0; k0 < K; k0 += 32) {
        __syncthreads();
#pragma unroll
        for (int p = 0; p < 8; p++) {
            int f = tid + 128 * p;
            int isA = f < 512;
            int fb = f & 511;
            int m = fb >> 3, q = fb & 7;
            const float* src = isA ? Ag + (ll)m * lda + k0 + q * 4
                                   : Bg + (ll)m * ldb + k0 + q * 4;
            float4 f4 = *reinterpret_cast<const float4*>(src);
            uint32_t w0 = m * 16 + ((2 * q) ^ (((m >> 1) & 3) << 2));
            if (isA) {
                *reinterpret_cast<uint2*>(AsH + w0) = make_uint2(pack_hi(f4.x, f4.y), pack_hi(f4.z, f4.w));
                *reinterpret_cast<uint2*>(AsL + w0) = make_uint2(pack_lo(f4.x, f4.y), pack_lo(f4.z, f4.w));
            } else {
                *reinterpret_cast<uint2*>(BsH + w0) = make_uint2(pack_hi(f4.x, f4.y), pack_hi(f4.z, f4.w));
                *reinterpret_cast<uint2*>(BsL + w0) = make_uint2(pack_lo(f4.x, f4.y), pack_lo(f4.z, f4.w));
            }
        }
        __syncthreads();
#pragma unroll
        for (int ks = 0; ks < 2; ks++) {
            int kx = ks * 8;
            uint32_t ah[2][4], al[2][4], bH[4][2], bL[4][2];
#pragma unroll
            for (int mt = 0; mt < 2; mt++)
#pragma unroll
                for (int i = 0; i < 4; i++) {
                    ah[mt][i] = AsH[aAddr[mt][i] ^ kx];
                    al[mt][i] = AsL[aAddr[mt][i] ^ kx];
                }
#pragma unroll
            for (int nt = 0; nt < 4; nt++)
#pragma unroll
                for (int i = 0; i < 2; i++) {
                    bH[nt][i] = BsH[bAddr[nt][i] ^ kx];
                    bL[nt][i] = BsL[bAddr[nt][i] ^ kx];
                }
#pragma unroll
            for (int mt = 0; mt < 2; mt++)
#pragma unroll
                for (int nt = 0; nt < 4; nt++)
                    MMA_BF16(acc[mt][nt], ah[mt], bH[nt][0], bH[nt][1]);
#pragma unroll
            for (int mt = 0; mt < 2; mt++)
#pragma unroll
                for (int nt = 0; nt < 4; nt++)
                    MMA_BF16(acc[mt][nt], al[mt], bH[nt][0], bH[nt][1]);
#pragma unroll
            for (int mt = 0; mt < 2; mt++)
#pragma unroll
                for (int nt = 0; nt < 4; nt++)
                    MMA_BF16(acc[mt][nt], ah[mt], bL[nt][0], bL[nt][1]);
        }
    }
#pragma unroll
    for (int mt = 0; mt < 2; mt++) {
#pragma unroll
        for (int nt = 0; nt < 4; nt++) {
            int cb = col0 + wn + nt * 8 + 2 * c0;
            float bz0 = bias ? bias[cb] : 0.f;
            float bz1 = bias ? bias[cb + 1] : 0.f;
#pragma unroll
            for (int h = 0; h < 2; h++) {
                int r = row0 + wm + mt * 16 + g + h * 8;
                float v0 = acc[mt][nt][h * 2 + 0] + bz0;
                float v1 = acc[mt][nt][h * 2 + 1] + bz1;
                *reinterpret_cast<float2*>(&C[(ll)r * ldc + cb]) = make_float2(v0, v1);
            }
        }
    }
}

// ---------------- elementwise ----------------
__global__ void embed_kernel(const int* __restrict__ ids, const float* __restrict__ emb,
                             const float* __restrict__ pos, float* __restrict__ x) {
    int t = blockIdx.x;
    int id = ids[t];
    int s = t % SS;
    const float* er = emb + (ll)id * HH;
    const float* pr = pos + (ll)s * HH;
    float* xr = x + (ll)t * HH;
    for (int j = threadIdx.x; j < HH; j += blockDim.x) xr[j] = er[j] + pr[j];
}

__global__ void ln_kernel(float* __restrict__ out, const float* __restrict__ a,
                          const float* __restrict__ res, const float* __restrict__ coef,
                          float coef_off, const float* __restrict__ g,
                          const float* __restrict__ bvec, float scale) {
    int t = blockIdx.x;
    __shared__ float red[256];
    float v[4];
    float s = 0.f;
#pragma unroll
    for (int j = 0; j < 4; j++) {
        int h = threadIdx.x + 256 * j;
        float xv = a[(ll)t * HH + h];
        if (res) {
            float c = (coef ? coef[h] : 0.f) + coef_off;
            xv += c * res[(ll)t * HH + h];
        }
        v[j] = xv;
        s += xv;
    }
    red[threadIdx.x] = s; __syncthreads();
    for (int o = 128; o > 0; o >>= 1) { if (threadIdx.x < o) red[threadIdx.x] += red[threadIdx.x + o]; __syncthreads(); }
    float mean = red[0] * (1.f / HH); __syncthreads();
    float s2 = 0.f;
#pragma unroll
    for (int j = 0; j < 4; j++) { float d = v[j] - mean; s2 += d * d; }
    red[threadIdx.x] = s2; __syncthreads();
    for (int o = 128; o > 0; o >>= 1) { if (threadIdx.x < o) red[threadIdx.x] += red[threadIdx.x + o]; __syncthreads(); }
    float rstd = rsqrtf(red[0] * (1.f / HH) + 1e-5f);
#pragma unroll
    for (int j = 0; j < 4; j++) {
        int h = threadIdx.x + 256 * j;
        out[(ll)t * HH + h] = ((v[j] - mean) * rstd * g[h] + bvec[h]) * scale;
    }
}

__global__ void gate_u_kernel(const float* __restrict__ gl, float* __restrict__ u, int n) {
    int i = blockIdx.x * blockDim.x + threadIdx.x;
    if (i < n) u[i] = u[i] / (1.f + expf(-gl[i]));
}

__global__ void scan_kernel(float* __restrict__ u, const float* __restrict__ A_log) {
    int b = blockIdx.x, n = threadIdx.x;
    float a = expf(A_log[n]);
    float s = 0.f;
    ll base = (ll)b * SS * NST + n;
    for (int t0 = 0; t0 < SS; t0 += 8) {
        float uv[8];
#pragma unroll
        for (int j = 0; j < 8; j++) uv[j] = u[base + (ll)(t0 + j) * NST];
#pragma unroll
        for (int j = 0; j < 8; j++) { s = a * s + uv[j]; uv[j] = s; }
#pragma unroll
        for (int j = 0; j < 8; j++) u[base + (ll)(t0 + j) * NST] = uv[j];
    }
}

__global__ void softmax512(float* __restrict__ p) {
    ll row = blockIdx.x;
    float* r = p + row * SS;
    int t = threadIdx.x;
    float v0 = r[t], v1 = r[t + 256];
    __shared__ float red[256];
    red[t] = fmaxf(v0, v1); __syncthreads();
    for (int o = 128; o > 0; o >>= 1) { if (t < o) red[t] = fmaxf(red[t], red[t + o]); __syncthreads(); }
    float m = red[0]; __syncthreads();
    float e0 = expf(v0 - m), e1 = expf(v1 - m);
    red[t] = e0 + e1; __syncthreads();
    for (int o = 128; o > 0; o >>= 1) { if (t < o) red[t] += red[t + o]; __syncthreads(); }
    float inv = 1.f / red[0];
    r[t] = e0 * inv; r[t + 256] = e1 * inv;
}

__global__ void transpose_v(const float* __restrict__ qkv, float* __restrict__ vt) {
    __shared__ float tile[32][33];
    int b = blockIdx.z >> 3, h = blockIdx.z & 7;
    int s0 = blockIdx.x * 32, d0 = blockIdx.y * 32;
    int tx = threadIdx.x, ty = threadIdx.y;
    for (int i = ty; i < 32; i += 8)
        tile[i][tx] = qkv[((ll)(b * SS + s0 + i)) * (3 * HH) + 2 * HH + h * DHD + d0 + tx];
    __syncthreads();
    for (int i = ty; i < 32; i += 8)
        vt[((ll)blockIdx.z * DHD + d0 + i) * SS + s0 + tx] = tile[tx][i];
}

// ---------------- host ----------------
// bf16x3 (attention, batched) path
static inline void GB(const float* A, const float* B, const float* bias, float* C,
                      int M, int N, int K, int lda, int ldb, int ldc,
                      int batch, int zmod,
                      ll sAa, ll sAb, ll sBa, ll sBb, ll sCa, ll sCb,
                      float alpha, int act) {
    dim3 grid(N / 128, M / 128, batch);
    gemm_main<<<grid, 128>>>(A, B, bias, C, K, lda, ldb, ldc, zmod,
                             sAa, sAb, sBa, sBb, sCa, sCb, alpha, act);
}
// fp16x2 (weight GEMMs + lm_head) path
static inline void GF(const float* A, const float* B, const float* bias, float* C,
                      int M, int N, int K, int lda, int ldb, int ldc,
                      float alpha = 1.f, int act = 0) {
    dim3 grid(N / 128, M / 128);
    gemm_f16<<<grid, 128>>>(A, B, bias, C, K, lda, ldb, ldc, alpha, act);
}
// small bf16x3 path (Wg/WB)
static inline void GS(const float* A, const float* B, const float* bias, float* C,
                      int M, int N, int K, int lda, int ldb, int ldc) {
    dim3 grid(N / 64, M / 64);
    gemm_small<<<grid, 128>>>(A, B, bias, C, K, lda, ldb, ldc);
}

extern "C" void kernel_launch(void* const* d_in, const int* in_sizes, int n_in,
                              void* d_out, int out_size) {
    const int*   ids  = (const int*)  d_in[0];
    const float* emb  = (const float*)d_in[1];
    const float* pos  = (const float*)d_in[2];
    const float* A_log= (const float*)d_in[3];
    const float* WB   = (const float*)d_in[4];
    const float* WC   = (const float*)d_in[5];
    const float* Dp   = (const float*)d_in[6];
    const float* Wg   = (const float*)d_in[7];
    const float* bg   = (const float*)d_in[8];
    const float* Wout = (const float*)d_in[9];
    const float* bout = (const float*)d_in[10];
    const float* gs   = (const float*)d_in[11];
    const float* bs   = (const float*)d_in[12];
    const float* Wqkv = (const float*)d_in[13];
    const float* bqkv = (const float*)d_in[14];
    const float* Wo   = (const float*)d_in[15];
    const float* bo   = (const float*)d_in[16];
    const float* W1   = (const float*)d_in[17];
    const float* b1   = (const float*)d_in[18];
    const float* W2   = (const float*)d_in[19];
    const float* b2   = (const float*)d_in[20];
    const float* g1   = (const float*)d_in[21];
    const float* bn1  = (const float*)d_in[22];
    const float* g2   = (const float*)d_in[23];
    const float* bn2  = (const float*)d_in[24];
    const float* g3   = (const float*)d_in[25];
    const float* bn3  = (const float*)d_in[26];
    const float* gf   = (const float*)d_in[27];
    const float* bf   = (const float*)d_in[28];

    float *x, *t1, *t2, *sc, *vt;
    cudaGetSymbolAddress((void**)&x,  g_x);
    cudaGetSymbolAddress((void**)&t1, g_t1);
    cudaGetSymbolAddress((void**)&t2, g_t2);
    cudaGetSymbolAddress((void**)&sc, g_sc);
    cudaGetSymbolAddress((void**)&vt, g_vt);

    embed_kernel<<<TT, 256>>>(ids, emb, pos, x);

    for (int i = 0; i < LL; i++) {
        // ===== SSM =====
        GS(x, Wg + (ll)i * NST * HH, bg + (ll)i * NST, t1, TT, NST, HH, HH, HH, NST);
        GS(x, WB + (ll)i * NST * HH, nullptr,          t2, TT, NST, HH, HH, HH, NST);
        gate_u_kernel<<<(TT * NST + 255) / 256, 256>>>(t1, t2, TT * NST);
        scan_kernel<<<BB, NST>>>(t2, A_log + (ll)i * NST);
        GF(t2, WC + (ll)i * HH * NST, nullptr, t1, TT, HH, NST, NST, NST, HH);
        ln_kernel<<<TT, 256>>>(t2, t1, x, Dp + (ll)i * HH, 1.f,
                               gs + (ll)i * HH, bs + (ll)i * HH, 1.f);
        GF(t2, Wout + (ll)i * HH * HH, bout + (ll)i * HH, t1, TT, HH, HH, HH, HH, HH);
        ln_kernel<<<TT, 256>>>(x, t1, x, nullptr, 1.f,
                               g1 + (ll)i * HH, bn1 + (ll)i * HH, 1.f);

        // ===== attention (odd layers) + memory fold (x2) =====
        if (i & 1) {
            GF(x, Wqkv + (ll)i * 3 * HH * HH, bqkv + (ll)i * 3 * HH, t1,
               TT, 3 * HH, HH, HH, HH, 3 * HH);
            float asc = 1.f / sqrtf((float)DHD);
            GB(t1, t1 + HH, nullptr, sc, SS, SS, DHD, 3 * HH, 3 * HH, SS,
               BB * NHD, NHD,
               (ll)SS * 3 * HH, DHD,
               (ll)SS * 3 * HH, DHD,
               (ll)NHD * SS * SS, (ll)SS * SS, asc, 0);
            softmax512<<<BB * NHD * SS, 256>>>(sc);
            {
                dim3 tg(SS / 32, DHD / 32, BB * NHD);
                transpose_v<<<tg, dim3(32, 8)>>>(t1, vt);
            }
            GB(sc, vt, nullptr, t2, SS, DHD, SS, SS, SS, HH,
               BB * NHD, NHD,
               (ll)NHD * SS * SS, (ll)SS * SS,
               (ll)NHD * DHD * SS, (ll)DHD * SS,
               (ll)SS * HH, DHD, 1.f, 0);
            GF(t2, Wo + (ll)i * HH * HH, bo + (ll)i * HH, t1, TT, HH, HH, HH, HH, HH);
            ln_kernel<<<TT, 256>>>(x, t1, x, nullptr, 1.f,
                                   g2 + (ll)i * HH, bn2 + (ll)i * HH, 2.f);
        } else {
            ln_kernel<<<TT, 256>>>(x, x, nullptr, nullptr, 0.f,
                                   g2 + (ll)i * HH, bn2 + (ll)i * HH, 2.f);
        }

        // ===== FFN =====
        GF(x, W1 + (ll)i * FFD * HH, b1 + (ll)i * FFD, t1,
           TT, FFD, HH, HH, HH, FFD, 1.f, 1);
        GF(t1, W2 + (ll)i * HH * FFD, b2 + (ll)i * HH, t2,
           TT, HH, FFD, FFD, FFD, HH);
        ln_kernel<<<TT, 256>>>(x, t2, x, nullptr, 1.f,
                               g3 + (ll)i * HH, bn3 + (ll)i * HH, 1.f);
    }

    // ===== final LN + tied lm_head (fp16x2) =====
    ln_kernel<<<TT, 256>>>(t1, x, nullptr, nullptr, 0.f, gf, bf, 1.f);
    GF(t1, emb, nullptr, (float*)d_out, TT, VV, HH, HH, HH, VV);
}

// round 13
// speedup vs baseline: 1.5057x; 1.0561x over previous
#include <cuda_runtime.h>
#include <cuda_bf16.h>
#include <cuda_fp16.h>
#include <math.h>
#include <stdint.h>

#define TT 2048
#define SS 512
#define BB 4
#define HH 1024
#define NST 128
#define LL 6
#define VV 32000
#define NHD 8
#define FFD 4096
#define DHD 128
typedef long long ll;

// ---------------- scratch ----------------
__device__ float g_x [TT * HH];
__device__ float g_t1[TT * FFD];
__device__ float g_t2[TT * FFD];
__device__ float g_sc[BB * NHD * SS * SS];
__device__ float g_vt[BB * NHD * DHD * SS];

// bf16 packers
__device__ __forceinline__ uint32_t pack_hi(float x, float y) {
    __nv_bfloat162 h = __floats2bfloat162_rn(x, y);
    return *reinterpret_cast<uint32_t*>(&h);
}
__device__ __forceinline__ uint32_t pack_lo(float x, float y) {
    float hx = __bfloat162float(__float2bfloat16_rn(x));
    float hy = __bfloat162float(__float2bfloat16_rn(y));
    __nv_bfloat162 l = __floats2bfloat162_rn(x - hx, y - hy);
    return *reinterpret_cast<uint32_t*>(&l);
}
// fp16 packers
__device__ __forceinline__ uint32_t pack_hi16(float x, float y) {
    __half2 h = __floats2half2_rn(x, y);
    return *reinterpret_cast<uint32_t*>(&h);
}
__device__ __forceinline__ uint32_t pack_lores16(float x, float y) {
    float hx = __half2float(__float2half_rn(x));
    float hy = __half2float(__float2half_rn(y));
    __half2 l = __floats2half2_rn(x - hx, y - hy);   // unscaled residual
    return *reinterpret_cast<uint32_t*>(&l);
}

#define MMA_BF16(ACC, AFR, BF0, BF1)                                            \
    asm volatile(                                                               \
        "mma.sync.aligned.m16n8k16.row.col.f32.bf16.bf16.f32 "                  \
        "{%0,%1,%2,%3}, {%4,%5,%6,%7}, {%8,%9}, {%0,%1,%2,%3};"                 \
        : "+f"((ACC)[0]), "+f"((ACC)[1]), "+f"((ACC)[2]), "+f"((ACC)[3])        \
        : "r"((AFR)[0]), "r"((AFR)[1]), "r"((AFR)[2]), "r"((AFR)[3]),           \
          "r"(BF0), "r"(BF1))

#define MMA_F16(ACC, AFR, BF0, BF1)                                             \
    asm volatile(                                                               \
        "mma.sync.aligned.m16n8k16.row.col.f32.f16.f16.f32 "                    \
        "{%0,%1,%2,%3}, {%4,%5,%6,%7}, {%8,%9}, {%0,%1,%2,%3};"                 \
        : "+f"((ACC)[0]), "+f"((ACC)[1]), "+f"((ACC)[2]), "+f"((ACC)[3])        \
        : "r"((AFR)[0]), "r"((AFR)[1]), "r"((AFR)[2]), "r"((AFR)[3]),           \
          "r"(BF0), "r"(BF1))

// ================= R10 bf16x3 NT GEMM (128x128, GBK=16, 3 separated passes) ===
__global__ __launch_bounds__(128, 2)
void gemm_main(const float* __restrict__ A, const float* __restrict__ B,
               const float* __restrict__ bias, float* __restrict__ C,
               int K, int lda, int ldb, int ldc, int zmod,
               ll sAa, ll sAb, ll sBa, ll sBb, ll sCa, ll sCb, float alpha, int act)
{
    __shared__ uint32_t sm[2][4][1024];

    int tid = threadIdx.x;
    int lane = tid & 31, warp = tid >> 5;
    int g = lane >> 2, c0 = lane & 3;
    int wm = (warp & 1) * 64, wn = (warp >> 1) * 64;

    int z = blockIdx.z;
    int zq = z / zmod, zr = z % zmod;
    A += (ll)zq * sAa + (ll)zr * sAb;
    B += (ll)zq * sBa + (ll)zr * sBb;
    C += (ll)zq * sCa + (ll)zr * sCb;

    int row0 = blockIdx.y * 128, col0 = blockIdx.x * 128;
    const float* Ag = A + (ll)row0 * lda;
    const float* Bg = B + (ll)col0 * ldb;

    int ur[4], uh[4], uw[4], ut[4];
#pragma unroll
    for (int p = 0; p < 4; p++) {
        int id = tid + 128 * p;
        ut[p] = (id < 256) ? 0 : 2;
        int id2 = id & 255;
        ur[p] = id2 >> 1; uh[p] = id2 & 1;
        uw[p] = ur[p] * 8 + 4 * (uh[p] ^ ((ur[p] >> 2) & 1));
    }
    int aBase[4], bBase[8];
#pragma unroll
    for (int mt = 0; mt < 4; mt++) {
        int r = wm + mt * 16 + g;
        aBase[mt] = r * 8 + (c0 ^ (((r >> 2) & 1) << 2));
    }
#pragma unroll
    for (int nt = 0; nt < 8; nt++) {
        int r = wn + nt * 8 + g;
        bBase[nt] = r * 8 + (c0 ^ (((r >> 2) & 1) << 2));
    }
    float acc[4][8][4];
#pragma unroll
    for (int a = 0; a < 4; a++)
#pragma unroll
        for (int b = 0; b < 8; b++)
#pragma unroll
            for (int c = 0; c < 4; c++) acc[a][b][c] = 0.f;

    float4 pf[8];
    const int NCH = K >> 4;
    auto LDGU = [&](int k0) {
#pragma unroll
        for (int p = 0; p < 4; p++) {
            const float* src = (ut[p] == 0)
                ? Ag + (ll)ur[p] * lda + k0 + 8 * uh[p]
                : Bg + (ll)ur[p] * ldb + k0 + 8 * uh[p];
            pf[2 * p]     = *reinterpret_cast<const float4*>(src);
            pf[2 * p + 1] = *reinterpret_cast<const float4*>(src + 4);
        }
    };
    auto STSU = [&](int buf) {
#pragma unroll
        for (int p = 0; p < 4; p++) {
            float4 f0 = pf[2 * p], f1 = pf[2 * p + 1];
            *reinterpret_cast<uint4*>(&sm[buf][ut[p]][uw[p]]) =
                make_uint4(pack_hi(f0.x, f0.y), pack_hi(f0.z, f0.w),
                           pack_hi(f1.x, f1.y), pack_hi(f1.z, f1.w));
            *reinterpret_cast<uint4*>(&sm[buf][ut[p] + 1][uw[p]]) =
                make_uint4(pack_lo(f0.x, f0.y), pack_lo(f0.z, f0.w),
                           pack_lo(f1.x, f1.y), pack_lo(f1.z, f1.w));
        }
    };
    LDGU(0); STSU(0); __syncthreads();

    for (int kb = 0; kb < NCH; kb++) {
        int buf = kb & 1;
        if (kb + 1 < NCH) LDGU((kb + 1) << 4);

        const uint32_t* AH = sm[buf][0];
        const uint32_t* AL = sm[buf][1];
        const uint32_t* BH = sm[buf][2];
        const uint32_t* BL = sm[buf][3];

        uint32_t ah[4][4], al[4][4], bH[8][2], bL[8][2];
#pragma unroll
        for (int mt = 0; mt < 4; mt++) {
            int a0 = aBase[mt];
            ah[mt][0] = AH[a0];      ah[mt][1] = AH[a0 + 64];
            ah[mt][2] = AH[a0 ^ 4];  ah[mt][3] = AH[(a0 + 64) ^ 4];
            al[mt][0] = AL[a0];      al[mt][1] = AL[a0 + 64];
            al[mt][2] = AL[a0 ^ 4];  al[mt][3] = AL[(a0 + 64) ^ 4];
        }
#pragma unroll
        for (int nt = 0; nt < 8; nt++) {
            int b0 = bBase[nt];
            bH[nt][0] = BH[b0]; bH[nt][1] = BH[b0 ^ 4];
            bL[nt][0] = BL[b0]; bL[nt][1] = BL[b0 ^ 4];
        }
#pragma unroll
        for (int mt = 0; mt < 4; mt++)
#pragma unroll
            for (int nt = 0; nt < 8; nt++)
                MMA_BF16(acc[mt][nt], ah[mt], bH[nt][0], bH[nt][1]);
#pragma unroll
        for (int mt = 0; mt < 4; mt++)
#pragma unroll
            for (int nt = 0; nt < 8; nt++)
                MMA_BF16(acc[mt][nt], al[mt], bH[nt][0], bH[nt][1]);
#pragma unroll
        for (int mt = 0; mt < 4; mt++)
#pragma unroll
            for (int nt = 0; nt < 8; nt++)
                MMA_BF16(acc[mt][nt], ah[mt], bL[nt][0], bL[nt][1]);

        if (kb + 1 < NCH) STSU(buf ^ 1);
        __syncthreads();
    }

#pragma unroll
    for (int mt = 0; mt < 4; mt++) {
#pragma unroll
        for (int nt = 0; nt < 8; nt++) {
            int cb = col0 + wn + nt * 8 + 2 * c0;
            float bz0 = bias ? bias[cb] : 0.f;
            float bz1 = bias ? bias[cb + 1] : 0.f;
#pragma unroll
            for (int h = 0; h < 2; h++) {
                int r = row0 + wm + mt * 16 + g + h * 8;
                float v0 = acc[mt][nt][h * 2 + 0] * alpha + bz0;
                float v1 = acc[mt][nt][h * 2 + 1] * alpha + bz1;
                if (act) {
                    v0 = 0.5f * v0 * (1.f + erff(v0 * 0.70710678118654752f));
                    v1 = 0.5f * v1 * (1.f + erff(v1 * 0.70710678118654752f));
                }
                *reinterpret_cast<float2*>(&C[(ll)r * ldc + cb]) = make_float2(v0, v1);
            }
        }
    }
}

// ================= fp16x2 NT GEMM (lm_head; R12 proven) ======================
__global__ __launch_bounds__(128, 2)
void gemm_f16(const float* __restrict__ A, const float* __restrict__ B,
              const float* __restrict__ bias, float* __restrict__ C,
              int K, int lda, int ldb, int ldc, float alpha, int act)
{
    __shared__ uint32_t sm[2][3][1024];   // [buf][AsH,BsH,BsL]

    int tid = threadIdx.x;
    int lane = tid & 31, warp = tid >> 5;
    int g = lane >> 2, c0 = lane & 3;
    int wm = (warp & 1) * 64, wn = (warp >> 1) * 64;

    int row0 = blockIdx.y * 128, col0 = blockIdx.x * 128;
    const float* Ag = A + (ll)row0 * lda;
    const float* Bg = B + (ll)col0 * ldb;

    int ur[4], uh[4], uw[4], ut[4];
#pragma unroll
    for (int p = 0; p < 4; p++) {
        int id = tid + 128 * p;
        ut[p] = (id < 256) ? 0 : 1;
        int id2 = id & 255;
        ur[p] = id2 >> 1; uh[p] = id2 & 1;
        uw[p] = ur[p] * 8 + 4 * (uh[p] ^ ((ur[p] >> 2) & 1));
    }
    int aBase[4], bBase[8];
#pragma unroll
    for (int mt = 0; mt < 4; mt++) {
        int r = wm + mt * 16 + g;
        aBase[mt] = r * 8 + (c0 ^ (((r >> 2) & 1) << 2));
    }
#pragma unroll
    for (int nt = 0; nt < 8; nt++) {
        int r = wn + nt * 8 + g;
        bBase[nt] = r * 8 + (c0 ^ (((r >> 2) & 1) << 2));
    }
    float acc[4][8][4];
#pragma unroll
    for (int a = 0; a < 4; a++)
#pragma unroll
        for (int b = 0; b < 8; b++)
#pragma unroll
            for (int c = 0; c < 4; c++) acc[a][b][c] = 0.f;

    float4 pf[8];
    const int NCH = K >> 4;
    auto LDGU = [&](int k0) {
#pragma unroll
        for (int p = 0; p < 4; p++) {
            const float* src = (ut[p] == 0)
                ? Ag + (ll)ur[p] * lda + k0 + 8 * uh[p]
                : Bg + (ll)ur[p] * ldb + k0 + 8 * uh[p];
            pf[2 * p]     = *reinterpret_cast<const float4*>(src);
            pf[2 * p + 1] = *reinterpret_cast<const float4*>(src + 4);
        }
    };
    auto STSU = [&](int buf) {
#pragma unroll
        for (int p = 0; p < 4; p++) {
            float4 f0 = pf[2 * p], f1 = pf[2 * p + 1];
            if (ut[p] == 0) {
                *reinterpret_cast<uint4*>(&sm[buf][0][uw[p]]) =
                    make_uint4(pack_hi16(f0.x, f0.y), pack_hi16(f0.z, f0.w),
                               pack_hi16(f1.x, f1.y), pack_hi16(f1.z, f1.w));
            } else {
                *reinterpret_cast<uint4*>(&sm[buf][1][uw[p]]) =
                    make_uint4(pack_hi16(f0.x, f0.y), pack_hi16(f0.z, f0.w),
                               pack_hi16(f1.x, f1.y), pack_hi16(f1.z, f1.w));
                *reinterpret_cast<uint4*>(&sm[buf][2][uw[p]]) =
                    make_uint4(pack_lores16(f0.x, f0.y), pack_lores16(f0.z, f0.w),
                               pack_lores16(f1.x, f1.y), pack_lores16(f1.z, f1.w));
            }
        }
    };
    LDGU(0); STSU(0); __syncthreads();

    for (int kb = 0; kb < NCH; kb++) {
        int buf = kb & 1;
        if (kb + 1 < NCH) LDGU((kb + 1) << 4);

        const uint32_t* AH = sm[buf][0];
        const uint32_t* BH = sm[buf][1];
        const uint32_t* BL = sm[buf][2];

        uint32_t ah[4][4], bH[8][2], bL[8][2];
#pragma unroll
        for (int mt = 0; mt < 4; mt++) {
            int a0 = aBase[mt];
            ah[mt][0] = AH[a0];      ah[mt][1] = AH[a0 + 64];
            ah[mt][2] = AH[a0 ^ 4];  ah[mt][3] = AH[(a0 + 64) ^ 4];
        }
#pragma unroll
        for (int nt = 0; nt < 8; nt++) {
            int b0 = bBase[nt];
            bH[nt][0] = BH[b0]; bH[nt][1] = BH[b0 ^ 4];
            bL[nt][0] = BL[b0]; bL[nt][1] = BL[b0 ^ 4];
        }
#pragma unroll
        for (int mt = 0; mt < 4; mt++)
#pragma unroll
            for (int nt = 0; nt < 8; nt++)
                MMA_F16(acc[mt][nt], ah[mt], bH[nt][0], bH[nt][1]);
#pragma unroll
        for (int mt = 0; mt < 4; mt++)
#pragma unroll
            for (int nt = 0; nt < 8; nt++)
                MMA_F16(acc[mt][nt], ah[mt], bL[nt][0], bL[nt][1]);

        if (kb + 1 < NCH) STSU(buf ^ 1);
        __syncthreads();
    }

#pragma unroll
    for (int mt = 0; mt < 4; mt++) {
#pragma unroll
        for (int nt = 0; nt < 8; nt++) {
            int cb = col0 + wn + nt * 8 + 2 * c0;
            float bz0 = bias ? bias[cb] : 0.f;
            float bz1 = bias ? bias[cb + 1] : 0.f;
#pragma unroll
            for (int h = 0; h < 2; h++) {
                int r = row0 + wm + mt * 16 + g + h * 8;
                float v0 = acc[mt][nt][h * 2 + 0] * alpha + bz0;
                float v1 = acc[mt][nt][h * 2 + 1] * alpha + bz1;
                if (act) {
                    v0 = 0.5f * v0 * (1.f + erff(v0 * 0.70710678118654752f));
                    v1 = 0.5f * v1 * (1.f + erff(v1 * 0.70710678118654752f));
                }
                *reinterpret_cast<float2*>(&C[(ll)r * ldc + cb]) = make_float2(v0, v1);
            }
        }
    }
}

// ================= fp16x1 NT GEMM (interior; single pass, no correction) =====
// Standalone clone of gemm_f16 with the BL tile and pass-2 removed.
__global__ __launch_bounds__(128, 2)
void gemm_f16x1(const float* __restrict__ A, const float* __restrict__ B,
                const float* __restrict__ bias, float* __restrict__ C,
                int K, int lda, int ldb, int ldc, float alpha, int act)
{
    __shared__ uint32_t sm[2][2][1024];   // [buf][AsH,BsH]

    int tid = threadIdx.x;
    int lane = tid & 31, warp = tid >> 5;
    int g = lane >> 2, c0 = lane & 3;
    int wm = (warp & 1) * 64, wn = (warp >> 1) * 64;

    int row0 = blockIdx.y * 128, col0 = blockIdx.x * 128;
    const float* Ag = A + (ll)row0 * lda;
    const float* Bg = B + (ll)col0 * ldb;

    int ur[4], uh[4], uw[4], ut[4];
#pragma unroll
    for (int p = 0; p < 4; p++) {
        int id = tid + 128 * p;
        ut[p] = (id < 256) ? 0 : 1;
        int id2 = id & 255;
        ur[p] = id2 >> 1; uh[p] = id2 & 1;
        uw[p] = ur[p] * 8 + 4 * (uh[p] ^ ((ur[p] >> 2) & 1));
    }
    int aBase[4], bBase[8];
#pragma unroll
    for (int mt = 0; mt < 4; mt++) {
        int r = wm + mt * 16 + g;
        aBase[mt] = r * 8 + (c0 ^ (((r >> 2) & 1) << 2));
    }
#pragma unroll
    for (int nt = 0; nt < 8; nt++) {
        int r = wn + nt * 8 + g;
        bBase[nt] = r * 8 + (c0 ^ (((r >> 2) & 1) << 2));
    }
    float acc[4][8][4];
#pragma unroll
    for (int a = 0; a < 4; a++)
#pragma unroll
        for (int b = 0; b < 8; b++)
#pragma unroll
            for (int c = 0; c < 4; c++) acc[a][b][c] = 0.f;

    float4 pf[8];
    const int NCH = K >> 4;
    auto LDGU = [&](int k0) {
#pragma unroll
        for (int p = 0; p < 4; p++) {
            const float* src = (ut[p] == 0)
                ? Ag + (ll)ur[p] * lda + k0 + 8 * uh[p]
                : Bg + (ll)ur[p] * ldb + k0 + 8 * uh[p];
            pf[2 * p]     = *reinterpret_cast<const float4*>(src);
            pf[2 * p + 1] = *reinterpret_cast<const float4*>(src + 4);
        }
    };
    auto STSU = [&](int buf) {
#pragma unroll
        for (int p = 0; p < 4; p++) {
            float4 f0 = pf[2 * p], f1 = pf[2 * p + 1];
            *reinterpret_cast<uint4*>(&sm[buf][ut[p]][uw[p]]) =
                make_uint4(pack_hi16(f0.x, f0.y), pack_hi16(f0.z, f0.w),
                           pack_hi16(f1.x, f1.y), pack_hi16(f1.z, f1.w));
        }
    };
    LDGU(0); STSU(0); __syncthreads();

    for (int kb = 0; kb < NCH; kb++) {
        int buf = kb & 1;
        if (kb + 1 < NCH) LDGU((kb + 1) << 4);

        const uint32_t* AH = sm[buf][0];
        const uint32_t* BH = sm[buf][1];

        uint32_t ah[4][4], bH[8][2];
#pragma unroll
        for (int mt = 0; mt < 4; mt++) {
            int a0 = aBase[mt];
            ah[mt][0] = AH[a0];      ah[mt][1] = AH[a0 + 64];
            ah[mt][2] = AH[a0 ^ 4];  ah[mt][3] = AH[(a0 + 64) ^ 4];
        }
#pragma unroll
        for (int nt = 0; nt < 8; nt++) {
            int b0 = bBase[nt];
            bH[nt][0] = BH[b0]; bH[nt][1] = BH[b0 ^ 4];
        }
#pragma unroll
        for (int mt = 0; mt < 4; mt++)
#pragma unroll
            for (int nt = 0; nt < 8; nt++)
                MMA_F16(acc[mt][nt], ah[mt], bH[nt][0], bH[nt][1]);

        if (kb + 1 < NCH) STSU(buf ^ 1);
        __syncthreads();
    }

#pragma unroll
    for (int mt = 0; mt < 4; mt++) {
#pragma unroll
        for (int nt = 0; nt < 8; nt++) {
            int cb = col0 + wn + nt * 8 + 2 * c0;
            float bz0 = bias ? bias[cb] : 0.f;
            float bz1 = bias ? bias[cb + 1] : 0.f;
#pragma unroll
            for (int h = 0; h < 2; h++) {
                int r = row0 + wm + mt * 16 + g + h * 8;
                float v0 = acc[mt][nt][h * 2 + 0] * alpha + bz0;
                float v1 = acc[mt][nt][h * 2 + 1] * alpha + bz1;
                if (act) {
                    v0 = 0.5f * v0 * (1.f + erff(v0 * 0.70710678118654752f));
                    v1 = 0.5f * v1 * (1.f + erff(v1 * 0.70710678118654752f));
                }
                *reinterpret_cast<float2*>(&C[(ll)r * ldc + cb]) = make_float2(v0, v1);
            }
        }
    }
}

// ================= small-tile bf16x3 NT GEMM (64x64, R8 reorder) ========
__global__ __launch_bounds__(128, 4)
void gemm_small(const float* __restrict__ A, const float* __restrict__ B,
                const float* __restrict__ bias, float* __restrict__ C,
                int K, int lda, int ldb, int ldc)
{
    __shared__ uint32_t AsH[1024], AsL[1024], BsH[1024], BsL[1024];
    int tid = threadIdx.x;
    int lane = tid & 31, warp = tid >> 5;
    int g = lane >> 2, c0 = lane & 3;
    int wm = (warp & 1) * 32, wn = (warp >> 1) * 32;
    int row0 = blockIdx.y * 64, col0 = blockIdx.x * 64;
    const float* Ag = A + (ll)row0 * lda;
    const float* Bg = B + (ll)col0 * ldb;

    float acc[2][4][4];
#pragma unroll
    for (int a = 0; a < 2; a++)
#pragma unroll
        for (int b = 0; b < 4; b++)
#pragma unroll
            for (int c = 0; c < 4; c++) acc[a][b][c] = 0.f;

    int aAddr[2][4], bAddr[4][2];
#pragma unroll
    for (int mt = 0; mt < 2; mt++)
#pragma unroll
        for (int i = 0; i < 4; i++) {
            int r = wm + mt * 16 + g + (i & 1) * 8;
            int j = c0 + (i >> 1) * 4;
            aAddr[mt][i] = r * 16 + (j ^ (((r >> 1) & 3) << 2));
        }
#pragma unroll
    for (int nt = 0; nt < 4; nt++)
#pragma unroll
        for (int i = 0; i < 2; i++) {
            int r = wn + nt * 8 + g;
            int j = c0 + i * 4;
            bAddr[nt][i] = r * 16 + (j ^ (((r >> 1) & 3) << 2));
        }

    for (int k0 = 0; k0 < K; k0 += 32) {
        __syncthreads();
#pragma unroll
        for (int p = 0; p < 8; p++) {
            int f = tid + 128 * p;
            int isA = f < 512;
            int fb = f & 511;
            int m = fb >> 3, q = fb & 7;
            const float* src = isA ? Ag + (ll)m * lda + k0 + q * 4
                                   : Bg + (ll)m * ldb + k0 + q * 4;
            float4 f4 = *reinterpret_cast<const float4*>(src);
            uint32_t w0 = m * 16 + ((2 * q) ^ (((m >> 1) & 3) << 2));
            if (isA) {
                *reinterpret_cast<uint2*>(AsH + w0) = make_uint2(pack_hi(f4.x, f4.y), pack_hi(f4.z, f4.w));
                *reinterpret_cast<uint2*>(AsL + w0) = make_uint2(pack_lo(f4.x, f4.y), pack_lo(f4.z, f4.w));
            } else {
                *reinterpret_cast<uint2*>(BsH + w0) = make_uint2(pack_hi(f4.x, f4.y), pack_hi(f4.z, f4.w));
                *reinterpret_cast<uint2*>(BsL + w0) = make_uint2(pack_lo(f4.x, f4.y), pack_lo(f4.z, f4.w));
            }
        }
        __syncthreads();
#pragma unroll
        for (int ks = 0; ks < 2; ks++) {
            int kx = ks * 8;
            uint32_t ah[2][4], al[2][4], bH[4][2], bL[4][2];
#pragma unroll
            for (int mt = 0; mt < 2; mt++)
#pragma unroll
                for (int i = 0; i < 4; i++) {
                    ah[mt][i] = AsH[aAddr[mt][i] ^ kx];
                    al[mt][i] = AsL[aAddr[mt][i] ^ kx];
                }
#pragma unroll
            for (int nt = 0; nt < 4; nt++)
#pragma unroll
                for (int i = 0; i < 2; i++) {
                    bH[nt][i] = BsH[bAddr[nt][i] ^ kx];
                    bL[nt][i] = BsL[bAddr[nt][i] ^ kx];
                }
#pragma unroll
            for (int mt = 0; mt < 2; mt++)
#pragma unroll
                for (int nt = 0; nt < 4; nt++)
                    MMA_BF16(acc[mt][nt], ah[mt], bH[nt][0], bH[nt][1]);
#pragma unroll
            for (int mt = 0; mt < 2; mt++)
#pragma unroll
                for (int nt = 0; nt < 4; nt++)
                    MMA_BF16(acc[mt][nt], al[mt], bH[nt][0], bH[nt][1]);
#pragma unroll
            for (int mt = 0; mt < 2; mt++)
#pragma unroll
                for (int nt = 0; nt < 4; nt++)
                    MMA_BF16(acc[mt][nt], ah[mt], bL[nt][0], bL[nt][1]);
        }
    }
#pragma unroll
    for (int mt = 0; mt < 2; mt++) {
#pragma unroll
        for (int nt = 0; nt < 4; nt++) {
            int cb = col0 + wn + nt * 8 + 2 * c0;
            float bz0 = bias ? bias[cb] : 0.f;
            float bz1 = bias ? bias[cb + 1] : 0.f;
#pragma unroll
            for (int h = 0; h < 2; h++) {
                int r = row0 + wm + mt * 16 + g + h * 8;
                float v0 = acc[mt][nt][h * 2 + 0] + bz0;
                float v1 = acc[mt][nt][h * 2 + 1] + bz1;
                *reinterpret_cast<float2*>(&C[(ll)r * ldc + cb]) = make_float2(v0, v1);
            }
        }
    }
}

// ---------------- elementwise ----------------
__global__ void embed_kernel(const int* __restrict__ ids, const float* __restrict__ emb,
                             const float* __restrict__ pos, float* __restrict__ x) {
    int t = blockIdx.x;
    int id = ids[t];
    int s = t % SS;
    const float* er = emb + (ll)id * HH;
    const float* pr = pos + (ll)s * HH;
    float* xr = x + (ll)t * HH;
    for (int j = threadIdx.x; j < HH; j += blockDim.x) xr[j] = er[j] + pr[j];
}

__global__ void ln_kernel(float* __restrict__ out, const float* __restrict__ a,
                          const float* __restrict__ res, const float* __restrict__ coef,
                          float coef_off, const float* __restrict__ g,
                          const float* __restrict__ bvec, float scale) {
    int t = blockIdx.x;
    __shared__ float red[256];
    float v[4];
    float s = 0.f;
#pragma unroll
    for (int j = 0; j < 4; j++) {
        int h = threadIdx.x + 256 * j;
        float xv = a[(ll)t * HH + h];
        if (res) {
            float c = (coef ? coef[h] : 0.f) + coef_off;
            xv += c * res[(ll)t * HH + h];
        }
        v[j] = xv;
        s += xv;
    }
    red[threadIdx.x] = s; __syncthreads();
    for (int o = 128; o > 0; o >>= 1) { if (threadIdx.x < o) red[threadIdx.x] += red[threadIdx.x + o]; __syncthreads(); }
    float mean = red[0] * (1.f / HH); __syncthreads();
    float s2 = 0.f;
#pragma unroll
    for (int j = 0; j < 4; j++) { float d = v[j] - mean; s2 += d * d; }
    red[threadIdx.x] = s2; __syncthreads();
    for (int o = 128; o > 0; o >>= 1) { if (threadIdx.x < o) red[threadIdx.x] += red[threadIdx.x + o]; __syncthreads(); }
    float rstd = rsqrtf(red[0] * (1.f / HH) + 1e-5f);
#pragma unroll
    for (int j = 0; j < 4; j++) {
        int h = threadIdx.x + 256 * j;
        out[(ll)t * HH + h] = ((v[j] - mean) * rstd * g[h] + bvec[h]) * scale;
    }
}

__global__ void gate_u_kernel(const float* __restrict__ gl, float* __restrict__ u, int n) {
    int i = blockIdx.x * blockDim.x + threadIdx.x;
    if (i < n) u[i] = u[i] / (1.f + expf(-gl[i]));
}

__global__ void scan_kernel(float* __restrict__ u, const float* __restrict__ A_log) {
    int b = blockIdx.x, n = threadIdx.x;
    float a = expf(A_log[n]);
    float s = 0.f;
    ll base = (ll)b * SS * NST + n;
    for (int t0 = 0; t0 < SS; t0 += 8) {
        float uv[8];
#pragma unroll
        for (int j = 0; j < 8; j++) uv[j] = u[base + (ll)(t0 + j) * NST];
#pragma unroll
        for (int j = 0; j < 8; j++) { s = a * s + uv[j]; uv[j] = s; }
#pragma unroll
        for (int j = 0; j < 8; j++) u[base + (ll)(t0 + j) * NST] = uv[j];
    }
}

__global__ void softmax512(float* __restrict__ p) {
    ll row = blockIdx.x;
    float* r = p + row * SS;
    int t = threadIdx.x;
    float v0 = r[t], v1 = r[t + 256];
    __shared__ float red[256];
    red[t] = fmaxf(v0, v1); __syncthreads();
    for (int o = 128; o > 0; o >>= 1) { if (t < o) red[t] = fmaxf(red[t], red[t + o]); __syncthreads(); }
    float m = red[0]; __syncthreads();
    float e0 = expf(v0 - m), e1 = expf(v1 - m);
    red[t] = e0 + e1; __syncthreads();
    for (int o = 128; o > 0; o >>= 1) { if (t < o) red[t] += red[t + o]; __syncthreads(); }
    float inv = 1.f / red[0];
    r[t] = e0 * inv; r[t + 256] = e1 * inv;
}

__global__ void transpose_v(const float* __restrict__ qkv, float* __restrict__ vt) {
    __shared__ float tile[32][33];
    int b = blockIdx.z >> 3, h = blockIdx.z & 7;
    int s0 = blockIdx.x * 32, d0 = blockIdx.y * 32;
    int tx = threadIdx.x, ty = threadIdx.y;
    for (int i = ty; i < 32; i += 8)
        tile[i][tx] = qkv[((ll)(b * SS + s0 + i)) * (3 * HH) + 2 * HH + h * DHD + d0 + tx];
    __syncthreads();
    for (int i = ty; i < 32; i += 8)
        vt[((ll)blockIdx.z * DHD + d0 + i) * SS + s0 + tx] = tile[tx][i];
}

// ---------------- host ----------------
static inline void GB(const float* A, const float* B, const float* bias, float* C,
                      int M, int N, int K, int lda, int ldb, int ldc,
                      int batch, int zmod,
                      ll sAa, ll sAb, ll sBa, ll sBb, ll sCa, ll sCb,
                      float alpha, int act) {
    dim3 grid(N / 128, M / 128, batch);
    gemm_main<<<grid, 128>>>(A, B, bias, C, K, lda, ldb, ldc, zmod,
                             sAa, sAb, sBa, sBb, sCa, sCb, alpha, act);
}
static inline void GF2(const float* A, const float* B, const float* bias, float* C,
                       int M, int N, int K, int lda, int ldb, int ldc,
                       float alpha = 1.f, int act = 0) {
    dim3 grid(N / 128, M / 128);
    gemm_f16<<<grid, 128>>>(A, B, bias, C, K, lda, ldb, ldc, alpha, act);
}
static inline void GF1(const float* A, const float* B, const float* bias, float* C,
                       int M, int N, int K, int lda, int ldb, int ldc,
                       float alpha = 1.f, int act = 0) {
    dim3 grid(N / 128, M / 128);
    gemm_f16x1<<<grid, 128>>>(A, B, bias, C, K, lda, ldb, ldc, alpha, act);
}
static inline void GS(const float* A, const float* B, const float* bias, float* C,
                      int M, int N, int K, int lda, int ldb, int ldc) {
    dim3 grid(N / 64, M / 64);
    gemm_small<<<grid, 128>>>(A, B, bias, C, K, lda, ldb, ldc);
}

extern "C" void kernel_launch(void* const* d_in, const int* in_sizes, int n_in,
                              void* d_out, int out_size) {
    const int*   ids  = (const int*)  d_in[0];
    const float* emb  = (const float*)d_in[1];
    const float* pos  = (const float*)d_in[2];
    const float* A_log= (const float*)d_in[3];
    const float* WB   = (const float*)d_in[4];
    const float* WC   = (const float*)d_in[5];
    const float* Dp   = (const float*)d_in[6];
    const float* Wg   = (const float*)d_in[7];
    const float* bg   = (const float*)d_in[8];
    const float* Wout = (const float*)d_in[9];
    const float* bout = (const float*)d_in[10];
    const float* gs   = (const float*)d_in[11];
    const float* bs   = (const float*)d_in[12];
    const float* Wqkv = (const float*)d_in[13];
    const float* bqkv = (const float*)d_in[14];
    const float* Wo   = (const float*)d_in[15];
    const float* bo   = (const float*)d_in[16];
    const float* W1   = (const float*)d_in[17];
    const float* b1   = (const float*)d_in[18];
    const float* W2   = (const float*)d_in[19];
    const float* b2   = (const float*)d_in[20];
    const float* g1   = (const float*)d_in[21];
    const float* bn1  = (const float*)d_in[22];
    const float* g2   = (const float*)d_in[23];
    const float* bn2  = (const float*)d_in[24];
    const float* g3   = (const float*)d_in[25];
    const float* bn3  = (const float*)d_in[26];
    const float* gf   = (const float*)d_in[27];
    const float* bf   = (const float*)d_in[28];

    float *x, *t1, *t2, *sc, *vt;
    cudaGetSymbolAddress((void**)&x,  g_x);
    cudaGetSymbolAddress((void**)&t1, g_t1);
    cudaGetSymbolAddress((void**)&t2, g_t2);
    cudaGetSymbolAddress((void**)&sc, g_sc);
    cudaGetSymbolAddress((void**)&vt, g_vt);

    embed_kernel<<<TT, 256>>>(ids, emb, pos, x);

    for (int i = 0; i < LL; i++) {
        // ===== SSM =====
        GS(x, Wg + (ll)i * NST * HH, bg + (ll)i * NST, t1, TT, NST, HH, HH, HH, NST);
        GS(x, WB + (ll)i * NST * HH, nullptr,          t2, TT, NST, HH, HH, HH, NST);
        gate_u_kernel<<<(TT * NST + 255) / 256, 256>>>(t1, t2, TT * NST);
        scan_kernel<<<BB, NST>>>(t2, A_log + (ll)i * NST);
        GF1(t2, WC + (ll)i * HH * NST, nullptr, t1, TT, HH, NST, NST, NST, HH);
        ln_kernel<<<TT, 256>>>(t2, t1, x, Dp + (ll)i * HH, 1.f,
                               gs + (ll)i * HH, bs + (ll)i * HH, 1.f);
        GF1(t2, Wout + (ll)i * HH * HH, bout + (ll)i * HH, t1, TT, HH, HH, HH, HH, HH);
        ln_kernel<<<TT, 256>>>(x, t1, x, nullptr, 1.f,
                               g1 + (ll)i * HH, bn1 + (ll)i * HH, 1.f);

        // ===== attention (odd layers) + memory fold (x2) =====
        if (i & 1) {
            GF1(x, Wqkv + (ll)i * 3 * HH * HH, bqkv + (ll)i * 3 * HH, t1,
                TT, 3 * HH, HH, HH, HH, 3 * HH);
            float asc = 1.f / sqrtf((float)DHD);
            GB(t1, t1 + HH, nullptr, sc, SS, SS, DHD, 3 * HH, 3 * HH, SS,
               BB * NHD, NHD,
               (ll)SS * 3 * HH, DHD,
               (ll)SS * 3 * HH, DHD,
               (ll)NHD * SS * SS, (ll)SS * SS, asc, 0);
            softmax512<<<BB * NHD * SS, 256>>>(sc);
            {
                dim3 tg(SS / 32, DHD / 32, BB * NHD);
                transpose_v<<<tg, dim3(32, 8)>>>(t1, vt);
            }
            GB(sc, vt, nullptr, t2, SS, DHD, SS, SS, SS, HH,
               BB * NHD, NHD,
               (ll)NHD * SS * SS, (ll)SS * SS,
               (ll)NHD * DHD * SS, (ll)DHD * SS,
               (ll)SS * HH, DHD, 1.f, 0);
            GF1(t2, Wo + (ll)i * HH * HH, bo + (ll)i * HH, t1, TT, HH, HH, HH, HH, HH);
            ln_kernel<<<TT, 256>>>(x, t1, x, nullptr, 1.f,
                                   g2 + (ll)i * HH, bn2 + (ll)i * HH, 2.f);
        } else {
            ln_kernel<<<TT, 256>>>(x, x, nullptr, nullptr, 0.f,
                                   g2 + (ll)i * HH, bn2 + (ll)i * HH, 2.f);
        }

        // ===== FFN =====
        GF1(x, W1 + (ll)i * FFD * HH, b1 + (ll)i * FFD, t1,
            TT, FFD, HH, HH, HH, FFD, 1.f, 1);
        GF1(t1, W2 + (ll)i * HH * FFD, b2 + (ll)i * HH, t2,
            TT, HH, FFD, FFD, FFD, HH);
        ln_kernel<<<TT, 256>>>(x, t2, x, nullptr, 1.f,
                               g3 + (ll)i * HH, bn3 + (ll)i * HH, 1.f);
    }

    // ===== final LN + tied lm_head (fp16x2) =====
    ln_kernel<<<TT, 256>>>(t1, x, nullptr, nullptr, 0.f, gf, bf, 1.f);
    GF2(t1, emb, nullptr, (float*)d_out, TT, VV, HH, HH, HH, VV);
}

// round 14
// speedup vs baseline: 1.7245x; 1.1454x over previous
#include <cuda_runtime.h>
#include <cuda_bf16.h>
#include <cuda_fp16.h>
#include <math.h>
#include <stdint.h>

#define TT 2048
#define SS 512
#define BB 4
#define HH 1024
#define NST 128
#define LL 6
#define VV 32000
#define NHD 8
#define FFD 4096
#define DHD 128
typedef long long ll;

// ---------------- scratch ----------------
__device__ float g_x [TT * HH];
__device__ float g_t1[TT * FFD];
__device__ float g_t2[TT * FFD];
__device__ float g_sc[BB * NHD * SS * SS];
__device__ float g_vt[BB * NHD * DHD * SS];
// fp16 shadows + weight arena
__device__ __half g_xh [TT * HH];
__device__ __half g_t1h[TT * FFD];
__device__ __half g_t2h[TT * HH];
#define OFF_WC    0LL
#define OFF_WOUT  786432LL
#define OFF_WQKV  7077888LL
#define OFF_WO    25952256LL
#define OFF_W1    32243712LL
#define OFF_W2    57409536LL
#define WH_TOTAL  82575360LL
__device__ __half g_wh[WH_TOTAL];

__device__ __forceinline__ uint32_t smem_u32(const void* p) {
    uint32_t a;
    asm("{ .reg .u64 t; cvta.to.shared.u64 t, %1; cvt.u32.u64 %0, t; }" : "=r"(a) : "l"(p));
    return a;
}

// bf16 packers
__device__ __forceinline__ uint32_t pack_hi(float x, float y) {
    __nv_bfloat162 h = __floats2bfloat162_rn(x, y);
    return *reinterpret_cast<uint32_t*>(&h);
}
__device__ __forceinline__ uint32_t pack_lo(float x, float y) {
    float hx = __bfloat162float(__float2bfloat16_rn(x));
    float hy = __bfloat162float(__float2bfloat16_rn(y));
    __nv_bfloat162 l = __floats2bfloat162_rn(x - hx, y - hy);
    return *reinterpret_cast<uint32_t*>(&l);
}
// fp16 packers
__device__ __forceinline__ uint32_t pack_hi16(float x, float y) {
    __half2 h = __floats2half2_rn(x, y);
    return *reinterpret_cast<uint32_t*>(&h);
}
__device__ __forceinline__ uint32_t pack_lores16(float x, float y) {
    float hx = __half2float(__float2half_rn(x));
    float hy = __half2float(__float2half_rn(y));
    __half2 l = __floats2half2_rn(x - hx, y - hy);
    return *reinterpret_cast<uint32_t*>(&l);
}

#define MMA_BF16(ACC, AFR, BF0, BF1)                                            \
    asm volatile(                                                               \
        "mma.sync.aligned.m16n8k16.row.col.f32.bf16.bf16.f32 "                  \
        "{%0,%1,%2,%3}, {%4,%5,%6,%7}, {%8,%9}, {%0,%1,%2,%3};"                 \
        : "+f"((ACC)[0]), "+f"((ACC)[1]), "+f"((ACC)[2]), "+f"((ACC)[3])        \
        : "r"((AFR)[0]), "r"((AFR)[1]), "r"((AFR)[2]), "r"((AFR)[3]),           \
          "r"(BF0), "r"(BF1))

#define MMA_F16(ACC, AFR, BF0, BF1)                                             \
    asm volatile(                                                               \
        "mma.sync.aligned.m16n8k16.row.col.f32.f16.f16.f32 "                    \
        "{%0,%1,%2,%3}, {%4,%5,%6,%7}, {%8,%9}, {%0,%1,%2,%3};"                 \
        : "+f"((ACC)[0]), "+f"((ACC)[1]), "+f"((ACC)[2]), "+f"((ACC)[3])        \
        : "r"((AFR)[0]), "r"((AFR)[1]), "r"((AFR)[2]), "r"((AFR)[3]),           \
          "r"(BF0), "r"(BF1))

#define CP16(dst, src) asm volatile(                                            \
    "cp.async.cg.shared.global [%0], [%1], 16;" :: "r"(dst), "l"(src))

// ---------------- weight fp32 -> fp16 conversion ----------------
__global__ void f2h_kernel(const float* __restrict__ src, __half* __restrict__ dst, int n) {
    int i = (blockIdx.x * blockDim.x + threadIdx.x) * 4;
    if (i < n) {
        float4 f = *reinterpret_cast<const float4*>(src + i);
        *reinterpret_cast<__half2*>(dst + i)     = __floats2half2_rn(f.x, f.y);
        *reinterpret_cast<__half2*>(dst + i + 2) = __floats2half2_rn(f.z, f.w);
    }
}

// ================= fp16xfp16 single-pass NT GEMM (cp.async staged) ===========
__global__ __launch_bounds__(128, 2)
void gemm_fh(const __half* __restrict__ A, const __half* __restrict__ B,
             const float* __restrict__ bias, float* __restrict__ C,
             __half* __restrict__ Ch,
             int K, int lda, int ldb, int ldc, float alpha, int act)
{
    __shared__ __align__(16) uint32_t sm[2][2][1024];  // [buf][A,B][128 rows * 8 words]

    int tid = threadIdx.x;
    int lane = tid & 31, warp = tid >> 5;
    int g = lane >> 2, c0 = lane & 3;
    int wm = (warp & 1) * 64, wn = (warp >> 1) * 64;

    int row0 = blockIdx.y * 128, col0 = blockIdx.x * 128;
    const __half* Ag = A + (ll)row0 * lda;
    const __half* Bg = B + (ll)col0 * ldb;
    uint32_t smb = smem_u32(sm);

    int aBase[4], bBase[8];
#pragma unroll
    for (int mt = 0; mt < 4; mt++) {
        int r = wm + mt * 16 + g;
        aBase[mt] = r * 8 + (c0 ^ (((r >> 2) & 1) << 2));
    }
#pragma unroll
    for (int nt = 0; nt < 8; nt++) {
        int r = wn + nt * 8 + g;
        bBase[nt] = r * 8 + (c0 ^ (((r >> 2) & 1) << 2));
    }
    float acc[4][8][4];
#pragma unroll
    for (int a = 0; a < 4; a++)
#pragma unroll
        for (int b = 0; b < 8; b++)
#pragma unroll
            for (int c = 0; c < 4; c++) acc[a][b][c] = 0.f;

    const int NCH = K >> 4;
    // staging: 512 units of 16B; unit u = tid + 128p: row = u>>1 (0..255), chunk = u&1
    auto issue = [&](int kc) {
        int buf = kc & 1, k0 = kc << 4;
#pragma unroll
        for (int p = 0; p < 4; p++) {
            int u = tid + 128 * p;
            int row = u >> 1, ch = u & 1;
            int r = row & 127;
            const __half* src = (row < 128)
                ? Ag + (ll)r * lda + k0 + ch * 8
                : Bg + (ll)r * ldb + k0 + ch * 8;
            uint32_t w = (uint32_t)(buf * 2048 + (row < 128 ? 0 : 1024)
                        + r * 8 + ((ch * 4) ^ (((r >> 2) & 1) << 2)));
            CP16(smb + w * 4u, src);
        }
        asm volatile("cp.async.commit_group;");
    };

    issue(0);
    for (int kb = 0; kb < NCH; kb++) {
        if (kb + 1 < NCH) {
            issue(kb + 1);
            asm volatile("cp.async.wait_group 1;");
        } else {
            asm volatile("cp.async.wait_group 0;");
        }
        __syncthreads();
        const uint32_t* AH = sm[kb & 1][0];
        const uint32_t* BH = sm[kb & 1][1];

        uint32_t ah[4][4], bH[8][2];
#pragma unroll
        for (int mt = 0; mt < 4; mt++) {
            int a0 = aBase[mt];
            ah[mt][0] = AH[a0];      ah[mt][1] = AH[a0 + 64];
            ah[mt][2] = AH[a0 ^ 4];  ah[mt][3] = AH[(a0 + 64) ^ 4];
        }
#pragma unroll
        for (int nt = 0; nt < 8; nt++) {
            int b0 = bBase[nt];
            bH[nt][0] = BH[b0]; bH[nt][1] = BH[b0 ^ 4];
        }
#pragma unroll
        for (int mt = 0; mt < 4; mt++)
#pragma unroll
            for (int nt = 0; nt < 8; nt++)
                MMA_F16(acc[mt][nt], ah[mt], bH[nt][0], bH[nt][1]);
        __syncthreads();
    }

#pragma unroll
    for (int mt = 0; mt < 4; mt++) {
#pragma unroll
        for (int nt = 0; nt < 8; nt++) {
            int cb = col0 + wn + nt * 8 + 2 * c0;
            float bz0 = bias ? bias[cb] : 0.f;
            float bz1 = bias ? bias[cb + 1] : 0.f;
#pragma unroll
            for (int h = 0; h < 2; h++) {
                int r = row0 + wm + mt * 16 + g + h * 8;
                float v0 = acc[mt][nt][h * 2 + 0] * alpha + bz0;
                float v1 = acc[mt][nt][h * 2 + 1] * alpha + bz1;
                if (act) {
                    v0 = 0.5f * v0 * (1.f + erff(v0 * 0.70710678118654752f));
                    v1 = 0.5f * v1 * (1.f + erff(v1 * 0.70710678118654752f));
                }
                *reinterpret_cast<float2*>(&C[(ll)r * ldc + cb]) = make_float2(v0, v1);
                if (Ch)
                    *reinterpret_cast<__half2*>(&Ch[(ll)r * ldc + cb]) =
                        __floats2half2_rn(v0, v1);
            }
        }
    }
}

// ================= R10 bf16x3 NT GEMM (attention; + optional fp16 out) =======
__global__ __launch_bounds__(128, 2)
void gemm_main(const float* __restrict__ A, const float* __restrict__ B,
               const float* __restrict__ bias, float* __restrict__ C,
               __half* __restrict__ Ch,
               int K, int lda, int ldb, int ldc, int zmod,
               ll sAa, ll sAb, ll sBa, ll sBb, ll sCa, ll sCb, float alpha, int act)
{
    __shared__ uint32_t sm[2][4][1024];

    int tid = threadIdx.x;
    int lane = tid & 31, warp = tid >> 5;
    int g = lane >> 2, c0 = lane & 3;
    int wm = (warp & 1) * 64, wn = (warp >> 1) * 64;

    int z = blockIdx.z;
    int zq = z / zmod, zr = z % zmod;
    A += (ll)zq * sAa + (ll)zr * sAb;
    B += (ll)zq * sBa + (ll)zr * sBb;
    C += (ll)zq * sCa + (ll)zr * sCb;
    if (Ch) Ch += (ll)zq * sCa + (ll)zr * sCb;

    int row0 = blockIdx.y * 128, col0 = blockIdx.x * 128;
    const float* Ag = A + (ll)row0 * lda;
    const float* Bg = B + (ll)col0 * ldb;

    int ur[4], uh[4], uw[4], ut[4];
#pragma unroll
    for (int p = 0; p < 4; p++) {
        int id = tid + 128 * p;
        ut[p] = (id < 256) ? 0 : 2;
        int id2 = id & 255;
        ur[p] = id2 >> 1; uh[p] = id2 & 1;
        uw[p] = ur[p] * 8 + 4 * (uh[p] ^ ((ur[p] >> 2) & 1));
    }
    int aBase[4], bBase[8];
#pragma unroll
    for (int mt = 0; mt < 4; mt++) {
        int r = wm + mt * 16 + g;
        aBase[mt] = r * 8 + (c0 ^ (((r >> 2) & 1) << 2));
    }
#pragma unroll
    for (int nt = 0; nt < 8; nt++) {
        int r = wn + nt * 8 + g;
        bBase[nt] = r * 8 + (c0 ^ (((r >> 2) & 1) << 2));
    }
    float acc[4][8][4];
#pragma unroll
    for (int a = 0; a < 4; a++)
#pragma unroll
        for (int b = 0; b < 8; b++)
#pragma unroll
            for (int c = 0; c < 4; c++) acc[a][b][c] = 0.f;

    float4 pf[8];
    const int NCH = K >> 4;
    auto LDGU = [&](int k0) {
#pragma unroll
        for (int p = 0; p < 4; p++) {
            const float* src = (ut[p] == 0)
                ? Ag + (ll)ur[p] * lda + k0 + 8 * uh[p]
                : Bg + (ll)ur[p] * ldb + k0 + 8 * uh[p];
            pf[2 * p]     = *reinterpret_cast<const float4*>(src);
            pf[2 * p + 1] = *reinterpret_cast<const float4*>(src + 4);
        }
    };
    auto STSU = [&](int buf) {
#pragma unroll
        for (int p = 0; p < 4; p++) {
            float4 f0 = pf[2 * p], f1 = pf[2 * p + 1];
            *reinterpret_cast<uint4*>(&sm[buf][ut[p]][uw[p]]) =
                make_uint4(pack_hi(f0.x, f0.y), pack_hi(f0.z, f0.w),
                           pack_hi(f1.x, f1.y), pack_hi(f1.z, f1.w));
            *reinterpret_cast<uint4*>(&sm[buf][ut[p] + 1][uw[p]]) =
                make_uint4(pack_lo(f0.x, f0.y), pack_lo(f0.z, f0.w),
                           pack_lo(f1.x, f1.y), pack_lo(f1.z, f1.w));
        }
    };
    LDGU(0); STSU(0); __syncthreads();

    for (int kb = 0; kb < NCH; kb++) {
        int buf = kb & 1;
        if (kb + 1 < NCH) LDGU((kb + 1) << 4);

        const uint32_t* AH = sm[buf][0];
        const uint32_t* AL = sm[buf][1];
        const uint32_t* BH = sm[buf][2];
        const uint32_t* BL = sm[buf][3];

        uint32_t ah[4][4], al[4][4], bH[8][2], bL[8][2];
#pragma unroll
        for (int mt = 0; mt < 4; mt++) {
            int a0 = aBase[mt];
            ah[mt][0] = AH[a0];      ah[mt][1] = AH[a0 + 64];
            ah[mt][2] = AH[a0 ^ 4];  ah[mt][3] = AH[(a0 + 64) ^ 4];
            al[mt][0] = AL[a0];      al[mt][1] = AL[a0 + 64];
            al[mt][2] = AL[a0 ^ 4];  al[mt][3] = AL[(a0 + 64) ^ 4];
        }
#pragma unroll
        for (int nt = 0; nt < 8; nt++) {
            int b0 = bBase[nt];
            bH[nt][0] = BH[b0]; bH[nt][1] = BH[b0 ^ 4];
            bL[nt][0] = BL[b0]; bL[nt][1] = BL[b0 ^ 4];
        }
#pragma unroll
        for (int mt = 0; mt < 4; mt++)
#pragma unroll
            for (int nt = 0; nt < 8; nt++)
                MMA_BF16(acc[mt][nt], ah[mt], bH[nt][0], bH[nt][1]);
#pragma unroll
        for (int mt = 0; mt < 4; mt++)
#pragma unroll
            for (int nt = 0; nt < 8; nt++)
                MMA_BF16(acc[mt][nt], al[mt], bH[nt][0], bH[nt][1]);
#pragma unroll
        for (int mt = 0; mt < 4; mt++)
#pragma unroll
            for (int nt = 0; nt < 8; nt++)
                MMA_BF16(acc[mt][nt], ah[mt], bL[nt][0], bL[nt][1]);

        if (kb + 1 < NCH) STSU(buf ^ 1);
        __syncthreads();
    }

#pragma unroll
    for (int mt = 0; mt < 4; mt++) {
#pragma unroll
        for (int nt = 0; nt < 8; nt++) {
            int cb = col0 + wn + nt * 8 + 2 * c0;
            float bz0 = bias ? bias[cb] : 0.f;
            float bz1 = bias ? bias[cb + 1] : 0.f;
#pragma unroll
            for (int h = 0; h < 2; h++) {
                int r = row0 + wm + mt * 16 + g + h * 8;
                float v0 = acc[mt][nt][h * 2 + 0] * alpha + bz0;
                float v1 = acc[mt][nt][h * 2 + 1] * alpha + bz1;
                if (act) {
                    v0 = 0.5f * v0 * (1.f + erff(v0 * 0.70710678118654752f));
                    v1 = 0.5f * v1 * (1.f + erff(v1 * 0.70710678118654752f));
                }
                *reinterpret_cast<float2*>(&C[(ll)r * ldc + cb]) = make_float2(v0, v1);
                if (Ch)
                    *reinterpret_cast<__half2*>(&Ch[(ll)r * ldc + cb]) =
                        __floats2half2_rn(v0, v1);
            }
        }
    }
}

// ================= fp16x2 NT GEMM (lm_head; R12 proven, unchanged) ===========
__global__ __launch_bounds__(128, 2)
void gemm_f16(const float* __restrict__ A, const float* __restrict__ B,
              const float* __restrict__ bias, float* __restrict__ C,
              int K, int lda, int ldb, int ldc, float alpha, int act)
{
    __shared__ uint32_t sm[2][3][1024];

    int tid = threadIdx.x;
    int lane = tid & 31, warp = tid >> 5;
    int g = lane >> 2, c0 = lane & 3;
    int wm = (warp & 1) * 64, wn = (warp >> 1) * 64;

    int row0 = blockIdx.y * 128, col0 = blockIdx.x * 128;
    const float* Ag = A + (ll)row0 * lda;
    const float* Bg = B + (ll)col0 * ldb;

    int ur[4], uh[4], uw[4], ut[4];
#pragma unroll
    for (int p = 0; p < 4; p++) {
        int id = tid + 128 * p;
        ut[p] = (id < 256) ? 0 : 1;
        int id2 = id & 255;
        ur[p] = id2 >> 1; uh[p] = id2 & 1;
        uw[p] = ur[p] * 8 + 4 * (uh[p] ^ ((ur[p] >> 2) & 1));
    }
    int aBase[4], bBase[8];
#pragma unroll
    for (int mt = 0; mt < 4; mt++) {
        int r = wm + mt * 16 + g;
        aBase[mt] = r * 8 + (c0 ^ (((r >> 2) & 1) << 2));
    }
#pragma unroll
    for (int nt = 0; nt < 8; nt++) {
        int r = wn + nt * 8 + g;
        bBase[nt] = r * 8 + (c0 ^ (((r >> 2) & 1) << 2));
    }
    float acc[4][8][4];
#pragma unroll
    for (int a = 0; a < 4; a++)
#pragma unroll
        for (int b = 0; b < 8; b++)
#pragma unroll
            for (int c = 0; c < 4; c++) acc[a][b][c] = 0.f;

    float4 pf[8];
    const int NCH = K >> 4;
    auto LDGU = [&](int k0) {
#pragma unroll
        for (int p = 0; p < 4; p++) {
            const float* src = (ut[p] == 0)
                ? Ag + (ll)ur[p] * lda + k0 + 8 * uh[p]
                : Bg + (ll)ur[p] * ldb + k0 + 8 * uh[p];
            pf[2 * p]     = *reinterpret_cast<const float4*>(src);
            pf[2 * p + 1] = *reinterpret_cast<const float4*>(src + 4);
        }
    };
    auto STSU = [&](int buf) {
#pragma unroll
        for (int p = 0; p < 4; p++) {
            float4 f0 = pf[2 * p], f1 = pf[2 * p + 1];
            if (ut[p] == 0) {
                *reinterpret_cast<uint4*>(&sm[buf][0][uw[p]]) =
                    make_uint4(pack_hi16(f0.x, f0.y), pack_hi16(f0.z, f0.w),
                               pack_hi16(f1.x, f1.y), pack_hi16(f1.z, f1.w));
            } else {
                *reinterpret_cast<uint4*>(&sm[buf][1][uw[p]]) =
                    make_uint4(pack_hi16(f0.x, f0.y), pack_hi16(f0.z, f0.w),
                               pack_hi16(f1.x, f1.y), pack_hi16(f1.z, f1.w));
                *reinterpret_cast<uint4*>(&sm[buf][2][uw[p]]) =
                    make_uint4(pack_lores16(f0.x, f0.y), pack_lores16(f0.z, f0.w),
                               pack_lores16(f1.x, f1.y), pack_lores16(f1.z, f1.w));
            }
        }
    };
    LDGU(0); STSU(0); __syncthreads();

    for (int kb = 0; kb < NCH; kb++) {
        int buf = kb & 1;
        if (kb + 1 < NCH) LDGU((kb + 1) << 4);

        const uint32_t* AH = sm[buf][0];
        const uint32_t* BH = sm[buf][1];
        const uint32_t* BL = sm[buf][2];

        uint32_t ah[4][4], bH[8][2], bL[8][2];
#pragma unroll
        for (int mt = 0; mt < 4; mt++) {
            int a0 = aBase[mt];
            ah[mt][0] = AH[a0];      ah[mt][1] = AH[a0 + 64];
            ah[mt][2] = AH[a0 ^ 4];  ah[mt][3] = AH[(a0 + 64) ^ 4];
        }
#pragma unroll
        for (int nt = 0; nt < 8; nt++) {
            int b0 = bBase[nt];
            bH[nt][0] = BH[b0]; bH[nt][1] = BH[b0 ^ 4];
            bL[nt][0] = BL[b0]; bL[nt][1] = BL[b0 ^ 4];
        }
#pragma unroll
        for (int mt = 0; mt < 4; mt++)
#pragma unroll
            for (int nt = 0; nt < 8; nt++)
                MMA_F16(acc[mt][nt], ah[mt], bH[nt][0], bH[nt][1]);
#pragma unroll
        for (int mt = 0; mt < 4; mt++)
#pragma unroll
            for (int nt = 0; nt < 8; nt++)
                MMA_F16(acc[mt][nt], ah[mt], bL[nt][0], bL[nt][1]);

        if (kb + 1 < NCH) STSU(buf ^ 1);
        __syncthreads();
    }

#pragma unroll
    for (int mt = 0; mt < 4; mt++) {
#pragma unroll
        for (int nt = 0; nt < 8; nt++) {
            int cb = col0 + wn + nt * 8 + 2 * c0;
#pragma unroll
            for (int h = 0; h < 2; h++) {
                int r = row0 + wm + mt * 16 + g + h * 8;
                float v0 = acc[mt][nt][h * 2 + 0] * alpha;
                float v1 = acc[mt][nt][h * 2 + 1] * alpha;
                *reinterpret_cast<float2*>(&C[(ll)r * ldc + cb]) = make_float2(v0, v1);
            }
        }
    }
}

// ================= small-tile bf16x3 NT GEMM (Wg/WB; unchanged) ========
__global__ __launch_bounds__(128, 4)
void gemm_small(const float* __restrict__ A, const float* __restrict__ B,
                const float* __restrict__ bias, float* __restrict__ C,
                int K, int lda, int ldb, int ldc)
{
    __shared__ uint32_t AsH[1024], AsL[1024], BsH[1024], BsL[1024];
    int tid = threadIdx.x;
    int lane = tid & 31, warp = tid >> 5;
    int g = lane >> 2, c0 = lane & 3;
    int wm = (warp & 1) * 32, wn = (warp >> 1) * 32;
    int row0 = blockIdx.y * 64, col0 = blockIdx.x * 64;
    const float* Ag = A + (ll)row0 * lda;
    const float* Bg = B + (ll)col0 * ldb;

    float acc[2][4][4];
#pragma unroll
    for (int a = 0; a < 2; a++)
#pragma unroll
        for (int b = 0; b < 4; b++)
#pragma unroll
            for (int c = 0; c < 4; c++) acc[a][b][c] = 0.f;

    int aAddr[2][4], bAddr[4][2];
#pragma unroll
    for (int mt = 0; mt < 2; mt++)
#pragma unroll
        for (int i = 0; i < 4; i++) {
            int r = wm + mt * 16 + g + (i & 1) * 8;
            int j = c0 + (i >> 1) * 4;
            aAddr[mt][i] = r * 16 + (j ^ (((r >> 1) & 3) << 2));
        }
#pragma unroll
    for (int nt = 0; nt < 4; nt++)
#pragma unroll
        for (int i = 0; i < 2; i++) {
            int r = wn + nt * 8 + g;
            int j = c0 + i * 4;
            bAddr[nt][i] = r * 16 + (j ^ (((r >> 1) & 3) << 2));
        }

    for (int k0 = 0; k0 < K; k0 += 32) {
        __syncthreads();
#pragma unroll
        for (int p = 0; p < 8; p++) {
            int f = tid + 128 * p;
            int isA = f < 512;
            int fb = f & 511;
            int m = fb >> 3, q = fb & 7;
            const float* src = isA ? Ag + (ll)m * lda + k0 + q * 4
                                   : Bg + (ll)m * ldb + k0 + q * 4;
            float4 f4 = *reinterpret_cast<const float4*>(src);
            uint32_t w0 = m * 16 + ((2 * q) ^ (((m >> 1) & 3) << 2));
            if (isA) {
                *reinterpret_cast<uint2*>(AsH + w0) = make_uint2(pack_hi(f4.x, f4.y), pack_hi(f4.z, f4.w));
                *reinterpret_cast<uint2*>(AsL + w0) = make_uint2(pack_lo(f4.x, f4.y), pack_lo(f4.z, f4.w));
            } else {
                *reinterpret_cast<uint2*>(BsH + w0) = make_uint2(pack_hi(f4.x, f4.y), pack_hi(f4.z, f4.w));
                *reinterpret_cast<uint2*>(BsL + w0) = make_uint2(pack_lo(f4.x, f4.y), pack_lo(f4.z, f4.w));
            }
        }
        __syncthreads();
#pragma unroll
        for (int ks = 0; ks < 2; ks++) {
            int kx = ks * 8;
            uint32_t ah[2][4], al[2][4], bH[4][2], bL[4][2];
#pragma unroll
            for (int mt = 0; mt < 2; mt++)
#pragma unroll
                for (int i = 0; i < 4; i++) {
                    ah[mt][i] = AsH[aAddr[mt][i] ^ kx];
                    al[mt][i] = AsL[aAddr[mt][i] ^ kx];
                }
#pragma unroll
            for (int nt = 0; nt < 4; nt++)
#pragma unroll
                for (int i = 0; i < 2; i++) {
                    bH[nt][i] = BsH[bAddr[nt][i] ^ kx];
                    bL[nt][i] = BsL[bAddr[nt][i] ^ kx];
                }
#pragma unroll
            for (int mt = 0; mt < 2; mt++)
#pragma unroll
                for (int nt = 0; nt < 4; nt++)
                    MMA_BF16(acc[mt][nt], ah[mt], bH[nt][0], bH[nt][1]);
#pragma unroll
            for (int mt = 0; mt < 2; mt++)
#pragma unroll
                for (int nt = 0; nt < 4; nt++)
                    MMA_BF16(acc[mt][nt], al[mt], bH[nt][0], bH[nt][1]);
#pragma unroll
            for (int mt = 0; mt < 2; mt++)
#pragma unroll
                for (int nt = 0; nt < 4; nt++)
                    MMA_BF16(acc[mt][nt], ah[mt], bL[nt][0], bL[nt][1]);
        }
    }
#pragma unroll
    for (int mt = 0; mt < 2; mt++) {
#pragma unroll
        for (int nt = 0; nt < 4; nt++) {
            int cb = col0 + wn + nt * 8 + 2 * c0;
            float bz0 = bias ? bias[cb] : 0.f;
            float bz1 = bias ? bias[cb + 1] : 0.f;
#pragma unroll
            for (int h = 0; h < 2; h++) {
                int r = row0 + wm + mt * 16 + g + h * 8;
                float v0 = acc[mt][nt][h * 2 + 0] + bz0;
                float v1 = acc[mt][nt][h * 2 + 1] + bz1;
                *reinterpret_cast<float2*>(&C[(ll)r * ldc + cb]) = make_float2(v0, v1);
            }
        }
    }
}

// ---------------- elementwise ----------------
__global__ void embed_kernel(const int* __restrict__ ids, const float* __restrict__ emb,
                             const float* __restrict__ pos, float* __restrict__ x) {
    int t = blockIdx.x;
    int id = ids[t];
    int s = t % SS;
    const float* er = emb + (ll)id * HH;
    const float* pr = pos + (ll)s * HH;
    float* xr = x + (ll)t * HH;
    for (int j = threadIdx.x; j < HH; j += blockDim.x) xr[j] = er[j] + pr[j];
}

__global__ void ln_kernel(float* __restrict__ out, __half* __restrict__ outh,
                          const float* __restrict__ a,
                          const float* __restrict__ res, const float* __restrict__ coef,
                          float coef_off, const float* __restrict__ g,
                          const float* __restrict__ bvec, float scale) {
    int t = blockIdx.x;
    __shared__ float red[256];
    float v[4];
    float s = 0.f;
#pragma unroll
    for (int j = 0; j < 4; j++) {
        int h = threadIdx.x + 256 * j;
        float xv = a[(ll)t * HH + h];
        if (res) {
            float c = (coef ? coef[h] : 0.f) + coef_off;
            xv += c * res[(ll)t * HH + h];
        }
        v[j] = xv;
        s += xv;
    }
    red[threadIdx.x] = s; __syncthreads();
    for (int o = 128; o > 0; o >>= 1) { if (threadIdx.x < o) red[threadIdx.x] += red[threadIdx.x + o]; __syncthreads(); }
    float mean = red[0] * (1.f / HH); __syncthreads();
    float s2 = 0.f;
#pragma unroll
    for (int j = 0; j < 4; j++) { float d = v[j] - mean; s2 += d * d; }
    red[threadIdx.x] = s2; __syncthreads();
    for (int o = 128; o > 0; o >>= 1) { if (threadIdx.x < o) red[threadIdx.x] += red[threadIdx.x + o]; __syncthreads(); }
    float rstd = rsqrtf(red[0] * (1.f / HH) + 1e-5f);
#pragma unroll
    for (int j = 0; j < 4; j++) {
        int h = threadIdx.x + 256 * j;
        float ov = ((v[j] - mean) * rstd * g[h] + bvec[h]) * scale;
        out[(ll)t * HH + h] = ov;
        if (outh) outh[(ll)t * HH + h] = __float2half_rn(ov);
    }
}

__global__ void gate_u_kernel(const float* __restrict__ gl, float* __restrict__ u, int n) {
    int i = blockIdx.x * blockDim.x + threadIdx.x;
    if (i < n) u[i] = u[i] / (1.f + expf(-gl[i]));
}

__global__ void scan_kernel(float* __restrict__ u, __half* __restrict__ uh,
                            const float* __restrict__ A_log) {
    int b = blockIdx.x, n = threadIdx.x;
    float a = expf(A_log[n]);
    float s = 0.f;
    ll base = (ll)b * SS * NST + n;
    for (int t0 = 0; t0 < SS; t0 += 8) {
        float uv[8];
#pragma unroll
        for (int j = 0; j < 8; j++) uv[j] = u[base + (ll)(t0 + j) * NST];
#pragma unroll
        for (int j = 0; j < 8; j++) { s = a * s + uv[j]; uv[j] = s; }
#pragma unroll
        for (int j = 0; j < 8; j++) {
            u [base + (ll)(t0 + j) * NST] = uv[j];
            uh[base + (ll)(t0 + j) * NST] = __float2half_rn(uv[j]);
        }
    }
}

__global__ void softmax512(float* __restrict__ p) {
    ll row = blockIdx.x;
    float* r = p + row * SS;
    int t = threadIdx.x;
    float v0 = r[t], v1 = r[t + 256];
    __shared__ float red[256];
    red[t] = fmaxf(v0, v1); __syncthreads();
    for (int o = 128; o > 0; o >>= 1) { if (t < o) red[t] = fmaxf(red[t], red[t + o]); __syncthreads(); }
    float m = red[0]; __syncthreads();
    float e0 = expf(v0 - m), e1 = expf(v1 - m);
    red[t] = e0 + e1; __syncthreads();
    for (int o = 128; o > 0; o >>= 1) { if (t < o) red[t] += red[t + o]; __syncthreads(); }
    float inv = 1.f / red[0];
    r[t] = e0 * inv; r[t + 256] = e1 * inv;
}

__global__ void transpose_v(const float* __restrict__ qkv, float* __restrict__ vt) {
    __shared__ float tile[32][33];
    int b = blockIdx.z >> 3, h = blockIdx.z & 7;
    int s0 = blockIdx.x * 32, d0 = blockIdx.y * 32;
    int tx = threadIdx.x, ty = threadIdx.y;
    for (int i = ty; i < 32; i += 8)
        tile[i][tx] = qkv[((ll)(b * SS + s0 + i)) * (3 * HH) + 2 * HH + h * DHD + d0 + tx];
    __syncthreads();
    for (int i = ty; i < 32; i += 8)
        vt[((ll)blockIdx.z * DHD + d0 + i) * SS + s0 + tx] = tile[tx][i];
}

// ---------------- host ----------------
static inline void GB(const float* A, const float* B, const float* bias, float* C,
                      __half* Ch, int M, int N, int K, int lda, int ldb, int ldc,
                      int batch, int zmod,
                      ll sAa, ll sAb, ll sBa, ll sBb, ll sCa, ll sCb,
                      float alpha, int act) {
    dim3 grid(N / 128, M / 128, batch);
    gemm_main<<<grid, 128>>>(A, B, bias, C, Ch, K, lda, ldb, ldc, zmod,
                             sAa, sAb, sBa, sBb, sCa, sCb, alpha, act);
}
static inline void GFH(const __half* A, const __half* B, const float* bias, float* C,
                       __half* Ch, int M, int N, int K, int lda, int ldb, int ldc,
                       float alpha = 1.f, int act = 0) {
    dim3 grid(N / 128, M / 128);
    gemm_fh<<<grid, 128>>>(A, B, bias, C, Ch, K, lda, ldb, ldc, alpha, act);
}
static inline void GF2(const float* A, const float* B, float* C,
                       int M, int N, int K, int lda, int ldb, int ldc) {
    dim3 grid(N / 128, M / 128);
    gemm_f16<<<grid, 128>>>(A, B, nullptr, C, K, lda, ldb, ldc, 1.f, 0);
}
static inline void GS(const float* A, const float* B, const float* bias, float* C,
                      int M, int N, int K, int lda, int ldb, int ldc) {
    dim3 grid(N / 64, M / 64);
    gemm_small<<<grid, 128>>>(A, B, bias, C, K, lda, ldb, ldc);
}

extern "C" void kernel_launch(void* const* d_in, const int* in_sizes, int n_in,
                              void* d_out, int out_size) {
    const int*   ids  = (const int*)  d_in[0];
    const float* emb  = (const float*)d_in[1];
    const float* pos  = (const float*)d_in[2];
    const float* A_log= (const float*)d_in[3];
    const float* WB   = (const float*)d_in[4];
    const float* WC   = (const float*)d_in[5];
    const float* Dp   = (const float*)d_in[6];
    const float* Wg   = (const float*)d_in[7];
    const float* bg   = (const float*)d_in[8];
    const float* Wout = (const float*)d_in[9];
    const float* bout = (const float*)d_in[10];
    const float* gs   = (const float*)d_in[11];
    const float* bs   = (const float*)d_in[12];
    const float* Wqkv = (const float*)d_in[13];
    const float* bqkv = (const float*)d_in[14];
    const float* Wo   = (const float*)d_in[15];
    const float* bo   = (const float*)d_in[16];
    const float* W1   = (const float*)d_in[17];
    const float* b1   = (const float*)d_in[18];
    const float* W2   = (const float*)d_in[19];
    const float* b2   = (const float*)d_in[20];
    const float* g1   = (const float*)d_in[21];
    const float* bn1  = (const float*)d_in[22];
    const float* g2   = (const float*)d_in[23];
    const float* bn2  = (const float*)d_in[24];
    const float* g3   = (const float*)d_in[25];
    const float* bn3  = (const float*)d_in[26];
    const float* gf   = (const float*)d_in[27];
    const float* bf   = (const float*)d_in[28];

    float *x, *t1, *t2, *sc, *vt;
    __half *xh, *t1h, *t2h, *wh;
    cudaGetSymbolAddress((void**)&x,   g_x);
    cudaGetSymbolAddress((void**)&t1,  g_t1);
    cudaGetSymbolAddress((void**)&t2,  g_t2);
    cudaGetSymbolAddress((void**)&sc,  g_sc);
    cudaGetSymbolAddress((void**)&vt,  g_vt);
    cudaGetSymbolAddress((void**)&xh,  g_xh);
    cudaGetSymbolAddress((void**)&t1h, g_t1h);
    cudaGetSymbolAddress((void**)&t2h, g_t2h);
    cudaGetSymbolAddress((void**)&wh,  g_wh);

    auto F2H = [&](const float* src, ll off, ll n) {
        f2h_kernel<<<(int)((n / 4 + 255) / 256), 256>>>(src, wh + off, (int)n);
    };
    F2H(WC,   OFF_WC,   (ll)LL * HH * NST);
    F2H(Wout, OFF_WOUT, (ll)LL * HH * HH);
    F2H(Wqkv, OFF_WQKV, (ll)LL * 3 * HH * HH);
    F2H(Wo,   OFF_WO,   (ll)LL * HH * HH);
    F2H(W1,   OFF_W1,   (ll)LL * FFD * HH);
    F2H(W2,   OFF_W2,   (ll)LL * HH * FFD);

    embed_kernel<<<TT, 256>>>(ids, emb, pos, x);

    for (int i = 0; i < LL; i++) {
        // ===== SSM =====
        GS(x, Wg + (ll)i * NST * HH, bg + (ll)i * NST, t1, TT, NST, HH, HH, HH, NST);
        GS(x, WB + (ll)i * NST * HH, nullptr,          t2, TT, NST, HH, HH, HH, NST);
        gate_u_kernel<<<(TT * NST + 255) / 256, 256>>>(t1, t2, TT * NST);
        scan_kernel<<<BB, NST>>>(t2, t2h, A_log + (ll)i * NST);
        GFH(t2h, wh + OFF_WC + (ll)i * HH * NST, nullptr, t1, nullptr,
            TT, HH, NST, NST, NST, HH);
        ln_kernel<<<TT, 256>>>(t2, t2h, t1, x, Dp + (ll)i * HH, 1.f,
                               gs + (ll)i * HH, bs + (ll)i * HH, 1.f);
        GFH(t2h, wh + OFF_WOUT + (ll)i * HH * HH, bout + (ll)i * HH, t1, nullptr,
            TT, HH, HH, HH, HH, HH);
        ln_kernel<<<TT, 256>>>(x, xh, t1, x, nullptr, 1.f,
                               g1 + (ll)i * HH, bn1 + (ll)i * HH, 1.f);

        // ===== attention (odd layers) + memory fold (x2) =====
        if (i & 1) {
            GFH(xh, wh + OFF_WQKV + (ll)i * 3 * HH * HH, bqkv + (ll)i * 3 * HH,
                t1, nullptr, TT, 3 * HH, HH, HH, HH, 3 * HH);
            float asc = 1.f / sqrtf((float)DHD);
            GB(t1, t1 + HH, nullptr, sc, nullptr, SS, SS, DHD, 3 * HH, 3 * HH, SS,
               BB * NHD, NHD,
               (ll)SS * 3 * HH, DHD,
               (ll)SS * 3 * HH, DHD,
               (ll)NHD * SS * SS, (ll)SS * SS, asc, 0);
            softmax512<<<BB * NHD * SS, 256>>>(sc);
            {
                dim3 tg(SS / 32, DHD / 32, BB * NHD);
                transpose_v<<<tg, dim3(32, 8)>>>(t1, vt);
            }
            GB(sc, vt, nullptr, t2, t2h, SS, DHD, SS, SS, SS, HH,
               BB * NHD, NHD,
               (ll)NHD * SS * SS, (ll)SS * SS,
               (ll)NHD * DHD * SS, (ll)DHD * SS,
               (ll)SS * HH, DHD, 1.f, 0);
            GFH(t2h, wh + OFF_WO + (ll)i * HH * HH, bo + (ll)i * HH, t1, nullptr,
                TT, HH, HH, HH, HH, HH);
            ln_kernel<<<TT, 256>>>(x, xh, t1, x, nullptr, 1.f,
                                   g2 + (ll)i * HH, bn2 + (ll)i * HH, 2.f);
        } else {
            ln_kernel<<<TT, 256>>>(x, xh, x, nullptr, nullptr, 0.f,
                                   g2 + (ll)i * HH, bn2 + (ll)i * HH, 2.f);
        }

        // ===== FFN =====
        GFH(xh, wh + OFF_W1 + (ll)i * FFD * HH, b1 + (ll)i * FFD, t1, t1h,
            TT, FFD, HH, HH, HH, FFD, 1.f, 1);
        GFH(t1h, wh + OFF_W2 + (ll)i * HH * FFD, b2 + (ll)i * HH, t2, nullptr,
            TT, HH, FFD, FFD, FFD, HH);
        ln_kernel<<<TT, 256>>>(x, xh, t2, x, nullptr, 1.f,
                               g3 + (ll)i * HH, bn3 + (ll)i * HH, 1.f);
    }

    // ===== final LN + tied lm_head (fp16x2, fp32 operands as before) =====
    ln_kernel<<<TT, 256>>>(t1, nullptr, x, nullptr, nullptr, 0.f, gf, bf, 1.f);
    GF2(t1, emb, (float*)d_out, TT, VV, HH, HH, HH, VV);
}

// round 15
// speedup vs baseline: 1.9144x; 1.1101x over previous
#include <cuda_runtime.h>
#include <cuda_bf16.h>
#include <cuda_fp16.h>
#include <math.h>
#include <stdint.h>

#define TT 2048
#define SS 512
#define BB 4
#define HH 1024
#define NST 128
#define LL 6
#define VV 32000
#define NHD 8
#define FFD 4096
#define DHD 128
typedef long long ll;

// ---------------- scratch ----------------
__device__ float g_x [TT * HH];
__device__ float g_t1[TT * FFD];
__device__ float g_t2[TT * FFD];
__device__ float g_sc[BB * NHD * SS * SS];
__device__ float g_vt[BB * NHD * DHD * SS];
// fp16 shadows + weight arenas
__device__ __half g_xh [TT * HH];
__device__ __half g_t1h[TT * FFD];
__device__ __half g_t2h[TT * HH];
__device__ __half g_embh[(ll)VV * HH];
#define OFF_WC    0LL
#define OFF_WOUT  786432LL
#define OFF_WQKV  7077888LL
#define OFF_WO    25952256LL
#define OFF_W1    32243712LL
#define OFF_W2    57409536LL
#define WH_TOTAL  82575360LL
__device__ __half g_wh[WH_TOTAL];

__device__ __forceinline__ uint32_t smem_u32(const void* p) {
    uint32_t a;
    asm("{ .reg .u64 t; cvta.to.shared.u64 t, %1; cvt.u32.u64 %0, t; }" : "=r"(a) : "l"(p));
    return a;
}

// bf16 packers
__device__ __forceinline__ uint32_t pack_hi(float x, float y) {
    __nv_bfloat162 h = __floats2bfloat162_rn(x, y);
    return *reinterpret_cast<uint32_t*>(&h);
}
__device__ __forceinline__ uint32_t pack_lo(float x, float y) {
    float hx = __bfloat162float(__float2bfloat16_rn(x));
    float hy = __bfloat162float(__float2bfloat16_rn(y));
    __nv_bfloat162 l = __floats2bfloat162_rn(x - hx, y - hy);
    return *reinterpret_cast<uint32_t*>(&l);
}

#define MMA_BF16(ACC, AFR, BF0, BF1)                                            \
    asm volatile(                                                               \
        "mma.sync.aligned.m16n8k16.row.col.f32.bf16.bf16.f32 "                  \
        "{%0,%1,%2,%3}, {%4,%5,%6,%7}, {%8,%9}, {%0,%1,%2,%3};"                 \
        : "+f"((ACC)[0]), "+f"((ACC)[1]), "+f"((ACC)[2]), "+f"((ACC)[3])        \
        : "r"((AFR)[0]), "r"((AFR)[1]), "r"((AFR)[2]), "r"((AFR)[3]),           \
          "r"(BF0), "r"(BF1))

#define MMA_F16(ACC, AFR, BF0, BF1)                                             \
    asm volatile(                                                               \
        "mma.sync.aligned.m16n8k16.row.col.f32.f16.f16.f32 "                    \
        "{%0,%1,%2,%3}, {%4,%5,%6,%7}, {%8,%9}, {%0,%1,%2,%3};"                 \
        : "+f"((ACC)[0]), "+f"((ACC)[1]), "+f"((ACC)[2]), "+f"((ACC)[3])        \
        : "r"((AFR)[0]), "r"((AFR)[1]), "r"((AFR)[2]), "r"((AFR)[3]),           \
          "r"(BF0), "r"(BF1))

#define CP16(dst, src) asm volatile(                                            \
    "cp.async.cg.shared.global [%0], [%1], 16;" :: "r"(dst), "l"(src))

// ---------------- fp32 -> fp16 conversion ----------------
__global__ void f2h_kernel(const float* __restrict__ src, __half* __restrict__ dst, int n) {
    int i = (blockIdx.x * blockDim.x + threadIdx.x) * 4;
    if (i < n) {
        float4 f = *reinterpret_cast<const float4*>(src + i);
        *reinterpret_cast<__half2*>(dst + i)     = __floats2half2_rn(f.x, f.y);
        *reinterpret_cast<__half2*>(dst + i + 2) = __floats2half2_rn(f.z, f.w);
    }
}

// ================= fp16xfp16 single-pass NT GEMM (cp.async staged) ===========
__global__ __launch_bounds__(128, 2)
void gemm_fh(const __half* __restrict__ A, const __half* __restrict__ B,
             const float* __restrict__ bias, float* __restrict__ C,
             __half* __restrict__ Ch,
             int K, int lda, int ldb, int ldc, float alpha, int act)
{
    __shared__ __align__(16) uint32_t sm[2][2][1024];

    int tid = threadIdx.x;
    int lane = tid & 31, warp = tid >> 5;
    int g = lane >> 2, c0 = lane & 3;
    int wm = (warp & 1) * 64, wn = (warp >> 1) * 64;

    int row0 = blockIdx.y * 128, col0 = blockIdx.x * 128;
    const __half* Ag = A + (ll)row0 * lda;
    const __half* Bg = B + (ll)col0 * ldb;
    uint32_t smb = smem_u32(sm);

    int aBase[4], bBase[8];
#pragma unroll
    for (int mt = 0; mt < 4; mt++) {
        int r = wm + mt * 16 + g;
        aBase[mt] = r * 8 + (c0 ^ (((r >> 2) & 1) << 2));
    }
#pragma unroll
    for (int nt = 0; nt < 8; nt++) {
        int r = wn + nt * 8 + g;
        bBase[nt] = r * 8 + (c0 ^ (((r >> 2) & 1) << 2));
    }
    float acc[4][8][4];
#pragma unroll
    for (int a = 0; a < 4; a++)
#pragma unroll
        for (int b = 0; b < 8; b++)
#pragma unroll
            for (int c = 0; c < 4; c++) acc[a][b][c] = 0.f;

    const int NCH = K >> 4;
    auto issue = [&](int kc) {
        int buf = kc & 1, k0 = kc << 4;
#pragma unroll
        for (int p = 0; p < 4; p++) {
            int u = tid + 128 * p;
            int row = u >> 1, ch = u & 1;
            int r = row & 127;
            const __half* src = (row < 128)
                ? Ag + (ll)r * lda + k0 + ch * 8
                : Bg + (ll)r * ldb + k0 + ch * 8;
            uint32_t w = (uint32_t)(buf * 2048 + (row < 128 ? 0 : 1024)
                        + r * 8 + ((ch * 4) ^ (((r >> 2) & 1) << 2)));
            CP16(smb + w * 4u, src);
        }
        asm volatile("cp.async.commit_group;");
    };

    issue(0);
    for (int kb = 0; kb < NCH; kb++) {
        if (kb + 1 < NCH) {
            issue(kb + 1);
            asm volatile("cp.async.wait_group 1;");
        } else {
            asm volatile("cp.async.wait_group 0;");
        }
        __syncthreads();
        const uint32_t* AH = sm[kb & 1][0];
        const uint32_t* BH = sm[kb & 1][1];

        uint32_t ah[4][4], bH[8][2];
#pragma unroll
        for (int mt = 0; mt < 4; mt++) {
            int a0 = aBase[mt];
            ah[mt][0] = AH[a0];      ah[mt][1] = AH[a0 + 64];
            ah[mt][2] = AH[a0 ^ 4];  ah[mt][3] = AH[(a0 + 64) ^ 4];
        }
#pragma unroll
        for (int nt = 0; nt < 8; nt++) {
            int b0 = bBase[nt];
            bH[nt][0] = BH[b0]; bH[nt][1] = BH[b0 ^ 4];
        }
#pragma unroll
        for (int mt = 0; mt < 4; mt++)
#pragma unroll
            for (int nt = 0; nt < 8; nt++)
                MMA_F16(acc[mt][nt], ah[mt], bH[nt][0], bH[nt][1]);
        __syncthreads();
    }

#pragma unroll
    for (int mt = 0; mt < 4; mt++) {
#pragma unroll
        for (int nt = 0; nt < 8; nt++) {
            int cb = col0 + wn + nt * 8 + 2 * c0;
            float bz0 = bias ? bias[cb] : 0.f;
            float bz1 = bias ? bias[cb + 1] : 0.f;
#pragma unroll
            for (int h = 0; h < 2; h++) {
                int r = row0 + wm + mt * 16 + g + h * 8;
                float v0 = acc[mt][nt][h * 2 + 0] * alpha + bz0;
                float v1 = acc[mt][nt][h * 2 + 1] * alpha + bz1;
                if (act) {
                    v0 = 0.5f * v0 * (1.f + erff(v0 * 0.70710678118654752f));
                    v1 = 0.5f * v1 * (1.f + erff(v1 * 0.70710678118654752f));
                }
                *reinterpret_cast<float2*>(&C[(ll)r * ldc + cb]) = make_float2(v0, v1);
                if (Ch)
                    *reinterpret_cast<__half2*>(&Ch[(ll)r * ldc + cb]) =
                        __floats2half2_rn(v0, v1);
            }
        }
    }
}

// ================= R10 bf16x3 NT GEMM (attention; + optional fp16 out) =======
__global__ __launch_bounds__(128, 2)
void gemm_main(const float* __restrict__ A, const float* __restrict__ B,
               const float* __restrict__ bias, float* __restrict__ C,
               __half* __restrict__ Ch,
               int K, int lda, int ldb, int ldc, int zmod,
               ll sAa, ll sAb, ll sBa, ll sBb, ll sCa, ll sCb, float alpha, int act)
{
    __shared__ uint32_t sm[2][4][1024];

    int tid = threadIdx.x;
    int lane = tid & 31, warp = tid >> 5;
    int g = lane >> 2, c0 = lane & 3;
    int wm = (warp & 1) * 64, wn = (warp >> 1) * 64;

    int z = blockIdx.z;
    int zq = z / zmod, zr = z % zmod;
    A += (ll)zq * sAa + (ll)zr * sAb;
    B += (ll)zq * sBa + (ll)zr * sBb;
    C += (ll)zq * sCa + (ll)zr * sCb;
    if (Ch) Ch += (ll)zq * sCa + (ll)zr * sCb;

    int row0 = blockIdx.y * 128, col0 = blockIdx.x * 128;
    const float* Ag = A + (ll)row0 * lda;
    const float* Bg = B + (ll)col0 * ldb;

    int ur[4], uh[4], uw[4], ut[4];
#pragma unroll
    for (int p = 0; p < 4; p++) {
        int id = tid + 128 * p;
        ut[p] = (id < 256) ? 0 : 2;
        int id2 = id & 255;
        ur[p] = id2 >> 1; uh[p] = id2 & 1;
        uw[p] = ur[p] * 8 + 4 * (uh[p] ^ ((ur[p] >> 2) & 1));
    }
    int aBase[4], bBase[8];
#pragma unroll
    for (int mt = 0; mt < 4; mt++) {
        int r = wm + mt * 16 + g;
        aBase[mt] = r * 8 + (c0 ^ (((r >> 2) & 1) << 2));
    }
#pragma unroll
    for (int nt = 0; nt < 8; nt++) {
        int r = wn + nt * 8 + g;
        bBase[nt] = r * 8 + (c0 ^ (((r >> 2) & 1) << 2));
    }
    float acc[4][8][4];
#pragma unroll
    for (int a = 0; a < 4; a++)
#pragma unroll
        for (int b = 0; b < 8; b++)
#pragma unroll
            for (int c = 0; c < 4; c++) acc[a][b][c] = 0.f;

    float4 pf[8];
    const int NCH = K >> 4;
    auto LDGU = [&](int k0) {
#pragma unroll
        for (int p = 0; p < 4; p++) {
            const float* src = (ut[p] == 0)
                ? Ag + (ll)ur[p] * lda + k0 + 8 * uh[p]
                : Bg + (ll)ur[p] * ldb + k0 + 8 * uh[p];
            pf[2 * p]     = *reinterpret_cast<const float4*>(src);
            pf[2 * p + 1] = *reinterpret_cast<const float4*>(src + 4);
        }
    };
    auto STSU = [&](int buf) {
#pragma unroll
        for (int p = 0; p < 4; p++) {
            float4 f0 = pf[2 * p], f1 = pf[2 * p + 1];
            *reinterpret_cast<uint4*>(&sm[buf][ut[p]][uw[p]]) =
                make_uint4(pack_hi(f0.x, f0.y), pack_hi(f0.z, f0.w),
                           pack_hi(f1.x, f1.y), pack_hi(f1.z, f1.w));
            *reinterpret_cast<uint4*>(&sm[buf][ut[p] + 1][uw[p]]) =
                make_uint4(pack_lo(f0.x, f0.y), pack_lo(f0.z, f0.w),
                           pack_lo(f1.x, f1.y), pack_lo(f1.z, f1.w));
        }
    };
    LDGU(0); STSU(0); __syncthreads();

    for (int kb = 0; kb < NCH; kb++) {
        int buf = kb & 1;
        if (kb + 1 < NCH) LDGU((kb + 1) << 4);

        const uint32_t* AH = sm[buf][0];
        const uint32_t* AL = sm[buf][1];
        const uint32_t* BH = sm[buf][2];
        const uint32_t* BL = sm[buf][3];

        uint32_t ah[4][4], al[4][4], bH[8][2], bL[8][2];
#pragma unroll
        for (int mt = 0; mt < 4; mt++) {
            int a0 = aBase[mt];
            ah[mt][0] = AH[a0];      ah[mt][1] = AH[a0 + 64];
            ah[mt][2] = AH[a0 ^ 4];  ah[mt][3] = AH[(a0 + 64) ^ 4];
            al[mt][0] = AL[a0];      al[mt][1] = AL[a0 + 64];
            al[mt][2] = AL[a0 ^ 4];  al[mt][3] = AL[(a0 + 64) ^ 4];
        }
#pragma unroll
        for (int nt = 0; nt < 8; nt++) {
            int b0 = bBase[nt];
            bH[nt][0] = BH[b0]; bH[nt][1] = BH[b0 ^ 4];
            bL[nt][0] = BL[b0]; bL[nt][1] = BL[b0 ^ 4];
        }
#pragma unroll
        for (int mt = 0; mt < 4; mt++)
#pragma unroll
            for (int nt = 0; nt < 8; nt++)
                MMA_BF16(acc[mt][nt], ah[mt], bH[nt][0], bH[nt][1]);
#pragma unroll
        for (int mt = 0; mt < 4; mt++)
#pragma unroll
            for (int nt = 0; nt < 8; nt++)
                MMA_BF16(acc[mt][nt], al[mt], bH[nt][0], bH[nt][1]);
#pragma unroll
        for (int mt = 0; mt < 4; mt++)
#pragma unroll
            for (int nt = 0; nt < 8; nt++)
                MMA_BF16(acc[mt][nt], ah[mt], bL[nt][0], bL[nt][1]);

        if (kb + 1 < NCH) STSU(buf ^ 1);
        __syncthreads();
    }

#pragma unroll
    for (int mt = 0; mt < 4; mt++) {
#pragma unroll
        for (int nt = 0; nt < 8; nt++) {
            int cb = col0 + wn + nt * 8 + 2 * c0;
            float bz0 = bias ? bias[cb] : 0.f;
            float bz1 = bias ? bias[cb + 1] : 0.f;
#pragma unroll
            for (int h = 0; h < 2; h++) {
                int r = row0 + wm + mt * 16 + g + h * 8;
                float v0 = acc[mt][nt][h * 2 + 0] * alpha + bz0;
                float v1 = acc[mt][nt][h * 2 + 1] * alpha + bz1;
                if (act) {
                    v0 = 0.5f * v0 * (1.f + erff(v0 * 0.70710678118654752f));
                    v1 = 0.5f * v1 * (1.f + erff(v1 * 0.70710678118654752f));
                }
                *reinterpret_cast<float2*>(&C[(ll)r * ldc + cb]) = make_float2(v0, v1);
                if (Ch)
                    *reinterpret_cast<__half2*>(&Ch[(ll)r * ldc + cb]) =
                        __floats2half2_rn(v0, v1);
            }
        }
    }
}

// ================= small-tile bf16x3 NT GEMM (Wg/WB; unchanged) ========
__global__ __launch_bounds__(128, 4)
void gemm_small(const float* __restrict__ A, const float* __restrict__ B,
                const float* __restrict__ bias, float* __restrict__ C,
                int K, int lda, int ldb, int ldc)
{
    __shared__ uint32_t AsH[1024], AsL[1024], BsH[1024], BsL[1024];
    int tid = threadIdx.x;
    int lane = tid & 31, warp = tid >> 5;
    int g = lane >> 2, c0 = lane & 3;
    int wm = (warp & 1) * 32, wn = (warp >> 1) * 32;
    int row0 = blockIdx.y * 64, col0 = blockIdx.x * 64;
    const float* Ag = A + (ll)row0 * lda;
    const float* Bg = B + (ll)col0 * ldb;

    float acc[2][4][4];
#pragma unroll
    for (int a = 0; a < 2; a++)
#pragma unroll
        for (int b = 0; b < 4; b++)
#pragma unroll
            for (int c = 0; c < 4; c++) acc[a][b][c] = 0.f;

    int aAddr[2][4], bAddr[4][2];
#pragma unroll
    for (int mt = 0; mt < 2; mt++)
#pragma unroll
        for (int i = 0; i < 4; i++) {
            int r = wm + mt * 16 + g + (i & 1) * 8;
            int j = c0 + (i >> 1) * 4;
            aAddr[mt][i] = r * 16 + (j ^ (((r >> 1) & 3) << 2));
        }
#pragma unroll
    for (int nt = 0; nt < 4; nt++)
#pragma unroll
        for (int i = 0; i < 2; i++) {
            int r = wn + nt * 8 + g;
            int j = c0 + i * 4;
            bAddr[nt][i] = r * 16 + (j ^ (((r >> 1) & 3) << 2));
        }

    for (int k0 = 0; k0 < K; k0 += 32) {
        __syncthreads();
#pragma unroll
        for (int p = 0; p < 8; p++) {
            int f = tid + 128 * p;
            int isA = f < 512;
            int fb = f & 511;
            int m = fb >> 3, q = fb & 7;
            const float* src = isA ? Ag + (ll)m * lda + k0 + q * 4
                                   : Bg + (ll)m * ldb + k0 + q * 4;
            float4 f4 = *reinterpret_cast<const float4*>(src);
            uint32_t w0 = m * 16 + ((2 * q) ^ (((m >> 1) & 3) << 2));
            if (isA) {
                *reinterpret_cast<uint2*>(AsH + w0) = make_uint2(pack_hi(f4.x, f4.y), pack_hi(f4.z, f4.w));
                *reinterpret_cast<uint2*>(AsL + w0) = make_uint2(pack_lo(f4.x, f4.y), pack_lo(f4.z, f4.w));
            } else {
                *reinterpret_cast<uint2*>(BsH + w0) = make_uint2(pack_hi(f4.x, f4.y), pack_hi(f4.z, f4.w));
                *reinterpret_cast<uint2*>(BsL + w0) = make_uint2(pack_lo(f4.x, f4.y), pack_lo(f4.z, f4.w));
            }
        }
        __syncthreads();
#pragma unroll
        for (int ks = 0; ks < 2; ks++) {
            int kx = ks * 8;
            uint32_t ah[2][4], al[2][4], bH[4][2], bL[4][2];
#pragma unroll
            for (int mt = 0; mt < 2; mt++)
#pragma unroll
                for (int i = 0; i < 4; i++) {
                    ah[mt][i] = AsH[aAddr[mt][i] ^ kx];
                    al[mt][i] = AsL[aAddr[mt][i] ^ kx];
                }
#pragma unroll
            for (int nt = 0; nt < 4; nt++)
#pragma unroll
                for (int i = 0; i < 2; i++) {
                    bH[nt][i] = BsH[bAddr[nt][i] ^ kx];
                    bL[nt][i] = BsL[bAddr[nt][i] ^ kx];
                }
#pragma unroll
            for (int mt = 0; mt < 2; mt++)
#pragma unroll
                for (int nt = 0; nt < 4; nt++)
                    MMA_BF16(acc[mt][nt], ah[mt], bH[nt][0], bH[nt][1]);
#pragma unroll
            for (int mt = 0; mt < 2; mt++)
#pragma unroll
                for (int nt = 0; nt < 4; nt++)
                    MMA_BF16(acc[mt][nt], al[mt], bH[nt][0], bH[nt][1]);
#pragma unroll
            for (int mt = 0; mt < 2; mt++)
#pragma unroll
                for (int nt = 0; nt < 4; nt++)
                    MMA_BF16(acc[mt][nt], ah[mt], bL[nt][0], bL[nt][1]);
        }
    }
#pragma unroll
    for (int mt = 0; mt < 2; mt++) {
#pragma unroll
        for (int nt = 0; nt < 4; nt++) {
            int cb = col0 + wn + nt * 8 + 2 * c0;
            float bz0 = bias ? bias[cb] : 0.f;
            float bz1 = bias ? bias[cb + 1] : 0.f;
#pragma unroll
            for (int h = 0; h < 2; h++) {
                int r = row0 + wm + mt * 16 + g + h * 8;
                float v0 = acc[mt][nt][h * 2 + 0] + bz0;
                float v1 = acc[mt][nt][h * 2 + 1] + bz1;
                *reinterpret_cast<float2*>(&C[(ll)r * ldc + cb]) = make_float2(v0, v1);
            }
        }
    }
}

// ---------------- elementwise ----------------
__global__ void embed_kernel(const int* __restrict__ ids, const float* __restrict__ emb,
                             const float* __restrict__ pos, float* __restrict__ x) {
    int t = blockIdx.x;
    int id = ids[t];
    int s = t % SS;
    const float* er = emb + (ll)id * HH;
    const float* pr = pos + (ll)s * HH;
    float* xr = x + (ll)t * HH;
    for (int j = threadIdx.x; j < HH; j += blockDim.x) xr[j] = er[j] + pr[j];
}

__global__ void ln_kernel(float* __restrict__ out, __half* __restrict__ outh,
                          const float* __restrict__ a,
                          const float* __restrict__ res, const float* __restrict__ coef,
                          float coef_off, const float* __restrict__ g,
                          const float* __restrict__ bvec, float scale) {
    int t = blockIdx.x;
    __shared__ float red[256];
    float v[4];
    float s = 0.f;
#pragma unroll
    for (int j = 0; j < 4; j++) {
        int h = threadIdx.x + 256 * j;
        float xv = a[(ll)t * HH + h];
        if (res) {
            float c = (coef ? coef[h] : 0.f) + coef_off;
            xv += c * res[(ll)t * HH + h];
        }
        v[j] = xv;
        s += xv;
    }
    red[threadIdx.x] = s; __syncthreads();
    for (int o = 128; o > 0; o >>= 1) { if (threadIdx.x < o) red[threadIdx.x] += red[threadIdx.x + o]; __syncthreads(); }
    float mean = red[0] * (1.f / HH); __syncthreads();
    float s2 = 0.f;
#pragma unroll
    for (int j = 0; j < 4; j++) { float d = v[j] - mean; s2 += d * d; }
    red[threadIdx.x] = s2; __syncthreads();
    for (int o = 128; o > 0; o >>= 1) { if (threadIdx.x < o) red[threadIdx.x] += red[threadIdx.x + o]; __syncthreads(); }
    float rstd = rsqrtf(red[0] * (1.f / HH) + 1e-5f);
#pragma unroll
    for (int j = 0; j < 4; j++) {
        int h = threadIdx.x + 256 * j;
        float ov = ((v[j] - mean) * rstd * g[h] + bvec[h]) * scale;
        out[(ll)t * HH + h] = ov;
        if (outh) outh[(ll)t * HH + h] = __float2half_rn(ov);
    }
}

__global__ void gate_u_kernel(const float* __restrict__ gl, float* __restrict__ u, int n) {
    int i = blockIdx.x * blockDim.x + threadIdx.x;
    if (i < n) u[i] = u[i] / (1.f + expf(-gl[i]));
}

__global__ void scan_kernel(float* __restrict__ u, __half* __restrict__ uh,
                            const float* __restrict__ A_log) {
    int b = blockIdx.x, n = threadIdx.x;
    float a = expf(A_log[n]);
    float s = 0.f;
    ll base = (ll)b * SS * NST + n;
    for (int t0 = 0; t0 < SS; t0 += 8) {
        float uv[8];
#pragma unroll
        for (int j = 0; j < 8; j++) uv[j] = u[base + (ll)(t0 + j) * NST];
#pragma unroll
        for (int j = 0; j < 8; j++) { s = a * s + uv[j]; uv[j] = s; }
#pragma unroll
        for (int j = 0; j < 8; j++) {
            u [base + (ll)(t0 + j) * NST] = uv[j];
            uh[base + (ll)(t0 + j) * NST] = __float2half_rn(uv[j]);
        }
    }
}

__global__ void softmax512(float* __restrict__ p) {
    ll row = blockIdx.x;
    float* r = p + row * SS;
    int t = threadIdx.x;
    float v0 = r[t], v1 = r[t + 256];
    __shared__ float red[256];
    red[t] = fmaxf(v0, v1); __syncthreads();
    for (int o = 128; o > 0; o >>= 1) { if (t < o) red[t] = fmaxf(red[t], red[t + o]); __syncthreads(); }
    float m = red[0]; __syncthreads();
    float e0 = expf(v0 - m), e1 = expf(v1 - m);
    red[t] = e0 + e1; __syncthreads();
    for (int o = 128; o > 0; o >>= 1) { if (t < o) red[t] += red[t + o]; __syncthreads(); }
    float inv = 1.f / red[0];
    r[t] = e0 * inv; r[t + 256] = e1 * inv;
}

__global__ void transpose_v(const float* __restrict__ qkv, float* __restrict__ vt) {
    __shared__ float tile[32][33];
    int b = blockIdx.z >> 3, h = blockIdx.z & 7;
    int s0 = blockIdx.x * 32, d0 = blockIdx.y * 32;
    int tx = threadIdx.x, ty = threadIdx.y;
    for (int i = ty; i < 32; i += 8)
        tile[i][tx] = qkv[((ll)(b * SS + s0 + i)) * (3 * HH) + 2 * HH + h * DHD + d0 + tx];
    __syncthreads();
    for (int i = ty; i < 32; i += 8)
        vt[((ll)blockIdx.z * DHD + d0 + i) * SS + s0 + tx] = tile[tx][i];
}

// ---------------- host ----------------
static inline void GB(const float* A, const float* B, const float* bias, float* C,
                      __half* Ch, int M, int N, int K, int lda, int ldb, int ldc,
                      int batch, int zmod,
                      ll sAa, ll sAb, ll sBa, ll sBb, ll sCa, ll sCb,
                      float alpha, int act) {
    dim3 grid(N / 128, M / 128, batch);
    gemm_main<<<grid, 128>>>(A, B, bias, C, Ch, K, lda, ldb, ldc, zmod,
                             sAa, sAb, sBa, sBb, sCa, sCb, alpha, act);
}
static inline void GFH(const __half* A, const __half* B, const float* bias, float* C,
                       __half* Ch, int M, int N, int K, int lda, int ldb, int ldc,
                       float alpha = 1.f, int act = 0) {
    dim3 grid(N / 128, M / 128);
    gemm_fh<<<grid, 128>>>(A, B, bias, C, Ch, K, lda, ldb, ldc, alpha, act);
}
static inline void GS(const float* A, const float* B, const float* bias, float* C,
                      int M, int N, int K, int lda, int ldb, int ldc) {
    dim3 grid(N / 64, M / 64);
    gemm_small<<<grid, 128>>>(A, B, bias, C, K, lda, ldb, ldc);
}

extern "C" void kernel_launch(void* const* d_in, const int* in_sizes, int n_in,
                              void* d_out, int out_size) {
    const int*   ids  = (const int*)  d_in[0];
    const float* emb  = (const float*)d_in[1];
    const float* pos  = (const float*)d_in[2];
    const float* A_log= (const float*)d_in[3];
    const float* WB   = (const float*)d_in[4];
    const float* WC   = (const float*)d_in[5];
    const float* Dp   = (const float*)d_in[6];
    const float* Wg   = (const float*)d_in[7];
    const float* bg   = (const float*)d_in[8];
    const float* Wout = (const float*)d_in[9];
    const float* bout = (const float*)d_in[10];
    const float* gs   = (const float*)d_in[11];
    const float* bs   = (const float*)d_in[12];
    const float* Wqkv = (const float*)d_in[13];
    const float* bqkv = (const float*)d_in[14];
    const float* Wo   = (const float*)d_in[15];
    const float* bo   = (const float*)d_in[16];
    const float* W1   = (const float*)d_in[17];
    const float* b1   = (const float*)d_in[18];
    const float* W2   = (const float*)d_in[19];
    const float* b2   = (const float*)d_in[20];
    const float* g1   = (const float*)d_in[21];
    const float* bn1  = (const float*)d_in[22];
    const float* g2   = (const float*)d_in[23];
    const float* bn2  = (const float*)d_in[24];
    const float* g3   = (const float*)d_in[25];
    const float* bn3  = (const float*)d_in[26];
    const float* gf   = (const float*)d_in[27];
    const float* bf   = (const float*)d_in[28];

    float *x, *t1, *t2, *sc, *vt;
    __half *xh, *t1h, *t2h, *wh, *embh;
    cudaGetSymbolAddress((void**)&x,    g_x);
    cudaGetSymbolAddress((void**)&t1,   g_t1);
    cudaGetSymbolAddress((void**)&t2,   g_t2);
    cudaGetSymbolAddress((void**)&sc,   g_sc);
    cudaGetSymbolAddress((void**)&vt,   g_vt);
    cudaGetSymbolAddress((void**)&xh,   g_xh);
    cudaGetSymbolAddress((void**)&t1h,  g_t1h);
    cudaGetSymbolAddress((void**)&t2h,  g_t2h);
    cudaGetSymbolAddress((void**)&wh,   g_wh);
    cudaGetSymbolAddress((void**)&embh, g_embh);

    auto F2H = [&](const float* src, __half* dst, ll n) {
        f2h_kernel<<<(int)((n / 4 + 255) / 256), 256>>>(src, dst, (int)n);
    };
    F2H(WC,   wh + OFF_WC,   (ll)LL * HH * NST);
    F2H(Wout, wh + OFF_WOUT, (ll)LL * HH * HH);
    F2H(Wqkv, wh + OFF_WQKV, (ll)LL * 3 * HH * HH);
    F2H(Wo,   wh + OFF_WO,   (ll)LL * HH * HH);
    F2H(W1,   wh + OFF_W1,   (ll)LL * FFD * HH);
    F2H(W2,   wh + OFF_W2,   (ll)LL * HH * FFD);
    F2H(emb,  embh,          (ll)VV * HH);

    embed_kernel<<<TT, 256>>>(ids, emb, pos, x);

    for (int i = 0; i < LL; i++) {
        // ===== SSM =====
        GS(x, Wg + (ll)i * NST * HH, bg + (ll)i * NST, t1, TT, NST, HH, HH, HH, NST);
        GS(x, WB + (ll)i * NST * HH, nullptr,          t2, TT, NST, HH, HH, HH, NST);
        gate_u_kernel<<<(TT * NST + 255) / 256, 256>>>(t1, t2, TT * NST);
        scan_kernel<<<BB, NST>>>(t2, t2h, A_log + (ll)i * NST);
        GFH(t2h, wh + OFF_WC + (ll)i * HH * NST, nullptr, t1, nullptr,
            TT, HH, NST, NST, NST, HH);
        ln_kernel<<<TT, 256>>>(t2, t2h, t1, x, Dp + (ll)i * HH, 1.f,
                               gs + (ll)i * HH, bs + (ll)i * HH, 1.f);
        GFH(t2h, wh + OFF_WOUT + (ll)i * HH * HH, bout + (ll)i * HH, t1, nullptr,
            TT, HH, HH, HH, HH, HH);
        ln_kernel<<<TT, 256>>>(x, xh, t1, x, nullptr, 1.f,
                               g1 + (ll)i * HH, bn1 + (ll)i * HH, 1.f);

        // ===== attention (odd layers) + memory fold (x2) =====
        if (i & 1) {
            GFH(xh, wh + OFF_WQKV + (ll)i * 3 * HH * HH, bqkv + (ll)i * 3 * HH,
                t1, nullptr, TT, 3 * HH, HH, HH, HH, 3 * HH);
            float asc = 1.f / sqrtf((float)DHD);
            GB(t1, t1 + HH, nullptr, sc, nullptr, SS, SS, DHD, 3 * HH, 3 * HH, SS,
               BB * NHD, NHD,
               (ll)SS * 3 * HH, DHD,
               (ll)SS * 3 * HH, DHD,
               (ll)NHD * SS * SS, (ll)SS * SS, asc, 0);
            softmax512<<<BB * NHD * SS, 256>>>(sc);
            {
                dim3 tg(SS / 32, DHD / 32, BB * NHD);
                transpose_v<<<tg, dim3(32, 8)>>>(t1, vt);
            }
            GB(sc, vt, nullptr, t2, t2h, SS, DHD, SS, SS, SS, HH,
               BB * NHD, NHD,
               (ll)NHD * SS * SS, (ll)SS * SS,
               (ll)NHD * DHD * SS, (ll)DHD * SS,
               (ll)SS * HH, DHD, 1.f, 0);
            GFH(t2h, wh + OFF_WO + (ll)i * HH * HH, bo + (ll)i * HH, t1, nullptr,
                TT, HH, HH, HH, HH, HH);
            ln_kernel<<<TT, 256>>>(x, xh, t1, x, nullptr, 1.f,
                                   g2 + (ll)i * HH, bn2 + (ll)i * HH, 2.f);
        } else {
            ln_kernel<<<TT, 256>>>(x, xh, x, nullptr, nullptr, 0.f,
                                   g2 + (ll)i * HH, bn2 + (ll)i * HH, 2.f);
        }

        // ===== FFN =====
        GFH(xh, wh + OFF_W1 + (ll)i * FFD * HH, b1 + (ll)i * FFD, t1, t1h,
            TT, FFD, HH, HH, HH, FFD, 1.f, 1);
        GFH(t1h, wh + OFF_W2 + (ll)i * HH * FFD, b2 + (ll)i * HH, t2, nullptr,
            TT, HH, FFD, FFD, FFD, HH);
        ln_kernel<<<TT, 256>>>(x, xh, t2, x, nullptr, 1.f,
                               g3 + (ll)i * HH, bn3 + (ll)i * HH, 1.f);
    }

    // ===== final LN + tied lm_head (fp16x1, fp16 operands, L2-resident emb) ====
    ln_kernel<<<TT, 256>>>(t1, t1h, x, nullptr, nullptr, 0.f, gf, bf, 1.f);
    GFH(t1h, embh, nullptr, (float*)d_out, nullptr, TT, VV, HH, HH, HH, VV);
}

// round 16
// speedup vs baseline: 1.9775x; 1.0330x over previous
#include <cuda_runtime.h>
#include <cuda_bf16.h>
#include <cuda_fp16.h>
#include <math.h>
#include <stdint.h>

#define TT 2048
#define SS 512
#define BB 4
#define HH 1024
#define NST 128
#define LL 6
#define VV 32000
#define NHD 8
#define FFD 4096
#define DHD 128
typedef long long ll;

// ---------------- scratch ----------------
__device__ float g_x [TT * HH];
__device__ float g_t1[TT * FFD];
__device__ float g_t2[TT * FFD];
__device__ float g_sc[BB * NHD * SS * SS];
// fp16 shadows + arenas
__device__ __half g_xh [TT * HH];
__device__ __half g_t1h[TT * FFD];
__device__ __half g_t2h[TT * HH];
__device__ __half g_sch[BB * NHD * SS * SS];
__device__ __half g_vth[BB * NHD * DHD * SS];
__device__ __half g_embh[(ll)VV * HH];
#define OFF_WC    0LL
#define OFF_WOUT  786432LL
#define OFF_WQKV  7077888LL
#define OFF_WO    25952256LL
#define OFF_W1    32243712LL
#define OFF_W2    57409536LL
#define WH_TOTAL  82575360LL
__device__ __half g_wh[WH_TOTAL];

__device__ __forceinline__ uint32_t smem_u32(const void* p) {
    uint32_t a;
    asm("{ .reg .u64 t; cvta.to.shared.u64 t, %1; cvt.u32.u64 %0, t; }" : "=r"(a) : "l"(p));
    return a;
}

// bf16 packers (gemm_small)
__device__ __forceinline__ uint32_t pack_hi(float x, float y) {
    __nv_bfloat162 h = __floats2bfloat162_rn(x, y);
    return *reinterpret_cast<uint32_t*>(&h);
}
__device__ __forceinline__ uint32_t pack_lo(float x, float y) {
    float hx = __bfloat162float(__float2bfloat16_rn(x));
    float hy = __bfloat162float(__float2bfloat16_rn(y));
    __nv_bfloat162 l = __floats2bfloat162_rn(x - hx, y - hy);
    return *reinterpret_cast<uint32_t*>(&l);
}

#define MMA_BF16(ACC, AFR, BF0, BF1)                                            \
    asm volatile(                                                               \
        "mma.sync.aligned.m16n8k16.row.col.f32.bf16.bf16.f32 "                  \
        "{%0,%1,%2,%3}, {%4,%5,%6,%7}, {%8,%9}, {%0,%1,%2,%3};"                 \
        : "+f"((ACC)[0]), "+f"((ACC)[1]), "+f"((ACC)[2]), "+f"((ACC)[3])        \
        : "r"((AFR)[0]), "r"((AFR)[1]), "r"((AFR)[2]), "r"((AFR)[3]),           \
          "r"(BF0), "r"(BF1))

#define MMA_F16(ACC, AFR, BF0, BF1)                                             \
    asm volatile(                                                               \
        "mma.sync.aligned.m16n8k16.row.col.f32.f16.f16.f32 "                    \
        "{%0,%1,%2,%3}, {%4,%5,%6,%7}, {%8,%9}, {%0,%1,%2,%3};"                 \
        : "+f"((ACC)[0]), "+f"((ACC)[1]), "+f"((ACC)[2]), "+f"((ACC)[3])        \
        : "r"((AFR)[0]), "r"((AFR)[1]), "r"((AFR)[2]), "r"((AFR)[3]),           \
          "r"(BF0), "r"(BF1))

#define CP16(dst, src) asm volatile(                                            \
    "cp.async.cg.shared.global [%0], [%1], 16;" :: "r"(dst), "l"(src))

// ---------------- fp32 -> fp16 conversion ----------------
__global__ void f2h_kernel(const float* __restrict__ src, __half* __restrict__ dst, int n) {
    int i = (blockIdx.x * blockDim.x + threadIdx.x) * 4;
    if (i < n) {
        float4 f = *reinterpret_cast<const float4*>(src + i);
        *reinterpret_cast<__half2*>(dst + i)     = __floats2half2_rn(f.x, f.y);
        *reinterpret_cast<__half2*>(dst + i + 2) = __floats2half2_rn(f.z, f.w);
    }
}

// ================= fp16xfp16 single-pass NT GEMM (cp.async staged; proven) ===
__global__ __launch_bounds__(128, 2)
void gemm_fh(const __half* __restrict__ A, const __half* __restrict__ B,
             const float* __restrict__ bias, float* __restrict__ C,
             __half* __restrict__ Ch,
             int K, int lda, int ldb, int ldc, float alpha, int act)
{
    __shared__ __align__(16) uint32_t sm[2][2][1024];

    int tid = threadIdx.x;
    int lane = tid & 31, warp = tid >> 5;
    int g = lane >> 2, c0 = lane & 3;
    int wm = (warp & 1) * 64, wn = (warp >> 1) * 64;

    int row0 = blockIdx.y * 128, col0 = blockIdx.x * 128;
    const __half* Ag = A + (ll)row0 * lda;
    const __half* Bg = B + (ll)col0 * ldb;
    uint32_t smb = smem_u32(sm);

    int aBase[4], bBase[8];
#pragma unroll
    for (int mt = 0; mt < 4; mt++) {
        int r = wm + mt * 16 + g;
        aBase[mt] = r * 8 + (c0 ^ (((r >> 2) & 1) << 2));
    }
#pragma unroll
    for (int nt = 0; nt < 8; nt++) {
        int r = wn + nt * 8 + g;
        bBase[nt] = r * 8 + (c0 ^ (((r >> 2) & 1) << 2));
    }
    float acc[4][8][4];
#pragma unroll
    for (int a = 0; a < 4; a++)
#pragma unroll
        for (int b = 0; b < 8; b++)
#pragma unroll
            for (int c = 0; c < 4; c++) acc[a][b][c] = 0.f;

    const int NCH = K >> 4;
    auto issue = [&](int kc) {
        int buf = kc & 1, k0 = kc << 4;
#pragma unroll
        for (int p = 0; p < 4; p++) {
            int u = tid + 128 * p;
            int row = u >> 1, ch = u & 1;
            int r = row & 127;
            const __half* src = (row < 128)
                ? Ag + (ll)r * lda + k0 + ch * 8
                : Bg + (ll)r * ldb + k0 + ch * 8;
            uint32_t w = (uint32_t)(buf * 2048 + (row < 128 ? 0 : 1024)
                        + r * 8 + ((ch * 4) ^ (((r >> 2) & 1) << 2)));
            CP16(smb + w * 4u, src);
        }
        asm volatile("cp.async.commit_group;");
    };

    issue(0);
    for (int kb = 0; kb < NCH; kb++) {
        if (kb + 1 < NCH) {
            issue(kb + 1);
            asm volatile("cp.async.wait_group 1;");
        } else {
            asm volatile("cp.async.wait_group 0;");
        }
        __syncthreads();
        const uint32_t* AH = sm[kb & 1][0];
        const uint32_t* BH = sm[kb & 1][1];

        uint32_t ah[4][4], bH[8][2];
#pragma unroll
        for (int mt = 0; mt < 4; mt++) {
            int a0 = aBase[mt];
            ah[mt][0] = AH[a0];      ah[mt][1] = AH[a0 + 64];
            ah[mt][2] = AH[a0 ^ 4];  ah[mt][3] = AH[(a0 + 64) ^ 4];
        }
#pragma unroll
        for (int nt = 0; nt < 8; nt++) {
            int b0 = bBase[nt];
            bH[nt][0] = BH[b0]; bH[nt][1] = BH[b0 ^ 4];
        }
#pragma unroll
        for (int mt = 0; mt < 4; mt++)
#pragma unroll
            for (int nt = 0; nt < 8; nt++)
                MMA_F16(acc[mt][nt], ah[mt], bH[nt][0], bH[nt][1]);
        __syncthreads();
    }

#pragma unroll
    for (int mt = 0; mt < 4; mt++) {
#pragma unroll
        for (int nt = 0; nt < 8; nt++) {
            int cb = col0 + wn + nt * 8 + 2 * c0;
            float bz0 = bias ? bias[cb] : 0.f;
            float bz1 = bias ? bias[cb + 1] : 0.f;
#pragma unroll
            for (int h = 0; h < 2; h++) {
                int r = row0 + wm + mt * 16 + g + h * 8;
                float v0 = acc[mt][nt][h * 2 + 0] * alpha + bz0;
                float v1 = acc[mt][nt][h * 2 + 1] * alpha + bz1;
                if (act) {
                    v0 = 0.5f * v0 * (1.f + erff(v0 * 0.70710678118654752f));
                    v1 = 0.5f * v1 * (1.f + erff(v1 * 0.70710678118654752f));
                }
                *reinterpret_cast<float2*>(&C[(ll)r * ldc + cb]) = make_float2(v0, v1);
                if (Ch)
                    *reinterpret_cast<__half2*>(&Ch[(ll)r * ldc + cb]) =
                        __floats2half2_rn(v0, v1);
            }
        }
    }
}

// ================= batched clone of gemm_fh (attention scores / attV) ========
// C (fp32) and Ch (fp16) both optional; z strides shared.
__global__ __launch_bounds__(128, 2)
void gemm_fh_b(const __half* __restrict__ A, const __half* __restrict__ B,
               float* __restrict__ C, __half* __restrict__ Ch,
               int K, int lda, int ldb, int ldc, int zmod,
               ll sAa, ll sAb, ll sBa, ll sBb, ll sCa, ll sCb, float alpha)
{
    __shared__ __align__(16) uint32_t sm[2][2][1024];

    int tid = threadIdx.x;
    int lane = tid & 31, warp = tid >> 5;
    int g = lane >> 2, c0 = lane & 3;
    int wm = (warp & 1) * 64, wn = (warp >> 1) * 64;

    int z = blockIdx.z;
    int zq = z / zmod, zr = z % zmod;
    A += (ll)zq * sAa + (ll)zr * sAb;
    B += (ll)zq * sBa + (ll)zr * sBb;
    if (C)  C  += (ll)zq * sCa + (ll)zr * sCb;
    if (Ch) Ch += (ll)zq * sCa + (ll)zr * sCb;

    int row0 = blockIdx.y * 128, col0 = blockIdx.x * 128;
    const __half* Ag = A + (ll)row0 * lda;
    const __half* Bg = B + (ll)col0 * ldb;
    uint32_t smb = smem_u32(sm);

    int aBase[4], bBase[8];
#pragma unroll
    for (int mt = 0; mt < 4; mt++) {
        int r = wm + mt * 16 + g;
        aBase[mt] = r * 8 + (c0 ^ (((r >> 2) & 1) << 2));
    }
#pragma unroll
    for (int nt = 0; nt < 8; nt++) {
        int r = wn + nt * 8 + g;
        bBase[nt] = r * 8 + (c0 ^ (((r >> 2) & 1) << 2));
    }
    float acc[4][8][4];
#pragma unroll
    for (int a = 0; a < 4; a++)
#pragma unroll
        for (int b = 0; b < 8; b++)
#pragma unroll
            for (int c = 0; c < 4; c++) acc[a][b][c] = 0.f;

    const int NCH = K >> 4;
    auto issue = [&](int kc) {
        int buf = kc & 1, k0 = kc << 4;
#pragma unroll
        for (int p = 0; p < 4; p++) {
            int u = tid + 128 * p;
            int row = u >> 1, ch = u & 1;
            int r = row & 127;
            const __half* src = (row < 128)
                ? Ag + (ll)r * lda + k0 + ch * 8
                : Bg + (ll)r * ldb + k0 + ch * 8;
            uint32_t w = (uint32_t)(buf * 2048 + (row < 128 ? 0 : 1024)
                        + r * 8 + ((ch * 4) ^ (((r >> 2) & 1) << 2)));
            CP16(smb + w * 4u, src);
        }
        asm volatile("cp.async.commit_group;");
    };

    issue(0);
    for (int kb = 0; kb < NCH; kb++) {
        if (kb + 1 < NCH) {
            issue(kb + 1);
            asm volatile("cp.async.wait_group 1;");
        } else {
            asm volatile("cp.async.wait_group 0;");
        }
        __syncthreads();
        const uint32_t* AH = sm[kb & 1][0];
        const uint32_t* BH = sm[kb & 1][1];

        uint32_t ah[4][4], bH[8][2];
#pragma unroll
        for (int mt = 0; mt < 4; mt++) {
            int a0 = aBase[mt];
            ah[mt][0] = AH[a0];      ah[mt][1] = AH[a0 + 64];
            ah[mt][2] = AH[a0 ^ 4];  ah[mt][3] = AH[(a0 + 64) ^ 4];
        }
#pragma unroll
        for (int nt = 0; nt < 8; nt++) {
            int b0 = bBase[nt];
            bH[nt][0] = BH[b0]; bH[nt][1] = BH[b0 ^ 4];
        }
#pragma unroll
        for (int mt = 0; mt < 4; mt++)
#pragma unroll
            for (int nt = 0; nt < 8; nt++)
                MMA_F16(acc[mt][nt], ah[mt], bH[nt][0], bH[nt][1]);
        __syncthreads();
    }

#pragma unroll
    for (int mt = 0; mt < 4; mt++) {
#pragma unroll
        for (int nt = 0; nt < 8; nt++) {
            int cb = col0 + wn + nt * 8 + 2 * c0;
#pragma unroll
            for (int h = 0; h < 2; h++) {
                int r = row0 + wm + mt * 16 + g + h * 8;
                float v0 = acc[mt][nt][h * 2 + 0] * alpha;
                float v1 = acc[mt][nt][h * 2 + 1] * alpha;
                if (C)
                    *reinterpret_cast<float2*>(&C[(ll)r * ldc + cb]) = make_float2(v0, v1);
                if (Ch)
                    *reinterpret_cast<__half2*>(&Ch[(ll)r * ldc + cb]) =
                        __floats2half2_rn(v0, v1);
            }
        }
    }
}

// ================= small-tile bf16x3 NT GEMM (Wg/WB; unchanged) ========
__global__ __launch_bounds__(128, 4)
void gemm_small(const float* __restrict__ A, const float* __restrict__ B,
                const float* __restrict__ bias, float* __restrict__ C,
                int K, int lda, int ldb, int ldc)
{
    __shared__ uint32_t AsH[1024], AsL[1024], BsH[1024], BsL[1024];
    int tid = threadIdx.x;
    int lane = tid & 31, warp = tid >> 5;
    int g = lane >> 2, c0 = lane & 3;
    int wm = (warp & 1) * 32, wn = (warp >> 1) * 32;
    int row0 = blockIdx.y * 64, col0 = blockIdx.x * 64;
    const float* Ag = A + (ll)row0 * lda;
    const float* Bg = B + (ll)col0 * ldb;

    float acc[2][4][4];
#pragma unroll
    for (int a = 0; a < 2; a++)
#pragma unroll
        for (int b = 0; b < 4; b++)
#pragma unroll
            for (int c = 0; c < 4; c++) acc[a][b][c] = 0.f;

    int aAddr[2][4], bAddr[4][2];
#pragma unroll
    for (int mt = 0; mt < 2; mt++)
#pragma unroll
        for (int i = 0; i < 4; i++) {
            int r = wm + mt * 16 + g + (i & 1) * 8;
            int j = c0 + (i >> 1) * 4;
            aAddr[mt][i] = r * 16 + (j ^ (((r >> 1) & 3) << 2));
        }
#pragma unroll
    for (int nt = 0; nt < 4; nt++)
#pragma unroll
        for (int i = 0; i < 2; i++) {
            int r = wn + nt * 8 + g;
            int j = c0 + i * 4;
            bAddr[nt][i] = r * 16 + (j ^ (((r >> 1) & 3) << 2));
        }

    for (int k0 = 0; k0 < K; k0 += 32) {
        __syncthreads();
#pragma unroll
        for (int p = 0; p < 8; p++) {
            int f = tid + 128 * p;
            int isA = f < 512;
            int fb = f & 511;
            int m = fb >> 3, q = fb & 7;
            const float* src = isA ? Ag + (ll)m * lda + k0 + q * 4
                                   : Bg + (ll)m * ldb + k0 + q * 4;
            float4 f4 = *reinterpret_cast<const float4*>(src);
            uint32_t w0 = m * 16 + ((2 * q) ^ (((m >> 1) & 3) << 2));
            if (isA) {
                *reinterpret_cast<uint2*>(AsH + w0) = make_uint2(pack_hi(f4.x, f4.y), pack_hi(f4.z, f4.w));
                *reinterpret_cast<uint2*>(AsL + w0) = make_uint2(pack_lo(f4.x, f4.y), pack_lo(f4.z, f4.w));
            } else {
                *reinterpret_cast<uint2*>(BsH + w0) = make_uint2(pack_hi(f4.x, f4.y), pack_hi(f4.z, f4.w));
                *reinterpret_cast<uint2*>(BsL + w0) = make_uint2(pack_lo(f4.x, f4.y), pack_lo(f4.z, f4.w));
            }
        }
        __syncthreads();
#pragma unroll
        for (int ks = 0; ks < 2; ks++) {
            int kx = ks * 8;
            uint32_t ah[2][4], al[2][4], bH[4][2], bL[4][2];
#pragma unroll
            for (int mt = 0; mt < 2; mt++)
#pragma unroll
                for (int i = 0; i < 4; i++) {
                    ah[mt][i] = AsH[aAddr[mt][i] ^ kx];
                    al[mt][i] = AsL[aAddr[mt][i] ^ kx];
                }
#pragma unroll
            for (int nt = 0; nt < 4; nt++)
#pragma unroll
                for (int i = 0; i < 2; i++) {
                    bH[nt][i] = BsH[bAddr[nt][i] ^ kx];
                    bL[nt][i] = BsL[bAddr[nt][i] ^ kx];
                }
#pragma unroll
            for (int mt = 0; mt < 2; mt++)
#pragma unroll
                for (int nt = 0; nt < 4; nt++)
                    MMA_BF16(acc[mt][nt], ah[mt], bH[nt][0], bH[nt][1]);
#pragma unroll
            for (int mt = 0; mt < 2; mt++)
#pragma unroll
                for (int nt = 0; nt < 4; nt++)
                    MMA_BF16(acc[mt][nt], al[mt], bH[nt][0], bH[nt][1]);
#pragma unroll
            for (int mt = 0; mt < 2; mt++)
#pragma unroll
                for (int nt = 0; nt < 4; nt++)
                    MMA_BF16(acc[mt][nt], ah[mt], bL[nt][0], bL[nt][1]);
        }
    }
#pragma unroll
    for (int mt = 0; mt < 2; mt++) {
#pragma unroll
        for (int nt = 0; nt < 4; nt++) {
            int cb = col0 + wn + nt * 8 + 2 * c0;
            float bz0 = bias ? bias[cb] : 0.f;
            float bz1 = bias ? bias[cb + 1] : 0.f;
#pragma unroll
            for (int h = 0; h < 2; h++) {
                int r = row0 + wm + mt * 16 + g + h * 8;
                float v0 = acc[mt][nt][h * 2 + 0] + bz0;
                float v1 = acc[mt][nt][h * 2 + 1] + bz1;
                *reinterpret_cast<float2*>(&C[(ll)r * ldc + cb]) = make_float2(v0, v1);
            }
        }
    }
}

// ---------------- elementwise ----------------
__global__ void embed_kernel(const int* __restrict__ ids, const float* __restrict__ emb,
                             const float* __restrict__ pos, float* __restrict__ x) {
    int t = blockIdx.x;
    int id = ids[t];
    int s = t % SS;
    const float* er = emb + (ll)id * HH;
    const float* pr = pos + (ll)s * HH;
    float* xr = x + (ll)t * HH;
    for (int j = threadIdx.x; j < HH; j += blockDim.x) xr[j] = er[j] + pr[j];
}

__global__ void ln_kernel(float* __restrict__ out, __half* __restrict__ outh,
                          const float* __restrict__ a,
                          const float* __restrict__ res, const float* __restrict__ coef,
                          float coef_off, const float* __restrict__ g,
                          const float* __restrict__ bvec, float scale) {
    int t = blockIdx.x;
    __shared__ float red[256];
    float v[4];
    float s = 0.f;
#pragma unroll
    for (int j = 0; j < 4; j++) {
        int h = threadIdx.x + 256 * j;
        float xv = a[(ll)t * HH + h];
        if (res) {
            float c = (coef ? coef[h] : 0.f) + coef_off;
            xv += c * res[(ll)t * HH + h];
        }
        v[j] = xv;
        s += xv;
    }
    red[threadIdx.x] = s; __syncthreads();
    for (int o = 128; o > 0; o >>= 1) { if (threadIdx.x < o) red[threadIdx.x] += red[threadIdx.x + o]; __syncthreads(); }
    float mean = red[0] * (1.f / HH); __syncthreads();
    float s2 = 0.f;
#pragma unroll
    for (int j = 0; j < 4; j++) { float d = v[j] - mean; s2 += d * d; }
    red[threadIdx.x] = s2; __syncthreads();
    for (int o = 128; o > 0; o >>= 1) { if (threadIdx.x < o) red[threadIdx.x] += red[threadIdx.x + o]; __syncthreads(); }
    float rstd = rsqrtf(red[0] * (1.f / HH) + 1e-5f);
#pragma unroll
    for (int j = 0; j < 4; j++) {
        int h = threadIdx.x + 256 * j;
        float ov = ((v[j] - mean) * rstd * g[h] + bvec[h]) * scale;
        out[(ll)t * HH + h] = ov;
        if (outh) outh[(ll)t * HH + h] = __float2half_rn(ov);
    }
}

__global__ void gate_u_kernel(const float* __restrict__ gl, float* __restrict__ u, int n) {
    int i = blockIdx.x * blockDim.x + threadIdx.x;
    if (i < n) u[i] = u[i] / (1.f + expf(-gl[i]));
}

__global__ void scan_kernel(float* __restrict__ u, __half* __restrict__ uh,
                            const float* __restrict__ A_log) {
    int b = blockIdx.x, n = threadIdx.x;
    float a = expf(A_log[n]);
    float s = 0.f;
    ll base = (ll)b * SS * NST + n;
    for (int t0 = 0; t0 < SS; t0 += 8) {
        float uv[8];
#pragma unroll
        for (int j = 0; j < 8; j++) uv[j] = u[base + (ll)(t0 + j) * NST];
#pragma unroll
        for (int j = 0; j < 8; j++) { s = a * s + uv[j]; uv[j] = s; }
#pragma unroll
        for (int j = 0; j < 8; j++) {
            u [base + (ll)(t0 + j) * NST] = uv[j];
            uh[base + (ll)(t0 + j) * NST] = __float2half_rn(uv[j]);
        }
    }
}

// softmax: fp32 in -> fp16 probs out
__global__ void softmax512(const float* __restrict__ p, __half* __restrict__ ph) {
    ll row = blockIdx.x;
    const float* r = p + row * SS;
    __half* rh = ph + row * SS;
    int t = threadIdx.x;
    float v0 = r[t], v1 = r[t + 256];
    __shared__ float red[256];
    red[t] = fmaxf(v0, v1); __syncthreads();
    for (int o = 128; o > 0; o >>= 1) { if (t < o) red[t] = fmaxf(red[t], red[t + o]); __syncthreads(); }
    float m = red[0]; __syncthreads();
    float e0 = expf(v0 - m), e1 = expf(v1 - m);
    red[t] = e0 + e1; __syncthreads();
    for (int o = 128; o > 0; o >>= 1) { if (t < o) red[t] += red[t + o]; __syncthreads(); }
    float inv = 1.f / red[0];
    rh[t]       = __float2half_rn(e0 * inv);
    rh[t + 256] = __float2half_rn(e1 * inv);
}

// V transpose: fp16 qkv shadow -> fp16 vt
__global__ void transpose_v(const __half* __restrict__ qkv, __half* __restrict__ vt) {
    __shared__ __half tile[32][33];
    int b = blockIdx.z >> 3, h = blockIdx.z & 7;
    int s0 = blockIdx.x * 32, d0 = blockIdx.y * 32;
    int tx = threadIdx.x, ty = threadIdx.y;
    for (int i = ty; i < 32; i += 8)
        tile[i][tx] = qkv[((ll)(b * SS + s0 + i)) * (3 * HH) + 2 * HH + h * DHD + d0 + tx];
    __syncthreads();
    for (int i = ty; i < 32; i += 8)
        vt[((ll)blockIdx.z * DHD + d0 + i) * SS + s0 + tx] = tile[tx][i];
}

// ---------------- host ----------------
static inline void GFH(const __half* A, const __half* B, const float* bias, float* C,
                       __half* Ch, int M, int N, int K, int lda, int ldb, int ldc,
                       float alpha = 1.f, int act = 0) {
    dim3 grid(N / 128, M / 128);
    gemm_fh<<<grid, 128>>>(A, B, bias, C, Ch, K, lda, ldb, ldc, alpha, act);
}
static inline void GFB(const __half* A, const __half* B, float* C, __half* Ch,
                       int M, int N, int K, int lda, int ldb, int ldc,
                       int batch, int zmod,
                       ll sAa, ll sAb, ll sBa, ll sBb, ll sCa, ll sCb, float alpha) {
    dim3 grid(N / 128, M / 128, batch);
    gemm_fh_b<<<grid, 128>>>(A, B, C, Ch, K, lda, ldb, ldc, zmod,
                             sAa, sAb, sBa, sBb, sCa, sCb, alpha);
}
static inline void GS(const float* A, const float* B, const float* bias, float* C,
                      int M, int N, int K, int lda, int ldb, int ldc) {
    dim3 grid(N / 64, M / 64);
    gemm_small<<<grid, 128>>>(A, B, bias, C, K, lda, ldb, ldc);
}

extern "C" void kernel_launch(void* const* d_in, const int* in_sizes, int n_in,
                              void* d_out, int out_size) {
    const int*   ids  = (const int*)  d_in[0];
    const float* emb  = (const float*)d_in[1];
    const float* pos  = (const float*)d_in[2];
    const float* A_log= (const float*)d_in[3];
    const float* WB   = (const float*)d_in[4];
    const float* WC   = (const float*)d_in[5];
    const float* Dp   = (const float*)d_in[6];
    const float* Wg   = (const float*)d_in[7];
    const float* bg   = (const float*)d_in[8];
    const float* Wout = (const float*)d_in[9];
    const float* bout = (const float*)d_in[10];
    const float* gs   = (const float*)d_in[11];
    const float* bs   = (const float*)d_in[12];
    const float* Wqkv = (const float*)d_in[13];
    const float* bqkv = (const float*)d_in[14];
    const float* Wo   = (const float*)d_in[15];
    const float* bo   = (const float*)d_in[16];
    const float* W1   = (const float*)d_in[17];
    const float* b1   = (const float*)d_in[18];
    const float* W2   = (const float*)d_in[19];
    const float* b2   = (const float*)d_in[20];
    const float* g1   = (const float*)d_in[21];
    const float* bn1  = (const float*)d_in[22];
    const float* g2   = (const float*)d_in[23];
    const float* bn2  = (const float*)d_in[24];
    const float* g3   = (const float*)d_in[25];
    const float* bn3  = (const float*)d_in[26];
    const float* gf   = (const float*)d_in[27];
    const float* bf   = (const float*)d_in[28];

    float *x, *t1, *t2, *sc;
    __half *xh, *t1h, *t2h, *sch, *vth, *wh, *embh;
    cudaGetSymbolAddress((void**)&x,    g_x);
    cudaGetSymbolAddress((void**)&t1,   g_t1);
    cudaGetSymbolAddress((void**)&t2,   g_t2);
    cudaGetSymbolAddress((void**)&sc,   g_sc);
    cudaGetSymbolAddress((void**)&xh,   g_xh);
    cudaGetSymbolAddress((void**)&t1h,  g_t1h);
    cudaGetSymbolAddress((void**)&t2h,  g_t2h);
    cudaGetSymbolAddress((void**)&sch,  g_sch);
    cudaGetSymbolAddress((void**)&vth,  g_vth);
    cudaGetSymbolAddress((void**)&wh,   g_wh);
    cudaGetSymbolAddress((void**)&embh, g_embh);

    auto F2H = [&](const float* src, __half* dst, ll n) {
        f2h_kernel<<<(int)((n / 4 + 255) / 256), 256>>>(src, dst, (int)n);
    };
    F2H(WC,   wh + OFF_WC,   (ll)LL * HH * NST);
    F2H(Wout, wh + OFF_WOUT, (ll)LL * HH * HH);
    F2H(Wqkv, wh + OFF_WQKV, (ll)LL * 3 * HH * HH);
    F2H(Wo,   wh + OFF_WO,   (ll)LL * HH * HH);
    F2H(W1,   wh + OFF_W1,   (ll)LL * FFD * HH);
    F2H(W2,   wh + OFF_W2,   (ll)LL * HH * FFD);
    F2H(emb,  embh,          (ll)VV * HH);

    embed_kernel<<<TT, 256>>>(ids, emb, pos, x);

    for (int i = 0; i < LL; i++) {
        // ===== SSM =====
        GS(x, Wg + (ll)i * NST * HH, bg + (ll)i * NST, t1, TT, NST, HH, HH, HH, NST);
        GS(x, WB + (ll)i * NST * HH, nullptr,          t2, TT, NST, HH, HH, HH, NST);
        gate_u_kernel<<<(TT * NST + 255) / 256, 256>>>(t1, t2, TT * NST);
        scan_kernel<<<BB, NST>>>(t2, t2h, A_log + (ll)i * NST);
        GFH(t2h, wh + OFF_WC + (ll)i * HH * NST, nullptr, t1, nullptr,
            TT, HH, NST, NST, NST, HH);
        ln_kernel<<<TT, 256>>>(t2, t2h, t1, x, Dp + (ll)i * HH, 1.f,
                               gs + (ll)i * HH, bs + (ll)i * HH, 1.f);
        GFH(t2h, wh + OFF_WOUT + (ll)i * HH * HH, bout + (ll)i * HH, t1, nullptr,
            TT, HH, HH, HH, HH, HH);
        ln_kernel<<<TT, 256>>>(x, xh, t1, x, nullptr, 1.f,
                               g1 + (ll)i * HH, bn1 + (ll)i * HH, 1.f);

        // ===== attention (odd layers) + memory fold (x2) =====
        if (i & 1) {
            // qkv (fp32 out unused; fp16 shadow is the consumer)
            GFH(xh, wh + OFF_WQKV + (ll)i * 3 * HH * HH, bqkv + (ll)i * 3 * HH,
                t1, t1h, TT, 3 * HH, HH, HH, HH, 3 * HH);
            float asc = 1.f / sqrtf((float)DHD);
            // scores (fp16 q,k -> fp32 sc)
            GFB(t1h, t1h + HH, sc, nullptr, SS, SS, DHD, 3 * HH, 3 * HH, SS,
                BB * NHD, NHD,
                (ll)SS * 3 * HH, DHD,
                (ll)SS * 3 * HH, DHD,
                (ll)NHD * SS * SS, (ll)SS * SS, asc);
            softmax512<<<BB * NHD * SS, 256>>>(sc, sch);
            {
                dim3 tg(SS / 32, DHD / 32, BB * NHD);
                transpose_v<<<tg, dim3(32, 8)>>>(t1h, vth);
            }
            // attV (fp16 probs x fp16 v -> fp16 t2h only)
            GFB(sch, vth, nullptr, t2h, SS, DHD, SS, SS, SS, HH,
                BB * NHD, NHD,
                (ll)NHD * SS * SS, (ll)SS * SS,
                (ll)NHD * DHD * SS, (ll)DHD * SS,
                (ll)SS * HH, DHD, 1.f);
            GFH(t2h, wh + OFF_WO + (ll)i * HH * HH, bo + (ll)i * HH, t1, nullptr,
                TT, HH, HH, HH, HH, HH);
            ln_kernel<<<TT, 256>>>(x, xh, t1, x, nullptr, 1.f,
                                   g2 + (ll)i * HH, bn2 + (ll)i * HH, 2.f);
        } else {
            ln_kernel<<<TT, 256>>>(x, xh, x, nullptr, nullptr, 0.f,
                                   g2 + (ll)i * HH, bn2 + (ll)i * HH, 2.f);
        }

        // ===== FFN =====
        GFH(xh, wh + OFF_W1 + (ll)i * FFD * HH, b1 + (ll)i * FFD, t1, t1h,
            TT, FFD, HH, HH, HH, FFD, 1.f, 1);
        GFH(t1h, wh + OFF_W2 + (ll)i * HH * FFD, b2 + (ll)i * HH, t2, nullptr,
            TT, HH, FFD, FFD, FFD, HH);
        ln_kernel<<<TT, 256>>>(x, xh, t2, x, nullptr, 1.f,
                               g3 + (ll)i * HH, bn3 + (ll)i * HH, 1.f);
    }

    // ===== final LN + tied lm_head (fp16x1, L2-resident emb) =====
    ln_kernel<<<TT, 256>>>(t1, t1h, x, nullptr, nullptr, 0.f, gf, bf, 1.f);
    GFH(t1h, embh, nullptr, (float*)d_out, nullptr, TT, VV, HH, HH, HH, VV);
}

// round 17
// speedup vs baseline: 2.1811x; 1.1029x over previous
#include <cuda_runtime.h>
#include <cuda_fp16.h>
#include <math.h>
#include <stdint.h>

#define TT 2048
#define SS 512
#define BB 4
#define HH 1024
#define NST 128
#define LL 6
#define VV 32000
#define NHD 8
#define FFD 4096
#define DHD 128
typedef long long ll;

// ---------------- scratch ----------------
__device__ float g_x [TT * HH];
__device__ float g_t1[TT * FFD];
__device__ float g_t2[TT * FFD];
__device__ float g_sc[BB * NHD * SS * SS];
// fp16 shadows + arenas
__device__ __half g_xh [TT * HH];
__device__ __half g_t1h[TT * FFD];
__device__ __half g_t2h[TT * HH];
__device__ __half g_sch[BB * NHD * SS * SS];
__device__ __half g_vth[BB * NHD * DHD * SS];
__device__ __half g_embh[(ll)VV * HH];
#define OFF_WC    0LL
#define OFF_WOUT  786432LL
#define OFF_WQKV  7077888LL
#define OFF_WO    25952256LL
#define OFF_W1    32243712LL
#define OFF_W2    57409536LL
#define WH_TOTAL  82575360LL
__device__ __half g_wh[WH_TOTAL];
__device__ __half g_wgb[(ll)LL * 256 * HH];   // packed [Wg;WB] per layer
__device__ float  g_bgb[LL * 256];            // packed [bg;0]

__device__ __forceinline__ uint32_t smem_u32(const void* p) {
    uint32_t a;
    asm("{ .reg .u64 t; cvta.to.shared.u64 t, %1; cvt.u32.u64 %0, t; }" : "=r"(a) : "l"(p));
    return a;
}

#define MMA_F16(ACC, AFR, BF0, BF1)                                             \
    asm volatile(                                                               \
        "mma.sync.aligned.m16n8k16.row.col.f32.f16.f16.f32 "                    \
        "{%0,%1,%2,%3}, {%4,%5,%6,%7}, {%8,%9}, {%0,%1,%2,%3};"                 \
        : "+f"((ACC)[0]), "+f"((ACC)[1]), "+f"((ACC)[2]), "+f"((ACC)[3])        \
        : "r"((AFR)[0]), "r"((AFR)[1]), "r"((AFR)[2]), "r"((AFR)[3]),           \
          "r"(BF0), "r"(BF1))

#define CP16(dst, src) asm volatile(                                            \
    "cp.async.cg.shared.global [%0], [%1], 16;" :: "r"(dst), "l"(src))

// ---------------- fp32 -> fp16 conversion ----------------
__global__ void f2h_kernel(const float* __restrict__ src, __half* __restrict__ dst, int n) {
    int i = (blockIdx.x * blockDim.x + threadIdx.x) * 4;
    if (i < n) {
        float4 f = *reinterpret_cast<const float4*>(src + i);
        *reinterpret_cast<__half2*>(dst + i)     = __floats2half2_rn(f.x, f.y);
        *reinterpret_cast<__half2*>(dst + i + 2) = __floats2half2_rn(f.z, f.w);
    }
}

// bias packer for [bg;0]
__global__ void pack_bgb(const float* __restrict__ bg, float* __restrict__ bgb) {
    int i = blockIdx.x, t = threadIdx.x;   // LL blocks x 256 threads
    bgb[i * 256 + t] = (t < NST) ? bg[i * NST + t] : 0.f;
}

// ================= fp16xfp16 single-pass NT GEMM (cp.async staged; proven) ===
__global__ __launch_bounds__(128, 2)
void gemm_fh(const __half* __restrict__ A, const __half* __restrict__ B,
             const float* __restrict__ bias, float* __restrict__ C,
             __half* __restrict__ Ch,
             int K, int lda, int ldb, int ldc, float alpha, int act)
{
    __shared__ __align__(16) uint32_t sm[2][2][1024];

    int tid = threadIdx.x;
    int lane = tid & 31, warp = tid >> 5;
    int g = lane >> 2, c0 = lane & 3;
    int wm = (warp & 1) * 64, wn = (warp >> 1) * 64;

    int row0 = blockIdx.y * 128, col0 = blockIdx.x * 128;
    const __half* Ag = A + (ll)row0 * lda;
    const __half* Bg = B + (ll)col0 * ldb;
    uint32_t smb = smem_u32(sm);

    int aBase[4], bBase[8];
#pragma unroll
    for (int mt = 0; mt < 4; mt++) {
        int r = wm + mt * 16 + g;
        aBase[mt] = r * 8 + (c0 ^ (((r >> 2) & 1) << 2));
    }
#pragma unroll
    for (int nt = 0; nt < 8; nt++) {
        int r = wn + nt * 8 + g;
        bBase[nt] = r * 8 + (c0 ^ (((r >> 2) & 1) << 2));
    }
    float acc[4][8][4];
#pragma unroll
    for (int a = 0; a < 4; a++)
#pragma unroll
        for (int b = 0; b < 8; b++)
#pragma unroll
            for (int c = 0; c < 4; c++) acc[a][b][c] = 0.f;

    const int NCH = K >> 4;
    auto issue = [&](int kc) {
        int buf = kc & 1, k0 = kc << 4;
#pragma unroll
        for (int p = 0; p < 4; p++) {
            int u = tid + 128 * p;
            int row = u >> 1, ch = u & 1;
            int r = row & 127;
            const __half* src = (row < 128)
                ? Ag + (ll)r * lda + k0 + ch * 8
                : Bg + (ll)r * ldb + k0 + ch * 8;
            uint32_t w = (uint32_t)(buf * 2048 + (row < 128 ? 0 : 1024)
                        + r * 8 + ((ch * 4) ^ (((r >> 2) & 1) << 2)));
            CP16(smb + w * 4u, src);
        }
        asm volatile("cp.async.commit_group;");
    };

    issue(0);
    for (int kb = 0; kb < NCH; kb++) {
        if (kb + 1 < NCH) {
            issue(kb + 1);
            asm volatile("cp.async.wait_group 1;");
        } else {
            asm volatile("cp.async.wait_group 0;");
        }
        __syncthreads();
        const uint32_t* AH = sm[kb & 1][0];
        const uint32_t* BH = sm[kb & 1][1];

        uint32_t ah[4][4], bH[8][2];
#pragma unroll
        for (int mt = 0; mt < 4; mt++) {
            int a0 = aBase[mt];
            ah[mt][0] = AH[a0];      ah[mt][1] = AH[a0 + 64];
            ah[mt][2] = AH[a0 ^ 4];  ah[mt][3] = AH[(a0 + 64) ^ 4];
        }
#pragma unroll
        for (int nt = 0; nt < 8; nt++) {
            int b0 = bBase[nt];
            bH[nt][0] = BH[b0]; bH[nt][1] = BH[b0 ^ 4];
        }
#pragma unroll
        for (int mt = 0; mt < 4; mt++)
#pragma unroll
            for (int nt = 0; nt < 8; nt++)
                MMA_F16(acc[mt][nt], ah[mt], bH[nt][0], bH[nt][1]);
        __syncthreads();
    }

#pragma unroll
    for (int mt = 0; mt < 4; mt++) {
#pragma unroll
        for (int nt = 0; nt < 8; nt++) {
            int cb = col0 + wn + nt * 8 + 2 * c0;
            float bz0 = bias ? bias[cb] : 0.f;
            float bz1 = bias ? bias[cb + 1] : 0.f;
#pragma unroll
            for (int h = 0; h < 2; h++) {
                int r = row0 + wm + mt * 16 + g + h * 8;
                float v0 = acc[mt][nt][h * 2 + 0] * alpha + bz0;
                float v1 = acc[mt][nt][h * 2 + 1] * alpha + bz1;
                if (act) {
                    v0 = 0.5f * v0 * (1.f + erff(v0 * 0.70710678118654752f));
                    v1 = 0.5f * v1 * (1.f + erff(v1 * 0.70710678118654752f));
                }
                if (C)
                    *reinterpret_cast<float2*>(&C[(ll)r * ldc + cb]) = make_float2(v0, v1);
                if (Ch)
                    *reinterpret_cast<__half2*>(&Ch[(ll)r * ldc + cb]) =
                        __floats2half2_rn(v0, v1);
            }
        }
    }
}

// ================= batched clone (attention scores / attV; proven) ===========
__global__ __launch_bounds__(128, 2)
void gemm_fh_b(const __half* __restrict__ A, const __half* __restrict__ B,
               float* __restrict__ C, __half* __restrict__ Ch,
               int K, int lda, int ldb, int ldc, int zmod,
               ll sAa, ll sAb, ll sBa, ll sBb, ll sCa, ll sCb, float alpha)
{
    __shared__ __align__(16) uint32_t sm[2][2][1024];

    int tid = threadIdx.x;
    int lane = tid & 31, warp = tid >> 5;
    int g = lane >> 2, c0 = lane & 3;
    int wm = (warp & 1) * 64, wn = (warp >> 1) * 64;

    int z = blockIdx.z;
    int zq = z / zmod, zr = z % zmod;
    A += (ll)zq * sAa + (ll)zr * sAb;
    B += (ll)zq * sBa + (ll)zr * sBb;
    if (C)  C  += (ll)zq * sCa + (ll)zr * sCb;
    if (Ch) Ch += (ll)zq * sCa + (ll)zr * sCb;

    int row0 = blockIdx.y * 128, col0 = blockIdx.x * 128;
    const __half* Ag = A + (ll)row0 * lda;
    const __half* Bg = B + (ll)col0 * ldb;
    uint32_t smb = smem_u32(sm);

    int aBase[4], bBase[8];
#pragma unroll
    for (int mt = 0; mt < 4; mt++) {
        int r = wm + mt * 16 + g;
        aBase[mt] = r * 8 + (c0 ^ (((r >> 2) & 1) << 2));
    }
#pragma unroll
    for (int nt = 0; nt < 8; nt++) {
        int r = wn + nt * 8 + g;
        bBase[nt] = r * 8 + (c0 ^ (((r >> 2) & 1) << 2));
    }
    float acc[4][8][4];
#pragma unroll
    for (int a = 0; a < 4; a++)
#pragma unroll
        for (int b = 0; b < 8; b++)
#pragma unroll
            for (int c = 0; c < 4; c++) acc[a][b][c] = 0.f;

    const int NCH = K >> 4;
    auto issue = [&](int kc) {
        int buf = kc & 1, k0 = kc << 4;
#pragma unroll
        for (int p = 0; p < 4; p++) {
            int u = tid + 128 * p;
            int row = u >> 1, ch = u & 1;
            int r = row & 127;
            const __half* src = (row < 128)
                ? Ag + (ll)r * lda + k0 + ch * 8
                : Bg + (ll)r * ldb + k0 + ch * 8;
            uint32_t w = (uint32_t)(buf * 2048 + (row < 128 ? 0 : 1024)
                        + r * 8 + ((ch * 4) ^ (((r >> 2) & 1) << 2)));
            CP16(smb + w * 4u, src);
        }
        asm volatile("cp.async.commit_group;");
    };

    issue(0);
    for (int kb = 0; kb < NCH; kb++) {
        if (kb + 1 < NCH) {
            issue(kb + 1);
            asm volatile("cp.async.wait_group 1;");
        } else {
            asm volatile("cp.async.wait_group 0;");
        }
        __syncthreads();
        const uint32_t* AH = sm[kb & 1][0];
        const uint32_t* BH = sm[kb & 1][1];

        uint32_t ah[4][4], bH[8][2];
#pragma unroll
        for (int mt = 0; mt < 4; mt++) {
            int a0 = aBase[mt];
            ah[mt][0] = AH[a0];      ah[mt][1] = AH[a0 + 64];
            ah[mt][2] = AH[a0 ^ 4];  ah[mt][3] = AH[(a0 + 64) ^ 4];
        }
#pragma unroll
        for (int nt = 0; nt < 8; nt++) {
            int b0 = bBase[nt];
            bH[nt][0] = BH[b0]; bH[nt][1] = BH[b0 ^ 4];
        }
#pragma unroll
        for (int mt = 0; mt < 4; mt++)
#pragma unroll
            for (int nt = 0; nt < 8; nt++)
                MMA_F16(acc[mt][nt], ah[mt], bH[nt][0], bH[nt][1]);
        __syncthreads();
    }

#pragma unroll
    for (int mt = 0; mt < 4; mt++) {
#pragma unroll
        for (int nt = 0; nt < 8; nt++) {
            int cb = col0 + wn + nt * 8 + 2 * c0;
#pragma unroll
            for (int h = 0; h < 2; h++) {
                int r = row0 + wm + mt * 16 + g + h * 8;
                float v0 = acc[mt][nt][h * 2 + 0] * alpha;
                float v1 = acc[mt][nt][h * 2 + 1] * alpha;
                if (C)
                    *reinterpret_cast<float2*>(&C[(ll)r * ldc + cb]) = make_float2(v0, v1);
                if (Ch)
                    *reinterpret_cast<__half2*>(&Ch[(ll)r * ldc + cb]) =
                        __floats2half2_rn(v0, v1);
            }
        }
    }
}

// ---------------- elementwise ----------------
__global__ void embed_kernel(const int* __restrict__ ids, const float* __restrict__ emb,
                             const float* __restrict__ pos, float* __restrict__ x,
                             __half* __restrict__ xh) {
    int t = blockIdx.x;
    int id = ids[t];
    int s = t % SS;
    const float* er = emb + (ll)id * HH;
    const float* pr = pos + (ll)s * HH;
    for (int j = threadIdx.x; j < HH; j += blockDim.x) {
        float v = er[j] + pr[j];
        x [(ll)t * HH + j] = v;
        xh[(ll)t * HH + j] = __float2half_rn(v);
    }
}

__global__ void ln_kernel(float* __restrict__ out, __half* __restrict__ outh,
                          const float* __restrict__ a,
                          const float* __restrict__ res, const float* __restrict__ coef,
                          float coef_off, const float* __restrict__ g,
                          const float* __restrict__ bvec, float scale) {
    int t = blockIdx.x;
    __shared__ float red[256];
    float v[4];
    float s = 0.f;
#pragma unroll
    for (int j = 0; j < 4; j++) {
        int h = threadIdx.x + 256 * j;
        float xv = a[(ll)t * HH + h];
        if (res) {
            float c = (coef ? coef[h] : 0.f) + coef_off;
            xv += c * res[(ll)t * HH + h];
        }
        v[j] = xv;
        s += xv;
    }
    red[threadIdx.x] = s; __syncthreads();
    for (int o = 128; o > 0; o >>= 1) { if (threadIdx.x < o) red[threadIdx.x] += red[threadIdx.x + o]; __syncthreads(); }
    float mean = red[0] * (1.f / HH); __syncthreads();
    float s2 = 0.f;
#pragma unroll
    for (int j = 0; j < 4; j++) { float d = v[j] - mean; s2 += d * d; }
    red[threadIdx.x] = s2; __syncthreads();
    for (int o = 128; o > 0; o >>= 1) { if (threadIdx.x < o) red[threadIdx.x] += red[threadIdx.x + o]; __syncthreads(); }
    float rstd = rsqrtf(red[0] * (1.f / HH) + 1e-5f);
#pragma unroll
    for (int j = 0; j < 4; j++) {
        int h = threadIdx.x + 256 * j;
        float ov = ((v[j] - mean) * rstd * g[h] + bvec[h]) * scale;
        if (out)  out [(ll)t * HH + h] = ov;
        if (outh) outh[(ll)t * HH + h] = __float2half_rn(ov);
    }
}

// gate_u2: gb layout [t][0:128]=gate logits, [128:256]=u -> t2[t][n] = u*sig(g)
__global__ void gate_u2_kernel(const float* __restrict__ gb, float* __restrict__ u2, int n) {
    int i = blockIdx.x * blockDim.x + threadIdx.x;
    if (i < n) {
        int t = i >> 7, c = i & 127;
        float gv = gb[(ll)t * 256 + c];
        float uv = gb[(ll)t * 256 + 128 + c];
        u2[i] = uv / (1.f + expf(-gv));
    }
}

__global__ void scan_kernel(float* __restrict__ u, __half* __restrict__ uh,
                            const float* __restrict__ A_log) {
    int b = blockIdx.x, n = threadIdx.x;
    float a = expf(A_log[n]);
    float s = 0.f;
    ll base = (ll)b * SS * NST + n;
    for (int t0 = 0; t0 < SS; t0 += 8) {
        float uv[8];
#pragma unroll
        for (int j = 0; j < 8; j++) uv[j] = u[base + (ll)(t0 + j) * NST];
#pragma unroll
        for (int j = 0; j < 8; j++) { s = a * s + uv[j]; uv[j] = s; }
#pragma unroll
        for (int j = 0; j < 8; j++) {
            u [base + (ll)(t0 + j) * NST] = uv[j];
            uh[base + (ll)(t0 + j) * NST] = __float2half_rn(uv[j]);
        }
    }
}

__global__ void softmax512(const float* __restrict__ p, __half* __restrict__ ph) {
    ll row = blockIdx.x;
    const float* r = p + row * SS;
    __half* rh = ph + row * SS;
    int t = threadIdx.x;
    float v0 = r[t], v1 = r[t + 256];
    __shared__ float red[256];
    red[t] = fmaxf(v0, v1); __syncthreads();
    for (int o = 128; o > 0; o >>= 1) { if (t < o) red[t] = fmaxf(red[t], red[t + o]); __syncthreads(); }
    float m = red[0]; __syncthreads();
    float e0 = expf(v0 - m), e1 = expf(v1 - m);
    red[t] = e0 + e1; __syncthreads();
    for (int o = 128; o > 0; o >>= 1) { if (t < o) red[t] += red[t + o]; __syncthreads(); }
    float inv = 1.f / red[0];
    rh[t]       = __float2half_rn(e0 * inv);
    rh[t + 256] = __float2half_rn(e1 * inv);
}

__global__ void transpose_v(const __half* __restrict__ qkv, __half* __restrict__ vt) {
    __shared__ __half tile[32][33];
    int b = blockIdx.z >> 3, h = blockIdx.z & 7;
    int s0 = blockIdx.x * 32, d0 = blockIdx.y * 32;
    int tx = threadIdx.x, ty = threadIdx.y;
    for (int i = ty; i < 32; i += 8)
        tile[i][tx] = qkv[((ll)(b * SS + s0 + i)) * (3 * HH) + 2 * HH + h * DHD + d0 + tx];
    __syncthreads();
    for (int i = ty; i < 32; i += 8)
        vt[((ll)blockIdx.z * DHD + d0 + i) * SS + s0 + tx] = tile[tx][i];
}

// ---------------- host ----------------
static inline void GFH(const __half* A, const __half* B, const float* bias, float* C,
                       __half* Ch, int M, int N, int K, int lda, int ldb, int ldc,
                       float alpha = 1.f, int act = 0) {
    dim3 grid(N / 128, M / 128);
    gemm_fh<<<grid, 128>>>(A, B, bias, C, Ch, K, lda, ldb, ldc, alpha, act);
}
static inline void GFB(const __half* A, const __half* B, float* C, __half* Ch,
                       int M, int N, int K, int lda, int ldb, int ldc,
                       int batch, int zmod,
                       ll sAa, ll sAb, ll sBa, ll sBb, ll sCa, ll sCb, float alpha) {
    dim3 grid(N / 128, M / 128, batch);
    gemm_fh_b<<<grid, 128>>>(A, B, C, Ch, K, lda, ldb, ldc, zmod,
                             sAa, sAb, sBa, sBb, sCa, sCb, alpha);
}

extern "C" void kernel_launch(void* const* d_in, const int* in_sizes, int n_in,
                              void* d_out, int out_size) {
    const int*   ids  = (const int*)  d_in[0];
    const float* emb  = (const float*)d_in[1];
    const float* pos  = (const float*)d_in[2];
    const float* A_log= (const float*)d_in[3];
    const float* WB   = (const float*)d_in[4];
    const float* WC   = (const float*)d_in[5];
    const float* Dp   = (const float*)d_in[6];
    const float* Wg   = (const float*)d_in[7];
    const float* bg   = (const float*)d_in[8];
    const float* Wout = (const float*)d_in[9];
    const float* bout = (const float*)d_in[10];
    const float* gs   = (const float*)d_in[11];
    const float* bs   = (const float*)d_in[12];
    const float* Wqkv = (const float*)d_in[13];
    const float* bqkv = (const float*)d_in[14];
    const float* Wo   = (const float*)d_in[15];
    const float* bo   = (const float*)d_in[16];
    const float* W1   = (const float*)d_in[17];
    const float* b1   = (const float*)d_in[18];
    const float* W2   = (const float*)d_in[19];
    const float* b2   = (const float*)d_in[20];
    const float* g1   = (const float*)d_in[21];
    const float* bn1  = (const float*)d_in[22];
    const float* g2   = (const float*)d_in[23];
    const float* bn2  = (const float*)d_in[24];
    const float* g3   = (const float*)d_in[25];
    const float* bn3  = (const float*)d_in[26];
    const float* gf   = (const float*)d_in[27];
    const float* bf   = (const float*)d_in[28];

    float *x, *t1, *t2, *sc, *bgb;
    __half *xh, *t1h, *t2h, *sch, *vth, *wh, *embh, *wgb;
    cudaGetSymbolAddress((void**)&x,    g_x);
    cudaGetSymbolAddress((void**)&t1,   g_t1);
    cudaGetSymbolAddress((void**)&t2,   g_t2);
    cudaGetSymbolAddress((void**)&sc,   g_sc);
    cudaGetSymbolAddress((void**)&xh,   g_xh);
    cudaGetSymbolAddress((void**)&t1h,  g_t1h);
    cudaGetSymbolAddress((void**)&t2h,  g_t2h);
    cudaGetSymbolAddress((void**)&sch,  g_sch);
    cudaGetSymbolAddress((void**)&vth,  g_vth);
    cudaGetSymbolAddress((void**)&wh,   g_wh);
    cudaGetSymbolAddress((void**)&embh, g_embh);
    cudaGetSymbolAddress((void**)&wgb,  g_wgb);
    cudaGetSymbolAddress((void**)&bgb,  g_bgb);

    auto F2H = [&](const float* src, __half* dst, ll n) {
        f2h_kernel<<<(int)((n / 4 + 255) / 256), 256>>>(src, dst, (int)n);
    };
    F2H(WC,   wh + OFF_WC,   (ll)LL * HH * NST);
    F2H(Wout, wh + OFF_WOUT, (ll)LL * HH * HH);
    F2H(Wqkv, wh + OFF_WQKV, (ll)LL * 3 * HH * HH);
    F2H(Wo,   wh + OFF_WO,   (ll)LL * HH * HH);
    F2H(W1,   wh + OFF_W1,   (ll)LL * FFD * HH);
    F2H(W2,   wh + OFF_W2,   (ll)LL * HH * FFD);
    F2H(emb,  embh,          (ll)VV * HH);
    // pack [Wg;WB] per layer into wgb (rows are K-contiguous, flat copies)
    for (int i = 0; i < LL; i++) {
        F2H(Wg + (ll)i * NST * HH, wgb + (ll)i * 256 * HH,            (ll)NST * HH);
        F2H(WB + (ll)i * NST * HH, wgb + (ll)i * 256 * HH + (ll)NST * HH, (ll)NST * HH);
    }
    pack_bgb<<<LL, 256>>>(bg, bgb);

    embed_kernel<<<TT, 256>>>(ids, emb, pos, x, xh);

    for (int i = 0; i < LL; i++) {
        // ===== SSM =====
        // packed gate/B projection: t1[t][0:128]=gate logits, [128:256]=u
        GFH(xh, wgb + (ll)i * 256 * HH, bgb + i * 256, t1, nullptr,
            TT, 256, HH, HH, HH, 256);
        gate_u2_kernel<<<(TT * NST + 255) / 256, 256>>>(t1, t2, TT * NST);
        scan_kernel<<<BB, NST>>>(t2, t2h, A_log + (ll)i * NST);
        GFH(t2h, wh + OFF_WC + (ll)i * HH * NST, nullptr, t1, nullptr,
            TT, HH, NST, NST, NST, HH);
        ln_kernel<<<TT, 256>>>(nullptr, t2h, t1, x, Dp + (ll)i * HH, 1.f,
                               gs + (ll)i * HH, bs + (ll)i * HH, 1.f);
        GFH(t2h, wh + OFF_WOUT + (ll)i * HH * HH, bout + (ll)i * HH, t1, nullptr,
            TT, HH, HH, HH, HH, HH);
        ln_kernel<<<TT, 256>>>(x, xh, t1, x, nullptr, 1.f,
                               g1 + (ll)i * HH, bn1 + (ll)i * HH, 1.f);

        // ===== attention (odd layers) + memory fold (x2) =====
        if (i & 1) {
            GFH(xh, wh + OFF_WQKV + (ll)i * 3 * HH * HH, bqkv + (ll)i * 3 * HH,
                nullptr, t1h, TT, 3 * HH, HH, HH, HH, 3 * HH);
            float asc = 1.f / sqrtf((float)DHD);
            GFB(t1h, t1h + HH, sc, nullptr, SS, SS, DHD, 3 * HH, 3 * HH, SS,
                BB * NHD, NHD,
                (ll)SS * 3 * HH, DHD,
                (ll)SS * 3 * HH, DHD,
                (ll)NHD * SS * SS, (ll)SS * SS, asc);
            softmax512<<<BB * NHD * SS, 256>>>(sc, sch);
            {
                dim3 tg(SS / 32, DHD / 32, BB * NHD);
                transpose_v<<<tg, dim3(32, 8)>>>(t1h, vth);
            }
            GFB(sch, vth, nullptr, t2h, SS, DHD, SS, SS, SS, HH,
                BB * NHD, NHD,
                (ll)NHD * SS * SS, (ll)SS * SS,
                (ll)NHD * DHD * SS, (ll)DHD * SS,
                (ll)SS * HH, DHD, 1.f);
            GFH(t2h, wh + OFF_WO + (ll)i * HH * HH, bo + (ll)i * HH, t1, nullptr,
                TT, HH, HH, HH, HH, HH);
            ln_kernel<<<TT, 256>>>(x, xh, t1, x, nullptr, 1.f,
                                   g2 + (ll)i * HH, bn2 + (ll)i * HH, 2.f);
        } else {
            ln_kernel<<<TT, 256>>>(x, xh, x, nullptr, nullptr, 0.f,
                                   g2 + (ll)i * HH, bn2 + (ll)i * HH, 2.f);
        }

        // ===== FFN =====
        GFH(xh, wh + OFF_W1 + (ll)i * FFD * HH, b1 + (ll)i * FFD, nullptr, t1h,
            TT, FFD, HH, HH, HH, FFD, 1.f, 1);
        GFH(t1h, wh + OFF_W2 + (ll)i * HH * FFD, b2 + (ll)i * HH, t2, nullptr,
            TT, HH, FFD, FFD, FFD, HH);
        ln_kernel<<<TT, 256>>>(x, xh, t2, x, nullptr, 1.f,
                               g3 + (ll)i * HH, bn3 + (ll)i * HH, 1.f);
    }

    // ===== final LN + tied lm_head (fp16x1, L2-resident emb) =====
    ln_kernel<<<TT, 256>>>(nullptr, t1h, x, nullptr, nullptr, 0.f, gf, bf, 1.f);
    GFH(t1h, embh, nullptr, (float*)d_out, nullptr, TT, VV, HH, HH, HH, VV);
}